// round 12
// baseline (speedup 1.0000x reference)
#include <cuda_runtime.h>
#include <cuda_bf16.h>
#include <cuda_fp16.h>
#include <math.h>
#include <stdint.h>

// ---------------- problem constants ----------------
#define Lnum 4
#define Bn   2
#define Sn   1024
#define En   1024
#define NHn  16
#define HDn  64
#define HIDn 1024
#define FFn  4096
#define Vn   32000
#define NTOK (Bn*Sn)   // 2048
#define M1   (1u<<20)  // 1024*1024

typedef __nv_bfloat16 bf16;

// ---------------- scratch (static device memory; no allocation) ----------------
__device__ float  g_x   [NTOK*En];                 // residual stream fp32
__device__ float  g_proj[NTOK*En];                 // attn projection fp32
__device__ __half g_att [(size_t)Bn*NHn*Sn*Sn];    // scoresT fp16, 64 MB
__device__ bf16   g_pt  [(size_t)Bn*NHn*Sn*Sn];    // probsT bf16, 64 MB

__device__ bf16 g_xh[NTOK*En],  g_xl[NTOK*En];     // x hi/lo
__device__ bf16 g_qh[NTOK*HIDn], g_ql[NTOK*HIDn];  // q head-major [b,h,s,d]
__device__ bf16 g_kh[NTOK*HIDn], g_kl[NTOK*HIDn];  // k head-major
__device__ bf16 g_vt[NTOK*HIDn];                   // v transposed [b,h,d,s]
__device__ bf16 g_mh[NTOK*En],  g_ml[NTOK*En];     // mha hi/lo (token-major)
__device__ bf16 g_rh[NTOK*En],  g_rl[NTOK*En];     // rmsnorm out hi/lo
__device__ bf16 g_hh[(size_t)NTOK*FFn], g_hl[(size_t)NTOK*FFn]; // FF hidden hi/lo

// bf16 hi/lo weights, NATURAL [K,N] layout (no transpose).
#define WTOT (48u*M1 + (size_t)Vn*En)
__device__ bf16 g_whi[WTOT];
__device__ bf16 g_wlo[WTOT];

// ---------------- helpers ----------------
__device__ __forceinline__ uint32_t smem_u32(const void* p) {
    uint32_t a;
    asm("{ .reg .u64 t; cvta.to.shared.u64 t, %1; cvt.u32.u64 %0, t; }" : "=r"(a) : "l"(p));
    return a;
}
__device__ __forceinline__ uint32_t pack_bf(bf16 a, bf16 b) {
    return (uint32_t)__bfloat16_as_ushort(a) | ((uint32_t)__bfloat16_as_ushort(b) << 16);
}
__device__ __forceinline__ void split2(float x, bf16& h, bf16& l) {
    h = __float2bfloat16_rn(x);
    l = __float2bfloat16_rn(x - __bfloat162float(h));
}

#define LDSM4(r, a) \
    asm volatile("ldmatrix.sync.aligned.m8n8.x4.shared.b16 {%0,%1,%2,%3}, [%4];" \
        : "=r"((r)[0]), "=r"((r)[1]), "=r"((r)[2]), "=r"((r)[3]) : "r"(a))

#define LDSM4T(r, a) \
    asm volatile("ldmatrix.sync.aligned.m8n8.x4.trans.shared.b16 {%0,%1,%2,%3}, [%4];" \
        : "=r"((r)[0]), "=r"((r)[1]), "=r"((r)[2]), "=r"((r)[3]) : "r"(a))

#define MMA16816(d, a, b0, b1) \
    asm volatile("mma.sync.aligned.m16n8k16.row.col.f32.bf16.bf16.f32 " \
        "{%0,%1,%2,%3}, {%4,%5,%6,%7}, {%8,%9}, {%0,%1,%2,%3};" \
        : "+f"((d)[0]), "+f"((d)[1]), "+f"((d)[2]), "+f"((d)[3]) \
        : "r"((a)[0]), "r"((a)[1]), "r"((a)[2]), "r"((a)[3]), "r"(b0), "r"(b1))

__device__ __forceinline__ void cp_async16(uint32_t dst, const void* src) {
    asm volatile("cp.async.cg.shared.global [%0], [%1], 16;" :: "r"(dst), "l"(src));
}

// ---------------- streaming bf16 split (NO transpose): W fp32 -> hi/lo, same layout ----------------
__global__ void convert_w(const float* __restrict__ W, bf16* __restrict__ hi,
                          bf16* __restrict__ lo, int n4) {
    int i = blockIdx.x * blockDim.x + threadIdx.x;
    if (i >= n4) return;
    float4 v = ((const float4*)W)[i];
    bf16 h0, l0, h1, l1, h2, l2, h3, l3;
    split2(v.x, h0, l0); split2(v.y, h1, l1);
    split2(v.z, h2, l2); split2(v.w, h3, l3);
    ((uint2*)hi)[i] = make_uint2(pack_bf(h0, h1), pack_bf(h2, h3));
    ((uint2*)lo)[i] = make_uint2(pack_bf(l0, l1), pack_bf(l2, l3));
}

// ---------------- mma.sync bf16-split GEMM ----------------
// C[M,N] = A(hi/lo [M,K]) * W(hi/lo [K,N]),  fp32 accum, 3-term split.
// B staged k-major (64 k-rows x 256B), fragments via ldmatrix.trans (R6-verified).
// flags: 1 = +bias[N], 2 = relu, 4 = +add (residual, MxN)
// omode: 0 = C fp32 only; 1 = C fp32 + Chi/Clo token-major; 2 = Chi/Clo only;
//        3 = head-major hi/lo q/k [b,h,s,d]; 4 = transposed bf16 v [b,h,d,s]
#define STAGE_BYTES 65536
#define GM_SMEM (2*STAGE_BYTES)
__global__ void __launch_bounds__(256, 1) gemm_mma(
    const bf16* __restrict__ Ahi, const bf16* __restrict__ Alo,
    const bf16* __restrict__ Bhi, const bf16* __restrict__ Blo,
    const float* __restrict__ bias, const float* __restrict__ add,
    float* __restrict__ C, bf16* __restrict__ Chi, bf16* __restrict__ Clo,
    int M, int N, int K, int flags, int omode)
{
    extern __shared__ char smem[];
    const uint32_t sb = smem_u32(smem);
    const int tid = threadIdx.x, wid = tid >> 5, lane = tid & 31;
    const int m0 = blockIdx.y << 7, n0 = blockIdx.x << 7;
    const int wm = (wid & 1) << 6;
    const int wn = (wid >> 1) << 5;

    const bf16* gAh = Ahi + (size_t)m0 * K;
    const bf16* gAl = Alo + (size_t)m0 * K;
    const bf16* gBh = Bhi + n0;   // [K,N], column offset
    const bf16* gBl = Blo + n0;

    const int nchunk = K >> 6;
    const int l_row = tid >> 3;
    const int l_ch  = tid & 7;

    auto load_stage = [&](int s, int c) {
        const uint32_t st = sb + (uint32_t)s * STAGE_BYTES;
        const int kb = c << 6;
        // A tiles: 128 rows x 128B (row-major M-K)
        {
            const bf16* srcs[2] = { gAh + kb, gAl + kb };
            #pragma unroll
            for (int t = 0; t < 2; t++) {
                const uint32_t dstb = st + (uint32_t)t * 16384u;
                #pragma unroll
                for (int i = 0; i < 4; i++) {
                    int row = l_row + (i << 5);
                    uint32_t dst = dstb + (uint32_t)(row << 7) + (uint32_t)((l_ch ^ (row & 7)) << 4);
                    cp_async16(dst, srcs[t] + (size_t)row * K + (l_ch << 3));
                }
            }
        }
        // B tiles: 64 k-rows x 256B (k-major K-N)
        {
            const bf16* srcs[2] = { gBh, gBl };
            #pragma unroll
            for (int t = 0; t < 2; t++) {
                const uint32_t dstb = st + 32768u + (uint32_t)t * 16384u;
                #pragma unroll
                for (int i = 0; i < 4; i++) {
                    int idx = tid + (i << 8);
                    int krow = idx >> 4, ch = idx & 15;
                    uint32_t dst = dstb + (uint32_t)(krow << 8) + (uint32_t)((ch ^ (krow & 7)) << 4);
                    cp_async16(dst, srcs[t] + (size_t)(kb + krow) * N + (ch << 3));
                }
            }
        }
        asm volatile("cp.async.commit_group;" ::: "memory");
    };

    float acc[4][4][4];
    #pragma unroll
    for (int i = 0; i < 4; i++)
        #pragma unroll
        for (int j = 0; j < 4; j++)
            #pragma unroll
            for (int q = 0; q < 4; q++) acc[i][j][q] = 0.f;

    // A fragment addressing (non-trans)
    const int a_row = lane & 15;
    const int a_cb  = (lane >> 4) << 4;
    const uint32_t aswz = (uint32_t)((lane & 7) << 4);
    // B fragment addressing (trans, k-major 256B rows) — R6-verified
    const int bm = lane >> 3, brr = lane & 7;
    const int krow_base = ((bm & 1) << 3) | brr;
    const int nch_off = bm >> 1;

    load_stage(0, 0);

    for (int c = 0; c < nchunk; c++) {
        const int s = c & 1;
        if (c + 1 < nchunk) {
            load_stage(s ^ 1, c + 1);
            asm volatile("cp.async.wait_group 1;" ::: "memory");
        } else {
            asm volatile("cp.async.wait_group 0;" ::: "memory");
        }
        __syncthreads();

        const uint32_t st = sb + (uint32_t)s * STAGE_BYTES;
        #pragma unroll
        for (int kk = 0; kk < 4; kk++) {
            uint32_t ah[4][4], al[4][4], bh2[2][4], bl2[2][4];
            #pragma unroll
            for (int mi = 0; mi < 4; mi++) {
                int row = wm + (mi << 4) + a_row;
                uint32_t off = (uint32_t)(row << 7) + (((uint32_t)((kk << 5) + a_cb)) ^ aswz);
                LDSM4(ah[mi], st + off);
                LDSM4(al[mi], st + 16384u + off);
            }
            #pragma unroll
            for (int jj = 0; jj < 2; jj++) {
                int krow = (kk << 4) + krow_base;
                uint32_t nch = (uint32_t)((wn >> 3) + (jj << 1) + nch_off);
                uint32_t off = (uint32_t)(krow << 8) + ((nch ^ (uint32_t)(krow & 7)) << 4);
                LDSM4T(bh2[jj], st + 32768u + off);
                LDSM4T(bl2[jj], st + 49152u + off);
            }
            #pragma unroll
            for (int mi = 0; mi < 4; mi++) {
                #pragma unroll
                for (int nj = 0; nj < 4; nj++) {
                    uint32_t b0 = bh2[nj >> 1][(nj & 1) << 1], b1 = bh2[nj >> 1][((nj & 1) << 1) + 1];
                    uint32_t c0 = bl2[nj >> 1][(nj & 1) << 1], c1 = bl2[nj >> 1][((nj & 1) << 1) + 1];
                    MMA16816(acc[mi][nj], ah[mi], b0, b1);
                    MMA16816(acc[mi][nj], ah[mi], c0, c1);
                    MMA16816(acc[mi][nj], al[mi], b0, b1);
                }
            }
        }
        __syncthreads();
    }

    // epilogue
    const int er = m0 + wm + (lane >> 2);
    const int ec = n0 + wn + ((lane & 3) << 1);
    #pragma unroll
    for (int mi = 0; mi < 4; mi++) {
        #pragma unroll
        for (int hf = 0; hf < 2; hf++) {
            int row = er + (mi << 4) + (hf << 3);
            const float* Ar = (flags & 4) ? (add + (size_t)row * N) : nullptr;
            int bidx = row >> 10, srow = row & 1023;
            #pragma unroll
            for (int nj = 0; nj < 4; nj++) {
                int col = ec + (nj << 3);
                float v0 = acc[mi][nj][hf * 2 + 0];
                float v1 = acc[mi][nj][hf * 2 + 1];
                if (flags & 1) { v0 += bias[col]; v1 += bias[col + 1]; }
                if (flags & 4) { v0 += Ar[col];   v1 += Ar[col + 1]; }
                if (flags & 2) { v0 = fmaxf(v0, 0.f); v1 = fmaxf(v1, 0.f); }
                if (omode <= 1)
                    *(float2*)(C + (size_t)row * N + col) = make_float2(v0, v1);
                if (omode == 1 || omode == 2) {
                    bf16 h0, l0, h1, l1;
                    split2(v0, h0, l0); split2(v1, h1, l1);
                    *(uint32_t*)&Chi[(size_t)row * N + col] = pack_bf(h0, h1);
                    *(uint32_t*)&Clo[(size_t)row * N + col] = pack_bf(l0, l1);
                } else if (omode == 3) {
                    int h = col >> 6, d = col & 63;
                    size_t dst = (((size_t)((bidx << 4) + h) << 10) + srow) * 64 + d;
                    bf16 h0, l0, h1, l1;
                    split2(v0, h0, l0); split2(v1, h1, l1);
                    *(uint32_t*)&Chi[dst] = pack_bf(h0, h1);
                    *(uint32_t*)&Clo[dst] = pack_bf(l0, l1);
                } else if (omode == 4) {
                    int h = col >> 6, d = col & 63;
                    size_t hb = (size_t)((bidx << 4) + h) << 6;
                    Chi[(hb + d) * 1024 + srow]     = __float2bfloat16_rn(v0);
                    Chi[(hb + d + 1) * 1024 + srow] = __float2bfloat16_rn(v1);
                }
            }
        }
    }
}

// ---------------- scoresT: scT[bh][t][s] = 0.125 * k[bh,t,:].q[bh,s,:]  (3-term, fp16 out) ----------------
#define SC_SMEM 65536
__global__ void __launch_bounds__(256, 1) scoresT_mma(
    const bf16* __restrict__ Kh, const bf16* __restrict__ Kl,
    const bf16* __restrict__ Qh, const bf16* __restrict__ Ql,
    __half* __restrict__ scT)
{
    extern __shared__ char smem[];
    const uint32_t sb = smem_u32(smem);
    const int tid = threadIdx.x, wid = tid >> 5, lane = tid & 31;
    const int bh = blockIdx.z;
    const int t0 = blockIdx.y << 7, s0 = blockIdx.x << 7;
    const size_t hbase = (size_t)bh << 16;
    const bf16* srcs[4] = {
        Kh + hbase + (size_t)t0 * 64, Kl + hbase + (size_t)t0 * 64,
        Qh + hbase + (size_t)s0 * 64, Ql + hbase + (size_t)s0 * 64 };

    {
        const int l_row = tid >> 3, l_ch = tid & 7;
        #pragma unroll
        for (int t = 0; t < 4; t++) {
            #pragma unroll
            for (int i = 0; i < 4; i++) {
                int row = l_row + (i << 5);
                uint32_t dst = sb + (uint32_t)t * 16384u + (uint32_t)(row << 7)
                             + (uint32_t)((l_ch ^ (row & 7)) << 4);
                cp_async16(dst, srcs[t] + (size_t)row * 64 + (l_ch << 3));
            }
        }
        asm volatile("cp.async.commit_group;" ::: "memory");
        asm volatile("cp.async.wait_group 0;" ::: "memory");
    }
    __syncthreads();

    const int wm = (wid & 1) << 6, wn = (wid >> 1) << 5;
    float acc[4][4][4];
    #pragma unroll
    for (int i = 0; i < 4; i++)
        #pragma unroll
        for (int j = 0; j < 4; j++)
            #pragma unroll
            for (int q = 0; q < 4; q++) acc[i][j][q] = 0.f;

    const int a_row = lane & 15, a_cb = (lane >> 4) << 4;
    const int b_row = (lane & 7) + ((lane >> 4) << 3), b_cb = ((lane >> 3) & 1) << 4;
    const uint32_t swz = (uint32_t)((lane & 7) << 4);

    #pragma unroll
    for (int kk = 0; kk < 4; kk++) {
        uint32_t ah[4][4], al[4][4], bh2[2][4], bl2[2][4];
        #pragma unroll
        for (int mi = 0; mi < 4; mi++) {
            int row = wm + (mi << 4) + a_row;
            uint32_t off = (uint32_t)(row << 7) + (((uint32_t)((kk << 5) + a_cb)) ^ swz);
            LDSM4(ah[mi], sb + off);
            LDSM4(al[mi], sb + 16384u + off);
        }
        #pragma unroll
        for (int j = 0; j < 2; j++) {
            int row = wn + (j << 4) + b_row;
            uint32_t off = (uint32_t)(row << 7) + (((uint32_t)((kk << 5) + b_cb)) ^ swz);
            LDSM4(bh2[j], sb + 32768u + off);
            LDSM4(bl2[j], sb + 49152u + off);
        }
        #pragma unroll
        for (int mi = 0; mi < 4; mi++) {
            #pragma unroll
            for (int nj = 0; nj < 4; nj++) {
                uint32_t b0 = bh2[nj >> 1][(nj & 1) << 1], b1 = bh2[nj >> 1][((nj & 1) << 1) + 1];
                uint32_t c0 = bl2[nj >> 1][(nj & 1) << 1], c1 = bl2[nj >> 1][((nj & 1) << 1) + 1];
                MMA16816(acc[mi][nj], ah[mi], b0, b1);
                MMA16816(acc[mi][nj], ah[mi], c0, c1);
                MMA16816(acc[mi][nj], al[mi], b0, b1);
            }
        }
    }

    __half* ob = scT + ((size_t)bh << 20);
    const int er = t0 + wm + (lane >> 2);
    const int ec = s0 + wn + ((lane & 3) << 1);
    #pragma unroll
    for (int mi = 0; mi < 4; mi++) {
        #pragma unroll
        for (int hf = 0; hf < 2; hf++) {
            int row = er + (mi << 4) + (hf << 3);
            #pragma unroll
            for (int nj = 0; nj < 4; nj++) {
                int col = ec + (nj << 3);
                *(__half2*)(ob + (size_t)row * Sn + col) =
                    __floats2half2_rn(acc[mi][nj][hf * 2] * 0.125f,
                                      acc[mi][nj][hf * 2 + 1] * 0.125f);
            }
        }
    }
}

// ---------------- parallel column softmax over t (UNMASKED, bug-faithful) ----------------
__global__ void __launch_bounds__(256) col_softmax(const __half* __restrict__ scT,
                                                   bf16* __restrict__ pT) {
    __shared__ float sm0[8][33], sm1[8][33], ss0[8][33], ss1[8][33];
    const int bh = blockIdx.y;
    const int lane = threadIdx.x & 31;
    const int chunk = threadIdx.x >> 5;
    const int s = (blockIdx.x << 6) + (lane << 1);
    const __half* base = scT + ((size_t)bh << 20) + s;
    const int t0 = chunk << 7;
    float cm0 = -3.402823466e38f, cm1 = -3.402823466e38f, cu0 = 0.f, cu1 = 0.f;
    #pragma unroll 4
    for (int t = 0; t < 128; t++) {
        __half2 h = *(const __half2*)(base + ((size_t)(t0 + t) << 10));
        float x0 = __low2float(h), x1 = __high2float(h);
        float n0 = fmaxf(cm0, x0), n1 = fmaxf(cm1, x1);
        cu0 = cu0 * __expf(cm0 - n0) + __expf(x0 - n0);
        cu1 = cu1 * __expf(cm1 - n1) + __expf(x1 - n1);
        cm0 = n0; cm1 = n1;
    }
    sm0[chunk][lane] = cm0; sm1[chunk][lane] = cm1;
    ss0[chunk][lane] = cu0; ss1[chunk][lane] = cu1;
    __syncthreads();
    float gM0 = -3.402823466e38f, gM1 = -3.402823466e38f;
    #pragma unroll
    for (int i = 0; i < 8; i++) {
        gM0 = fmaxf(gM0, sm0[i][lane]);
        gM1 = fmaxf(gM1, sm1[i][lane]);
    }
    float gS0 = 0.f, gS1 = 0.f;
    #pragma unroll
    for (int i = 0; i < 8; i++) {
        gS0 += ss0[i][lane] * __expf(sm0[i][lane] - gM0);
        gS1 += ss1[i][lane] * __expf(sm1[i][lane] - gM1);
    }
    float inv0 = 1.f / gS0, inv1 = 1.f / gS1;
    bf16* ob = pT + ((size_t)bh << 20) + s;
    #pragma unroll 4
    for (int t = 0; t < 128; t++) {
        __half2 h = *(const __half2*)(base + ((size_t)(t0 + t) << 10));
        float p0 = __expf(__low2float(h) - gM0) * inv0;
        float p1 = __expf(__high2float(h) - gM1) * inv1;
        *(uint32_t*)(ob + ((size_t)(t0 + t) << 10)) =
            pack_bf(__float2bfloat16_rn(p0), __float2bfloat16_rn(p1));
    }
}

// ---------------- AV: mha[b,t,h,d] = sum_s pT[bh,t,s] * vT[bh,d,s] ----------------
#define AV_STAGE 49152
#define AV_SMEM (2*AV_STAGE)
__global__ void __launch_bounds__(256, 1) av_mma(
    const bf16* __restrict__ pT, const bf16* __restrict__ vT,
    bf16* __restrict__ Mh, bf16* __restrict__ Ml)
{
    extern __shared__ char smem[];
    const uint32_t sb = smem_u32(smem);
    const int tid = threadIdx.x, wid = tid >> 5, lane = tid & 31;
    const int bh = blockIdx.y, t0 = blockIdx.x << 7;
    const bf16* gA = pT + ((size_t)bh << 20) + (size_t)t0 * 1024;
    const bf16* gB = vT + ((size_t)bh << 16);

    auto load_stage = [&](int s, int c) {
        const uint32_t st = sb + (uint32_t)s * AV_STAGE;
        const int kb = c << 7;
        #pragma unroll
        for (int i = 0; i < 8; i++) {
            int idx = tid + (i << 8);
            int row = idx >> 4, ch = idx & 15;
            uint32_t dst = st + (uint32_t)(row << 8) + (uint32_t)((ch ^ (row & 7)) << 4);
            cp_async16(dst, gA + (size_t)row * 1024 + kb + (ch << 3));
        }
        #pragma unroll
        for (int i = 0; i < 4; i++) {
            int idx = tid + (i << 8);
            int row = idx >> 4, ch = idx & 15;
            uint32_t dst = st + 32768u + (uint32_t)(row << 8) + (uint32_t)((ch ^ (row & 7)) << 4);
            cp_async16(dst, gB + (size_t)row * 1024 + kb + (ch << 3));
        }
        asm volatile("cp.async.commit_group;" ::: "memory");
    };

    const int wm = (wid & 3) << 5, wn = (wid >> 2) << 5;
    float acc[2][4][4];
    #pragma unroll
    for (int i = 0; i < 2; i++)
        #pragma unroll
        for (int j = 0; j < 4; j++)
            #pragma unroll
            for (int q = 0; q < 4; q++) acc[i][j][q] = 0.f;

    const int a_row = lane & 15, a_cb = (lane >> 4) << 4;
    const int b_row = (lane & 7) + ((lane >> 4) << 3), b_cb = ((lane >> 3) & 1) << 4;
    const uint32_t swz = (uint32_t)((lane & 7) << 4);

    load_stage(0, 0);
    for (int c = 0; c < 8; c++) {
        const int s = c & 1;
        if (c + 1 < 8) {
            load_stage(s ^ 1, c + 1);
            asm volatile("cp.async.wait_group 1;" ::: "memory");
        } else {
            asm volatile("cp.async.wait_group 0;" ::: "memory");
        }
        __syncthreads();

        const uint32_t st = sb + (uint32_t)s * AV_STAGE;
        #pragma unroll
        for (int kk = 0; kk < 8; kk++) {
            uint32_t af[2][4], bf2[2][4];
            #pragma unroll
            for (int mi = 0; mi < 2; mi++) {
                int row = wm + (mi << 4) + a_row;
                uint32_t off = (uint32_t)(row << 8) + (((uint32_t)((kk << 5) + a_cb)) ^ swz);
                LDSM4(af[mi], st + off);
            }
            #pragma unroll
            for (int j = 0; j < 2; j++) {
                int row = wn + (j << 4) + b_row;
                uint32_t off = (uint32_t)(row << 8) + (((uint32_t)((kk << 5) + b_cb)) ^ swz);
                LDSM4(bf2[j], st + 32768u + off);
            }
            #pragma unroll
            for (int mi = 0; mi < 2; mi++) {
                #pragma unroll
                for (int nj = 0; nj < 4; nj++) {
                    MMA16816(acc[mi][nj], af[mi],
                             bf2[nj >> 1][(nj & 1) << 1], bf2[nj >> 1][((nj & 1) << 1) + 1]);
                }
            }
        }
        __syncthreads();
    }

    const int b = bh >> 4, h = bh & 15;
    const int er = t0 + wm + (lane >> 2);
    const int ec = wn + ((lane & 3) << 1);
    #pragma unroll
    for (int mi = 0; mi < 2; mi++) {
        #pragma unroll
        for (int hf = 0; hf < 2; hf++) {
            int t = er + (mi << 4) + (hf << 3);
            size_t rowbase = ((size_t)(b << 10) + t) * 1024 + (h << 6);
            #pragma unroll
            for (int nj = 0; nj < 4; nj++) {
                int col = ec + (nj << 3);
                bf16 h0, l0, h1, l1;
                split2(acc[mi][nj][hf * 2], h0, l0);
                split2(acc[mi][nj][hf * 2 + 1], h1, l1);
                *(uint32_t*)&Mh[rowbase + col] = pack_bf(h0, h1);
                *(uint32_t*)&Ml[rowbase + col] = pack_bf(l0, l1);
            }
        }
    }
}

// ---------------- block reductions ----------------
__device__ __forceinline__ float blockReduceSum(float v) {
    __shared__ float sh[33];
    int lane = threadIdx.x & 31, w = threadIdx.x >> 5;
    #pragma unroll
    for (int o = 16; o > 0; o >>= 1) v += __shfl_xor_sync(0xffffffffu, v, o);
    __syncthreads();
    if (lane == 0) sh[w] = v;
    __syncthreads();
    if (w == 0) {
        v = (lane < (int)(blockDim.x >> 5)) ? sh[lane] : 0.f;
        #pragma unroll
        for (int o = 16; o > 0; o >>= 1) v += __shfl_xor_sync(0xffffffffu, v, o);
        if (lane == 0) sh[32] = v;
    }
    __syncthreads();
    return sh[32];
}
__device__ __forceinline__ float blockReduceMax(float v) {
    __shared__ float sh[33];
    int lane = threadIdx.x & 31, w = threadIdx.x >> 5;
    #pragma unroll
    for (int o = 16; o > 0; o >>= 1) v = fmaxf(v, __shfl_xor_sync(0xffffffffu, v, o));
    __syncthreads();
    if (lane == 0) sh[w] = v;
    __syncthreads();
    if (w == 0) {
        v = (lane < (int)(blockDim.x >> 5)) ? sh[lane] : -3.402823466e38f;
        #pragma unroll
        for (int o = 16; o > 0; o >>= 1) v = fmaxf(v, __shfl_xor_sync(0xffffffffu, v, o));
        if (lane == 0) sh[32] = v;
    }
    __syncthreads();
    return sh[32];
}

// ---------------- embedding: x fp32 + hi/lo bf16 ----------------
__global__ void embed_kernel(const int* __restrict__ tokens,
                             const float* __restrict__ tok,
                             const float* __restrict__ pos,
                             float* __restrict__ x,
                             bf16* __restrict__ xh, bf16* __restrict__ xl) {
    int idx = blockIdx.x * blockDim.x + threadIdx.x;
    const int EV = En / 4;
    if (idx >= NTOK * EV) return;
    int bs = idx / EV, e4 = idx % EV;
    int s = bs & (Sn - 1);
    int t = tokens[bs];
    float4 a = ((const float4*)tok)[(size_t)t * EV + e4];
    float4 p = ((const float4*)pos)[(size_t)s * EV + e4];
    float4 r;
    r.x = a.x + p.x; r.y = a.y + p.y; r.z = a.z + p.z; r.w = a.w + p.w;
    ((float4*)x)[idx] = r;
    bf16 h0, l0, h1, l1, h2, l2, h3, l3;
    split2(r.x, h0, l0); split2(r.y, h1, l1);
    split2(r.z, h2, l2); split2(r.w, h3, l3);
    ((uint2*)xh)[idx] = make_uint2(pack_bf(h0, h1), pack_bf(h2, h3));
    ((uint2*)xl)[idx] = make_uint2(pack_bf(l0, l1), pack_bf(l2, l3));
}

// ---------------- rmsnorm -> hi/lo bf16 ----------------
__global__ void add_rmsnorm_kernel(const float* __restrict__ x, const float* __restrict__ add,
                                   const float* __restrict__ scale,
                                   bf16* __restrict__ oh, bf16* __restrict__ ol)
{
    int row = blockIdx.x, tid = threadIdx.x;
    const float* xr = x + (size_t)row * En;
    const float* ar = add ? add + (size_t)row * En : nullptr;
    float v[4]; float ss = 0.f;
    #pragma unroll
    for (int j = 0; j < 4; j++) {
        int e = tid + j * 256;
        float t = xr[e];
        if (ar) t += ar[e];
        v[j] = t;
        ss += t * t;
    }
    ss = blockReduceSum(ss);
    float r = rsqrtf(ss * (1.f / En) + 1e-6f);
    #pragma unroll
    for (int j = 0; j < 4; j++) {
        int e = tid + j * 256;
        float t = v[j] * r * scale[e];
        bf16 h, l;
        split2(t, h, l);
        oh[(size_t)row * En + e] = h;
        ol[(size_t)row * En + e] = l;
    }
}

// ---------------- log_softmax ----------------
__global__ void log_softmax_kernel(float* __restrict__ a) {
    float* row = a + (size_t)blockIdx.x * Vn;
    int tid = threadIdx.x;
    float m = -3.402823466e38f;
    for (int i = tid; i < Vn; i += 256) m = fmaxf(m, row[i]);
    m = blockReduceMax(m);
    float s = 0.f;
    for (int i = tid; i < Vn; i += 256) s += __expf(row[i] - m);
    s = blockReduceSum(s);
    float lse = m + logf(s);
    for (int i = tid; i < Vn; i += 256) row[i] -= lse;
}

// ---------------- launch ----------------
extern "C" void kernel_launch(void* const* d_in, const int* in_sizes, int n_in,
                              void* d_out, int out_size) {
    const int*   tokens      = (const int*)  d_in[0];
    const float* tok_embed   = (const float*)d_in[1];
    const float* pos_embed   = (const float*)d_in[2];
    const float* Qw          = (const float*)d_in[3];
    const float* Kw          = (const float*)d_in[4];
    const float* Vw          = (const float*)d_in[5];
    const float* Ow          = (const float*)d_in[6];
    const float* rs2         = (const float*)d_in[7];
    const float* w1          = (const float*)d_in[8];
    const float* b1          = (const float*)d_in[9];
    const float* w2          = (const float*)d_in[10];
    const float* b2          = (const float*)d_in[11];
    const float* final_scale = (const float*)d_in[12];
    const float* w_out       = (const float*)d_in[13];
    const float* b_out       = (const float*)d_in[14];
    float* out = (float*)d_out;

    float *xb, *projb;
    __half* attb;
    bf16 *whi, *wlo, *ptb, *xh, *xl, *qh, *ql, *kh, *kl, *vt, *mh, *ml, *rh, *rl, *hh, *hl;
    cudaGetSymbolAddress((void**)&xb,    g_x);
    cudaGetSymbolAddress((void**)&projb, g_proj);
    cudaGetSymbolAddress((void**)&attb,  g_att);
    cudaGetSymbolAddress((void**)&ptb,   g_pt);
    cudaGetSymbolAddress((void**)&whi,   g_whi);
    cudaGetSymbolAddress((void**)&wlo,   g_wlo);
    cudaGetSymbolAddress((void**)&xh,    g_xh);
    cudaGetSymbolAddress((void**)&xl,    g_xl);
    cudaGetSymbolAddress((void**)&qh,    g_qh);
    cudaGetSymbolAddress((void**)&ql,    g_ql);
    cudaGetSymbolAddress((void**)&kh,    g_kh);
    cudaGetSymbolAddress((void**)&kl,    g_kl);
    cudaGetSymbolAddress((void**)&vt,    g_vt);
    cudaGetSymbolAddress((void**)&mh,    g_mh);
    cudaGetSymbolAddress((void**)&ml,    g_ml);
    cudaGetSymbolAddress((void**)&rh,    g_rh);
    cudaGetSymbolAddress((void**)&rl,    g_rl);
    cudaGetSymbolAddress((void**)&hh,    g_hh);
    cudaGetSymbolAddress((void**)&hl,    g_hl);

    cudaFuncSetAttribute(gemm_mma,    cudaFuncAttributeMaxDynamicSharedMemorySize, GM_SMEM);
    cudaFuncSetAttribute(scoresT_mma, cudaFuncAttributeMaxDynamicSharedMemorySize, SC_SMEM);
    cudaFuncSetAttribute(av_mma,      cudaFuncAttributeMaxDynamicSharedMemorySize, AV_SMEM);

    // ---- weight bf16 split (streaming, no transpose): 7 launches, all layers at once ----
    {
        const int n4_w  = (int)(Lnum * M1 / 4);       // 1M float4 per 1024x1024x4L tensor
        const int n4_ff = (int)(Lnum * 4 * M1 / 4);   // 4M float4
        const int n4_vo = (int)((size_t)Vn * En / 4); // 8.192M float4
        convert_w<<<(n4_w  + 255) / 256, 256>>>(Qw,    whi,                 wlo,                 n4_w);
        convert_w<<<(n4_w  + 255) / 256, 256>>>(Kw,    whi + 4 * (size_t)M1,  wlo + 4 * (size_t)M1,  n4_w);
        convert_w<<<(n4_w  + 255) / 256, 256>>>(Vw,    whi + 8 * (size_t)M1,  wlo + 8 * (size_t)M1,  n4_w);
        convert_w<<<(n4_w  + 255) / 256, 256>>>(Ow,    whi + 12 * (size_t)M1, wlo + 12 * (size_t)M1, n4_w);
        convert_w<<<(n4_ff + 255) / 256, 256>>>(w1,    whi + 16 * (size_t)M1, wlo + 16 * (size_t)M1, n4_ff);
        convert_w<<<(n4_ff + 255) / 256, 256>>>(w2,    whi + 32 * (size_t)M1, wlo + 32 * (size_t)M1, n4_ff);
        convert_w<<<(n4_vo + 255) / 256, 256>>>(w_out, whi + 48 * (size_t)M1, wlo + 48 * (size_t)M1, n4_vo);
    }

    embed_kernel<<<(NTOK * (En / 4) + 255) / 256, 256>>>(tokens, tok_embed, pos_embed, xb, xh, xl);

    for (int l = 0; l < Lnum; l++) {
        const bf16 *Qh = whi + (size_t)l * M1,                   *Ql2 = wlo + (size_t)l * M1;
        const bf16 *Kh = whi + 4 * (size_t)M1 + (size_t)l * M1,  *Kl2 = wlo + 4 * (size_t)M1 + (size_t)l * M1;
        const bf16 *Vh = whi + 8 * (size_t)M1 + (size_t)l * M1,  *Vl2 = wlo + 8 * (size_t)M1 + (size_t)l * M1;
        const bf16 *Oh = whi + 12 * (size_t)M1 + (size_t)l * M1, *Ol2 = wlo + 12 * (size_t)M1 + (size_t)l * M1;
        const bf16 *W1h = whi + 16 * (size_t)M1 + (size_t)l * 4 * M1,
                   *W1l = wlo + 16 * (size_t)M1 + (size_t)l * 4 * M1;
        const bf16 *W2h = whi + 32 * (size_t)M1 + (size_t)l * 4 * M1,
                   *W2l = wlo + 32 * (size_t)M1 + (size_t)l * 4 * M1;
        const float* r2l = rs2 + (size_t)l * En;
        const float* b1l = b1 + (size_t)l * FFn;
        const float* b2l = b2 + (size_t)l * En;

        dim3 g1024(HIDn / 128, NTOK / 128);
        gemm_mma<<<g1024, 256, GM_SMEM>>>(xh, xl, Qh, Ql2, nullptr, nullptr,
                                          nullptr, qh, ql, NTOK, HIDn, En, 0, 3);
        gemm_mma<<<g1024, 256, GM_SMEM>>>(xh, xl, Kh, Kl2, nullptr, nullptr,
                                          nullptr, kh, kl, NTOK, HIDn, En, 0, 3);
        gemm_mma<<<g1024, 256, GM_SMEM>>>(xh, xl, Vh, Vl2, nullptr, nullptr,
                                          nullptr, vt, nullptr, NTOK, HIDn, En, 0, 4);

        scoresT_mma<<<dim3(Sn / 128, Sn / 128, Bn * NHn), 256, SC_SMEM>>>(kh, kl, qh, ql, attb);
        col_softmax<<<dim3(Sn / 64, Bn * NHn), 256>>>(attb, ptb);
        av_mma<<<dim3(Sn / 128, Bn * NHn), 256, AV_SMEM>>>(ptb, vt, mh, ml);

        gemm_mma<<<g1024, 256, GM_SMEM>>>(mh, ml, Oh, Ol2, nullptr, nullptr,
                                          projb, nullptr, nullptr, NTOK, En, HIDn, 0, 0);
        add_rmsnorm_kernel<<<NTOK, 256>>>(xb, projb, r2l, rh, rl);

        gemm_mma<<<dim3(FFn / 128, NTOK / 128), 256, GM_SMEM>>>(rh, rl, W1h, W1l, b1l, nullptr,
                                                                nullptr, hh, hl, NTOK, FFn, En, 1 | 2, 2);
        gemm_mma<<<g1024, 256, GM_SMEM>>>(hh, hl, W2h, W2l, b2l, projb,
                                          xb, xh, xl, NTOK, En, FFn, 1 | 4, 1);
    }

    add_rmsnorm_kernel<<<NTOK, 256>>>(xb, nullptr, final_scale, xh, xl);

    gemm_mma<<<dim3(Vn / 128, NTOK / 128), 256, GM_SMEM>>>(xh, xl, whi + 48 * (size_t)M1,
                                                           wlo + 48 * (size_t)M1, b_out, nullptr,
                                                           out, nullptr, nullptr, NTOK, Vn, En, 1, 0);
    log_softmax_kernel<<<NTOK, 256>>>(out);
}

// round 13
// speedup vs baseline: 1.0282x; 1.0282x over previous
#include <cuda_runtime.h>
#include <cuda_bf16.h>
#include <cuda_fp16.h>
#include <math.h>
#include <stdint.h>

// ---------------- problem constants ----------------
#define Lnum 4
#define Bn   2
#define Sn   1024
#define En   1024
#define NHn  16
#define HDn  64
#define HIDn 1024
#define FFn  4096
#define Vn   32000
#define NTOK (Bn*Sn)   // 2048
#define M1   (1u<<20)  // 1024*1024

typedef __nv_bfloat16 bf16;

// ---------------- scratch (static device memory; no allocation) ----------------
__device__ float  g_x   [NTOK*En];                 // residual stream fp32
__device__ float  g_proj[NTOK*En];                 // attn projection fp32
__device__ __half g_att [(size_t)Bn*NHn*Sn*Sn];    // scoresT fp16, 64 MB
__device__ bf16   g_pt  [(size_t)Bn*NHn*Sn*Sn];    // probsT bf16, 64 MB

__device__ bf16 g_xh[NTOK*En],  g_xl[NTOK*En];     // x hi/lo
__device__ bf16 g_qh[NTOK*HIDn];                   // q head-major [b,h,s,d] (bf16 single)
__device__ bf16 g_kh[NTOK*HIDn];                   // k head-major (bf16 single)
__device__ bf16 g_vt[NTOK*HIDn];                   // v transposed [b,h,d,s]
__device__ bf16 g_mh[NTOK*En],  g_ml[NTOK*En];     // mha hi/lo (token-major)
__device__ bf16 g_rh[NTOK*En],  g_rl[NTOK*En];     // rmsnorm out hi/lo
__device__ bf16 g_hh[(size_t)NTOK*FFn], g_hl[(size_t)NTOK*FFn]; // FF hidden hi/lo

// bf16 hi/lo transposed weights: [N,K] layout.
#define WTOT (48u*M1 + (size_t)Vn*En)
__device__ bf16 g_whi[WTOT];
__device__ bf16 g_wlo[WTOT];

// ---------------- helpers ----------------
__device__ __forceinline__ uint32_t smem_u32(const void* p) {
    uint32_t a;
    asm("{ .reg .u64 t; cvta.to.shared.u64 t, %1; cvt.u32.u64 %0, t; }" : "=r"(a) : "l"(p));
    return a;
}
__device__ __forceinline__ uint32_t pack_bf(bf16 a, bf16 b) {
    return (uint32_t)__bfloat16_as_ushort(a) | ((uint32_t)__bfloat16_as_ushort(b) << 16);
}
__device__ __forceinline__ void split2(float x, bf16& h, bf16& l) {
    h = __float2bfloat16_rn(x);
    l = __float2bfloat16_rn(x - __bfloat162float(h));
}

#define LDSM4(r, a) \
    asm volatile("ldmatrix.sync.aligned.m8n8.x4.shared.b16 {%0,%1,%2,%3}, [%4];" \
        : "=r"((r)[0]), "=r"((r)[1]), "=r"((r)[2]), "=r"((r)[3]) : "r"(a))

#define MMA16816(d, a, b0, b1) \
    asm volatile("mma.sync.aligned.m16n8k16.row.col.f32.bf16.bf16.f32 " \
        "{%0,%1,%2,%3}, {%4,%5,%6,%7}, {%8,%9}, {%0,%1,%2,%3};" \
        : "+f"((d)[0]), "+f"((d)[1]), "+f"((d)[2]), "+f"((d)[3]) \
        : "r"((a)[0]), "r"((a)[1]), "r"((a)[2]), "r"((a)[3]), "r"(b0), "r"(b1))

__device__ __forceinline__ void cp_async16(uint32_t dst, const void* src) {
    asm volatile("cp.async.cg.shared.global [%0], [%1], 16;" :: "r"(dst), "l"(src));
}

// ---------------- weight transpose + bf16 split: W[K,N] fp32 -> hi/lo [N,K] ----------------
// grid (N/32, K/64), block (32, 8). smem tile stored [n][k] so stores are K-contiguous uint4.
__global__ void convert_w(const float* __restrict__ W, bf16* __restrict__ hi,
                          bf16* __restrict__ lo, int K, int N) {
    __shared__ float t[32][65];
    int n0 = blockIdx.x << 5, k0 = blockIdx.y << 6;
    int tx = threadIdx.x, ty = threadIdx.y;
    #pragma unroll
    for (int j = 0; j < 64; j += 8)
        t[tx][ty + j] = W[(size_t)(k0 + ty + j) * N + n0 + tx];
    __syncthreads();
    int tid = ty * 32 + tx;
    int n = tid >> 3, kc = (tid & 7) << 3;
    uint32_t h4[4], l4[4];
    #pragma unroll
    for (int i = 0; i < 4; i++) {
        float v0 = t[n][kc + 2 * i], v1 = t[n][kc + 2 * i + 1];
        bf16 h0, l0, h1, l1;
        split2(v0, h0, l0); split2(v1, h1, l1);
        h4[i] = pack_bf(h0, h1);
        l4[i] = pack_bf(l0, l1);
    }
    size_t o = (size_t)(n0 + n) * K + k0 + kc;
    *(uint4*)&hi[o] = make_uint4(h4[0], h4[1], h4[2], h4[3]);
    *(uint4*)&lo[o] = make_uint4(l4[0], l4[1], l4[2], l4[3]);
}

// ---------------- mma.sync bf16-split GEMM ----------------
// C[M,N] = A(hi/lo [M,K]) * B(hi/lo [N,K]),  fp32 accum, 3-term split.
// flags: 1 = +bias[N], 2 = relu, 4 = +add (residual, MxN)
// omode: 0 = C fp32 only; 1 = C fp32 + Chi/Clo token-major; 2 = Chi/Clo only;
//        3 = head-major [b,h,s,d] (hi always; lo only if Clo != null);
//        4 = transposed bf16 v [b,h,d,s]
#define STAGE_BYTES 65536
#define GM_SMEM (2*STAGE_BYTES)
__global__ void __launch_bounds__(256, 1) gemm_mma(
    const bf16* __restrict__ Ahi, const bf16* __restrict__ Alo,
    const bf16* __restrict__ Bhi, const bf16* __restrict__ Blo,
    const float* __restrict__ bias, const float* __restrict__ add,
    float* __restrict__ C, bf16* __restrict__ Chi, bf16* __restrict__ Clo,
    int M, int N, int K, int flags, int omode)
{
    extern __shared__ char smem[];
    const uint32_t sb = smem_u32(smem);
    const int tid = threadIdx.x, wid = tid >> 5, lane = tid & 31;
    const int m0 = blockIdx.y << 7, n0 = blockIdx.x << 7;
    const int wm = (wid & 1) << 6;
    const int wn = (wid >> 1) << 5;

    const bf16* gAh = Ahi + (size_t)m0 * K;
    const bf16* gAl = Alo + (size_t)m0 * K;
    const bf16* gBh = Bhi + (size_t)n0 * K;
    const bf16* gBl = Blo + (size_t)n0 * K;

    const int nchunk = K >> 6;
    const int l_row = tid >> 3;
    const int l_ch  = tid & 7;

    auto load_stage = [&](int s, int c) {
        const uint32_t st = sb + (uint32_t)s * STAGE_BYTES;
        const int kb = c << 6;
        const bf16* srcs[4] = { gAh + kb, gAl + kb, gBh + kb, gBl + kb };
        #pragma unroll
        for (int t = 0; t < 4; t++) {
            const uint32_t dstb = st + (uint32_t)t * 16384u;
            #pragma unroll
            for (int i = 0; i < 4; i++) {
                int row = l_row + (i << 5);
                uint32_t dst = dstb + (uint32_t)(row << 7) + (uint32_t)((l_ch ^ (row & 7)) << 4);
                cp_async16(dst, srcs[t] + (size_t)row * K + (l_ch << 3));
            }
        }
        asm volatile("cp.async.commit_group;" ::: "memory");
    };

    float acc[4][4][4];
    #pragma unroll
    for (int i = 0; i < 4; i++)
        #pragma unroll
        for (int j = 0; j < 4; j++)
            #pragma unroll
            for (int q = 0; q < 4; q++) acc[i][j][q] = 0.f;

    const int a_row = lane & 15;
    const int a_cb  = (lane >> 4) << 4;
    const int b_row = (lane & 7) + ((lane >> 4) << 3);
    const int b_cb  = ((lane >> 3) & 1) << 4;
    const uint32_t swz = (uint32_t)((lane & 7) << 4);

    load_stage(0, 0);

    for (int c = 0; c < nchunk; c++) {
        const int s = c & 1;
        if (c + 1 < nchunk) {
            load_stage(s ^ 1, c + 1);
            asm volatile("cp.async.wait_group 1;" ::: "memory");
        } else {
            asm volatile("cp.async.wait_group 0;" ::: "memory");
        }
        __syncthreads();

        const uint32_t st = sb + (uint32_t)s * STAGE_BYTES;
        #pragma unroll
        for (int kk = 0; kk < 4; kk++) {
            uint32_t ah[4][4], al[4][4], bh[2][4], bl[2][4];
            #pragma unroll
            for (int mi = 0; mi < 4; mi++) {
                int row = wm + (mi << 4) + a_row;
                uint32_t off = (uint32_t)(row << 7) + (((uint32_t)((kk << 5) + a_cb)) ^ swz);
                LDSM4(ah[mi], st + off);
                LDSM4(al[mi], st + 16384u + off);
            }
            #pragma unroll
            for (int j = 0; j < 2; j++) {
                int row = wn + (j << 4) + b_row;
                uint32_t off = (uint32_t)(row << 7) + (((uint32_t)((kk << 5) + b_cb)) ^ swz);
                LDSM4(bh[j], st + 32768u + off);
                LDSM4(bl[j], st + 49152u + off);
            }
            #pragma unroll
            for (int mi = 0; mi < 4; mi++) {
                #pragma unroll
                for (int nj = 0; nj < 4; nj++) {
                    uint32_t bh0 = bh[nj >> 1][(nj & 1) << 1], bh1 = bh[nj >> 1][((nj & 1) << 1) + 1];
                    uint32_t bl0 = bl[nj >> 1][(nj & 1) << 1], bl1 = bl[nj >> 1][((nj & 1) << 1) + 1];
                    MMA16816(acc[mi][nj], ah[mi], bh0, bh1);
                    MMA16816(acc[mi][nj], ah[mi], bl0, bl1);
                    MMA16816(acc[mi][nj], al[mi], bh0, bh1);
                }
            }
        }
        __syncthreads();
    }

    // epilogue
    const int er = m0 + wm + (lane >> 2);
    const int ec = n0 + wn + ((lane & 3) << 1);
    #pragma unroll
    for (int mi = 0; mi < 4; mi++) {
        #pragma unroll
        for (int hf = 0; hf < 2; hf++) {
            int row = er + (mi << 4) + (hf << 3);
            const float* Ar = (flags & 4) ? (add + (size_t)row * N) : nullptr;
            int bidx = row >> 10, srow = row & 1023;
            #pragma unroll
            for (int nj = 0; nj < 4; nj++) {
                int col = ec + (nj << 3);
                float v0 = acc[mi][nj][hf * 2 + 0];
                float v1 = acc[mi][nj][hf * 2 + 1];
                if (flags & 1) { v0 += bias[col]; v1 += bias[col + 1]; }
                if (flags & 4) { v0 += Ar[col];   v1 += Ar[col + 1]; }
                if (flags & 2) { v0 = fmaxf(v0, 0.f); v1 = fmaxf(v1, 0.f); }
                if (omode <= 1)
                    *(float2*)(C + (size_t)row * N + col) = make_float2(v0, v1);
                if (omode == 1 || omode == 2) {
                    bf16 h0, l0, h1, l1;
                    split2(v0, h0, l0); split2(v1, h1, l1);
                    *(uint32_t*)&Chi[(size_t)row * N + col] = pack_bf(h0, h1);
                    *(uint32_t*)&Clo[(size_t)row * N + col] = pack_bf(l0, l1);
                } else if (omode == 3) {
                    int h = col >> 6, d = col & 63;
                    size_t dst = (((size_t)((bidx << 4) + h) << 10) + srow) * 64 + d;
                    *(uint32_t*)&Chi[dst] =
                        pack_bf(__float2bfloat16_rn(v0), __float2bfloat16_rn(v1));
                    if (Clo) {
                        bf16 h0, l0, h1, l1;
                        split2(v0, h0, l0); split2(v1, h1, l1);
                        *(uint32_t*)&Chi[dst] = pack_bf(h0, h1);
                        *(uint32_t*)&Clo[dst] = pack_bf(l0, l1);
                    }
                } else if (omode == 4) {
                    int h = col >> 6, d = col & 63;
                    size_t hb = (size_t)((bidx << 4) + h) << 6;
                    Chi[(hb + d) * 1024 + srow]     = __float2bfloat16_rn(v0);
                    Chi[(hb + d + 1) * 1024 + srow] = __float2bfloat16_rn(v1);
                }
            }
        }
    }
}

// ---------------- scoresT: scT[bh][t][s] = 0.125 * k[bh,t,:].q[bh,s,:]  (single bf16, fp16 out) ----------------
#define SC_SMEM 32768
__global__ void __launch_bounds__(256, 1) scoresT_mma(
    const bf16* __restrict__ Kh, const bf16* __restrict__ Qh,
    __half* __restrict__ scT)
{
    extern __shared__ char smem[];
    const uint32_t sb = smem_u32(smem);
    const int tid = threadIdx.x, wid = tid >> 5, lane = tid & 31;
    const int bh = blockIdx.z;
    const int t0 = blockIdx.y << 7, s0 = blockIdx.x << 7;
    const size_t hbase = (size_t)bh << 16;
    const bf16* srcs[2] = { Kh + hbase + (size_t)t0 * 64, Qh + hbase + (size_t)s0 * 64 };

    {
        const int l_row = tid >> 3, l_ch = tid & 7;
        #pragma unroll
        for (int t = 0; t < 2; t++) {
            #pragma unroll
            for (int i = 0; i < 4; i++) {
                int row = l_row + (i << 5);
                uint32_t dst = sb + (uint32_t)t * 16384u + (uint32_t)(row << 7)
                             + (uint32_t)((l_ch ^ (row & 7)) << 4);
                cp_async16(dst, srcs[t] + (size_t)row * 64 + (l_ch << 3));
            }
        }
        asm volatile("cp.async.commit_group;" ::: "memory");
        asm volatile("cp.async.wait_group 0;" ::: "memory");
    }
    __syncthreads();

    const int wm = (wid & 1) << 6, wn = (wid >> 1) << 5;
    float acc[4][4][4];
    #pragma unroll
    for (int i = 0; i < 4; i++)
        #pragma unroll
        for (int j = 0; j < 4; j++)
            #pragma unroll
            for (int q = 0; q < 4; q++) acc[i][j][q] = 0.f;

    const int a_row = lane & 15, a_cb = (lane >> 4) << 4;
    const int b_row = (lane & 7) + ((lane >> 4) << 3), b_cb = ((lane >> 3) & 1) << 4;
    const uint32_t swz = (uint32_t)((lane & 7) << 4);

    #pragma unroll
    for (int kk = 0; kk < 4; kk++) {
        uint32_t ah[4][4], bh2[2][4];
        #pragma unroll
        for (int mi = 0; mi < 4; mi++) {
            int row = wm + (mi << 4) + a_row;
            uint32_t off = (uint32_t)(row << 7) + (((uint32_t)((kk << 5) + a_cb)) ^ swz);
            LDSM4(ah[mi], sb + off);
        }
        #pragma unroll
        for (int j = 0; j < 2; j++) {
            int row = wn + (j << 4) + b_row;
            uint32_t off = (uint32_t)(row << 7) + (((uint32_t)((kk << 5) + b_cb)) ^ swz);
            LDSM4(bh2[j], sb + 16384u + off);
        }
        #pragma unroll
        for (int mi = 0; mi < 4; mi++) {
            #pragma unroll
            for (int nj = 0; nj < 4; nj++) {
                MMA16816(acc[mi][nj], ah[mi],
                         bh2[nj >> 1][(nj & 1) << 1], bh2[nj >> 1][((nj & 1) << 1) + 1]);
            }
        }
    }

    __half* ob = scT + ((size_t)bh << 20);
    const int er = t0 + wm + (lane >> 2);
    const int ec = s0 + wn + ((lane & 3) << 1);
    #pragma unroll
    for (int mi = 0; mi < 4; mi++) {
        #pragma unroll
        for (int hf = 0; hf < 2; hf++) {
            int row = er + (mi << 4) + (hf << 3);
            #pragma unroll
            for (int nj = 0; nj < 4; nj++) {
                int col = ec + (nj << 3);
                *(__half2*)(ob + (size_t)row * Sn + col) =
                    __floats2half2_rn(acc[mi][nj][hf * 2] * 0.125f,
                                      acc[mi][nj][hf * 2 + 1] * 0.125f);
            }
        }
    }
}

// ---------------- parallel column softmax over t (UNMASKED, bug-faithful) ----------------
__global__ void __launch_bounds__(256) col_softmax(const __half* __restrict__ scT,
                                                   bf16* __restrict__ pT) {
    __shared__ float sm0[8][33], sm1[8][33], ss0[8][33], ss1[8][33];
    const int bh = blockIdx.y;
    const int lane = threadIdx.x & 31;
    const int chunk = threadIdx.x >> 5;
    const int s = (blockIdx.x << 6) + (lane << 1);
    const __half* base = scT + ((size_t)bh << 20) + s;
    const int t0 = chunk << 7;
    float cm0 = -3.402823466e38f, cm1 = -3.402823466e38f, cu0 = 0.f, cu1 = 0.f;
    #pragma unroll 4
    for (int t = 0; t < 128; t++) {
        __half2 h = *(const __half2*)(base + ((size_t)(t0 + t) << 10));
        float x0 = __low2float(h), x1 = __high2float(h);
        float n0 = fmaxf(cm0, x0), n1 = fmaxf(cm1, x1);
        cu0 = cu0 * __expf(cm0 - n0) + __expf(x0 - n0);
        cu1 = cu1 * __expf(cm1 - n1) + __expf(x1 - n1);
        cm0 = n0; cm1 = n1;
    }
    sm0[chunk][lane] = cm0; sm1[chunk][lane] = cm1;
    ss0[chunk][lane] = cu0; ss1[chunk][lane] = cu1;
    __syncthreads();
    float gM0 = -3.402823466e38f, gM1 = -3.402823466e38f;
    #pragma unroll
    for (int i = 0; i < 8; i++) {
        gM0 = fmaxf(gM0, sm0[i][lane]);
        gM1 = fmaxf(gM1, sm1[i][lane]);
    }
    float gS0 = 0.f, gS1 = 0.f;
    #pragma unroll
    for (int i = 0; i < 8; i++) {
        gS0 += ss0[i][lane] * __expf(sm0[i][lane] - gM0);
        gS1 += ss1[i][lane] * __expf(sm1[i][lane] - gM1);
    }
    float inv0 = 1.f / gS0, inv1 = 1.f / gS1;
    bf16* ob = pT + ((size_t)bh << 20) + s;
    #pragma unroll 4
    for (int t = 0; t < 128; t++) {
        __half2 h = *(const __half2*)(base + ((size_t)(t0 + t) << 10));
        float p0 = __expf(__low2float(h) - gM0) * inv0;
        float p1 = __expf(__high2float(h) - gM1) * inv1;
        *(uint32_t*)(ob + ((size_t)(t0 + t) << 10)) =
            pack_bf(__float2bfloat16_rn(p0), __float2bfloat16_rn(p1));
    }
}

// ---------------- AV: mha[b,t,h,d] = sum_s pT[bh,t,s] * vT[bh,d,s] ----------------
#define AV_STAGE 49152
#define AV_SMEM (2*AV_STAGE)
__global__ void __launch_bounds__(256, 1) av_mma(
    const bf16* __restrict__ pT, const bf16* __restrict__ vT,
    bf16* __restrict__ Mh, bf16* __restrict__ Ml)
{
    extern __shared__ char smem[];
    const uint32_t sb = smem_u32(smem);
    const int tid = threadIdx.x, wid = tid >> 5, lane = tid & 31;
    const int bh = blockIdx.y, t0 = blockIdx.x << 7;
    const bf16* gA = pT + ((size_t)bh << 20) + (size_t)t0 * 1024;
    const bf16* gB = vT + ((size_t)bh << 16);

    auto load_stage = [&](int s, int c) {
        const uint32_t st = sb + (uint32_t)s * AV_STAGE;
        const int kb = c << 7;
        #pragma unroll
        for (int i = 0; i < 8; i++) {
            int idx = tid + (i << 8);
            int row = idx >> 4, ch = idx & 15;
            uint32_t dst = st + (uint32_t)(row << 8) + (uint32_t)((ch ^ (row & 7)) << 4);
            cp_async16(dst, gA + (size_t)row * 1024 + kb + (ch << 3));
        }
        #pragma unroll
        for (int i = 0; i < 4; i++) {
            int idx = tid + (i << 8);
            int row = idx >> 4, ch = idx & 15;
            uint32_t dst = st + 32768u + (uint32_t)(row << 8) + (uint32_t)((ch ^ (row & 7)) << 4);
            cp_async16(dst, gB + (size_t)row * 1024 + kb + (ch << 3));
        }
        asm volatile("cp.async.commit_group;" ::: "memory");
    };

    const int wm = (wid & 3) << 5, wn = (wid >> 2) << 5;
    float acc[2][4][4];
    #pragma unroll
    for (int i = 0; i < 2; i++)
        #pragma unroll
        for (int j = 0; j < 4; j++)
            #pragma unroll
            for (int q = 0; q < 4; q++) acc[i][j][q] = 0.f;

    const int a_row = lane & 15, a_cb = (lane >> 4) << 4;
    const int b_row = (lane & 7) + ((lane >> 4) << 3), b_cb = ((lane >> 3) & 1) << 4;
    const uint32_t swz = (uint32_t)((lane & 7) << 4);

    load_stage(0, 0);
    for (int c = 0; c < 8; c++) {
        const int s = c & 1;
        if (c + 1 < 8) {
            load_stage(s ^ 1, c + 1);
            asm volatile("cp.async.wait_group 1;" ::: "memory");
        } else {
            asm volatile("cp.async.wait_group 0;" ::: "memory");
        }
        __syncthreads();

        const uint32_t st = sb + (uint32_t)s * AV_STAGE;
        #pragma unroll
        for (int kk = 0; kk < 8; kk++) {
            uint32_t af[2][4], bf2[2][4];
            #pragma unroll
            for (int mi = 0; mi < 2; mi++) {
                int row = wm + (mi << 4) + a_row;
                uint32_t off = (uint32_t)(row << 8) + (((uint32_t)((kk << 5) + a_cb)) ^ swz);
                LDSM4(af[mi], st + off);
            }
            #pragma unroll
            for (int j = 0; j < 2; j++) {
                int row = wn + (j << 4) + b_row;
                uint32_t off = (uint32_t)(row << 8) + (((uint32_t)((kk << 5) + b_cb)) ^ swz);
                LDSM4(bf2[j], st + 32768u + off);
            }
            #pragma unroll
            for (int mi = 0; mi < 2; mi++) {
                #pragma unroll
                for (int nj = 0; nj < 4; nj++) {
                    MMA16816(acc[mi][nj], af[mi],
                             bf2[nj >> 1][(nj & 1) << 1], bf2[nj >> 1][((nj & 1) << 1) + 1]);
                }
            }
        }
        __syncthreads();
    }

    const int b = bh >> 4, h = bh & 15;
    const int er = t0 + wm + (lane >> 2);
    const int ec = wn + ((lane & 3) << 1);
    #pragma unroll
    for (int mi = 0; mi < 2; mi++) {
        #pragma unroll
        for (int hf = 0; hf < 2; hf++) {
            int t = er + (mi << 4) + (hf << 3);
            size_t rowbase = ((size_t)(b << 10) + t) * 1024 + (h << 6);
            #pragma unroll
            for (int nj = 0; nj < 4; nj++) {
                int col = ec + (nj << 3);
                bf16 h0, l0, h1, l1;
                split2(acc[mi][nj][hf * 2], h0, l0);
                split2(acc[mi][nj][hf * 2 + 1], h1, l1);
                *(uint32_t*)&Mh[rowbase + col] = pack_bf(h0, h1);
                *(uint32_t*)&Ml[rowbase + col] = pack_bf(l0, l1);
            }
        }
    }
}

// ---------------- block reductions ----------------
__device__ __forceinline__ float blockReduceSum(float v) {
    __shared__ float sh[33];
    int lane = threadIdx.x & 31, w = threadIdx.x >> 5;
    #pragma unroll
    for (int o = 16; o > 0; o >>= 1) v += __shfl_xor_sync(0xffffffffu, v, o);
    __syncthreads();
    if (lane == 0) sh[w] = v;
    __syncthreads();
    if (w == 0) {
        v = (lane < (int)(blockDim.x >> 5)) ? sh[lane] : 0.f;
        #pragma unroll
        for (int o = 16; o > 0; o >>= 1) v += __shfl_xor_sync(0xffffffffu, v, o);
        if (lane == 0) sh[32] = v;
    }
    __syncthreads();
    return sh[32];
}
__device__ __forceinline__ float blockReduceMax(float v) {
    __shared__ float sh[33];
    int lane = threadIdx.x & 31, w = threadIdx.x >> 5;
    #pragma unroll
    for (int o = 16; o > 0; o >>= 1) v = fmaxf(v, __shfl_xor_sync(0xffffffffu, v, o));
    __syncthreads();
    if (lane == 0) sh[w] = v;
    __syncthreads();
    if (w == 0) {
        v = (lane < (int)(blockDim.x >> 5)) ? sh[lane] : -3.402823466e38f;
        #pragma unroll
        for (int o = 16; o > 0; o >>= 1) v = fmaxf(v, __shfl_xor_sync(0xffffffffu, v, o));
        if (lane == 0) sh[32] = v;
    }
    __syncthreads();
    return sh[32];
}

// ---------------- embedding: x fp32 + hi/lo bf16 ----------------
__global__ void embed_kernel(const int* __restrict__ tokens,
                             const float* __restrict__ tok,
                             const float* __restrict__ pos,
                             float* __restrict__ x,
                             bf16* __restrict__ xh, bf16* __restrict__ xl) {
    int idx = blockIdx.x * blockDim.x + threadIdx.x;
    const int EV = En / 4;
    if (idx >= NTOK * EV) return;
    int bs = idx / EV, e4 = idx % EV;
    int s = bs & (Sn - 1);
    int t = tokens[bs];
    float4 a = ((const float4*)tok)[(size_t)t * EV + e4];
    float4 p = ((const float4*)pos)[(size_t)s * EV + e4];
    float4 r;
    r.x = a.x + p.x; r.y = a.y + p.y; r.z = a.z + p.z; r.w = a.w + p.w;
    ((float4*)x)[idx] = r;
    bf16 h0, l0, h1, l1, h2, l2, h3, l3;
    split2(r.x, h0, l0); split2(r.y, h1, l1);
    split2(r.z, h2, l2); split2(r.w, h3, l3);
    ((uint2*)xh)[idx] = make_uint2(pack_bf(h0, h1), pack_bf(h2, h3));
    ((uint2*)xl)[idx] = make_uint2(pack_bf(l0, l1), pack_bf(l2, l3));
}

// ---------------- rmsnorm -> hi/lo bf16 ----------------
__global__ void add_rmsnorm_kernel(const float* __restrict__ x, const float* __restrict__ add,
                                   const float* __restrict__ scale,
                                   bf16* __restrict__ oh, bf16* __restrict__ ol)
{
    int row = blockIdx.x, tid = threadIdx.x;
    const float* xr = x + (size_t)row * En;
    const float* ar = add ? add + (size_t)row * En : nullptr;
    float v[4]; float ss = 0.f;
    #pragma unroll
    for (int j = 0; j < 4; j++) {
        int e = tid + j * 256;
        float t = xr[e];
        if (ar) t += ar[e];
        v[j] = t;
        ss += t * t;
    }
    ss = blockReduceSum(ss);
    float r = rsqrtf(ss * (1.f / En) + 1e-6f);
    #pragma unroll
    for (int j = 0; j < 4; j++) {
        int e = tid + j * 256;
        float t = v[j] * r * scale[e];
        bf16 h, l;
        split2(t, h, l);
        oh[(size_t)row * En + e] = h;
        ol[(size_t)row * En + e] = l;
    }
}

// ---------------- log_softmax ----------------
__global__ void log_softmax_kernel(float* __restrict__ a) {
    float* row = a + (size_t)blockIdx.x * Vn;
    int tid = threadIdx.x;
    float m = -3.402823466e38f;
    for (int i = tid; i < Vn; i += 256) m = fmaxf(m, row[i]);
    m = blockReduceMax(m);
    float s = 0.f;
    for (int i = tid; i < Vn; i += 256) s += __expf(row[i] - m);
    s = blockReduceSum(s);
    float lse = m + logf(s);
    for (int i = tid; i < Vn; i += 256) row[i] -= lse;
}

// ---------------- launch ----------------
extern "C" void kernel_launch(void* const* d_in, const int* in_sizes, int n_in,
                              void* d_out, int out_size) {
    const int*   tokens      = (const int*)  d_in[0];
    const float* tok_embed   = (const float*)d_in[1];
    const float* pos_embed   = (const float*)d_in[2];
    const float* Qw          = (const float*)d_in[3];
    const float* Kw          = (const float*)d_in[4];
    const float* Vw          = (const float*)d_in[5];
    const float* Ow          = (const float*)d_in[6];
    const float* rs2         = (const float*)d_in[7];
    const float* w1          = (const float*)d_in[8];
    const float* b1          = (const float*)d_in[9];
    const float* w2          = (const float*)d_in[10];
    const float* b2          = (const float*)d_in[11];
    const float* final_scale = (const float*)d_in[12];
    const float* w_out       = (const float*)d_in[13];
    const float* b_out       = (const float*)d_in[14];
    float* out = (float*)d_out;

    float *xb, *projb;
    __half* attb;
    bf16 *whi, *wlo, *ptb, *xh, *xl, *qh, *kh, *vt, *mh, *ml, *rh, *rl, *hh, *hl;
    cudaGetSymbolAddress((void**)&xb,    g_x);
    cudaGetSymbolAddress((void**)&projb, g_proj);
    cudaGetSymbolAddress((void**)&attb,  g_att);
    cudaGetSymbolAddress((void**)&ptb,   g_pt);
    cudaGetSymbolAddress((void**)&whi,   g_whi);
    cudaGetSymbolAddress((void**)&wlo,   g_wlo);
    cudaGetSymbolAddress((void**)&xh,    g_xh);
    cudaGetSymbolAddress((void**)&xl,    g_xl);
    cudaGetSymbolAddress((void**)&qh,    g_qh);
    cudaGetSymbolAddress((void**)&kh,    g_kh);
    cudaGetSymbolAddress((void**)&vt,    g_vt);
    cudaGetSymbolAddress((void**)&mh,    g_mh);
    cudaGetSymbolAddress((void**)&ml,    g_ml);
    cudaGetSymbolAddress((void**)&rh,    g_rh);
    cudaGetSymbolAddress((void**)&rl,    g_rl);
    cudaGetSymbolAddress((void**)&hh,    g_hh);
    cudaGetSymbolAddress((void**)&hl,    g_hl);

    cudaFuncSetAttribute(gemm_mma,    cudaFuncAttributeMaxDynamicSharedMemorySize, GM_SMEM);
    cudaFuncSetAttribute(scoresT_mma, cudaFuncAttributeMaxDynamicSharedMemorySize, SC_SMEM);
    cudaFuncSetAttribute(av_mma,      cudaFuncAttributeMaxDynamicSharedMemorySize, AV_SMEM);

    // ---- weight conversion: transpose + bf16 split ----
    dim3 cb(32, 8);
    for (int l = 0; l < Lnum; l++) {
        convert_w<<<dim3(32, 16), cb>>>(Qw + (size_t)l * M1, whi + (size_t)l * M1,
                                        wlo + (size_t)l * M1, En, HIDn);
        convert_w<<<dim3(32, 16), cb>>>(Kw + (size_t)l * M1, whi + 4 * (size_t)M1 + (size_t)l * M1,
                                        wlo + 4 * (size_t)M1 + (size_t)l * M1, En, HIDn);
        convert_w<<<dim3(32, 16), cb>>>(Vw + (size_t)l * M1, whi + 8 * (size_t)M1 + (size_t)l * M1,
                                        wlo + 8 * (size_t)M1 + (size_t)l * M1, En, HIDn);
        convert_w<<<dim3(32, 16), cb>>>(Ow + (size_t)l * M1, whi + 12 * (size_t)M1 + (size_t)l * M1,
                                        wlo + 12 * (size_t)M1 + (size_t)l * M1, HIDn, En);
        convert_w<<<dim3(128, 16), cb>>>(w1 + (size_t)l * 4 * M1,
                                         whi + 16 * (size_t)M1 + (size_t)l * 4 * M1,
                                         wlo + 16 * (size_t)M1 + (size_t)l * 4 * M1, En, FFn);
        convert_w<<<dim3(32, 64), cb>>>(w2 + (size_t)l * 4 * M1,
                                        whi + 32 * (size_t)M1 + (size_t)l * 4 * M1,
                                        wlo + 32 * (size_t)M1 + (size_t)l * 4 * M1, FFn, En);
    }
    convert_w<<<dim3(Vn / 32, 16), cb>>>(w_out, whi + 48 * (size_t)M1, wlo + 48 * (size_t)M1, En, Vn);

    embed_kernel<<<(NTOK * (En / 4) + 255) / 256, 256>>>(tokens, tok_embed, pos_embed, xb, xh, xl);

    for (int l = 0; l < Lnum; l++) {
        const bf16 *Qh = whi + (size_t)l * M1,                   *Ql2 = wlo + (size_t)l * M1;
        const bf16 *Kh = whi + 4 * (size_t)M1 + (size_t)l * M1,  *Kl2 = wlo + 4 * (size_t)M1 + (size_t)l * M1;
        const bf16 *Vh = whi + 8 * (size_t)M1 + (size_t)l * M1,  *Vl2 = wlo + 8 * (size_t)M1 + (size_t)l * M1;
        const bf16 *Oh = whi + 12 * (size_t)M1 + (size_t)l * M1, *Ol2 = wlo + 12 * (size_t)M1 + (size_t)l * M1;
        const bf16 *W1h = whi + 16 * (size_t)M1 + (size_t)l * 4 * M1,
                   *W1l = wlo + 16 * (size_t)M1 + (size_t)l * 4 * M1;
        const bf16 *W2h = whi + 32 * (size_t)M1 + (size_t)l * 4 * M1,
                   *W2l = wlo + 32 * (size_t)M1 + (size_t)l * 4 * M1;
        const float* r2l = rs2 + (size_t)l * En;
        const float* b1l = b1 + (size_t)l * FFn;
        const float* b2l = b2 + (size_t)l * En;

        dim3 g1024(HIDn / 128, NTOK / 128);
        gemm_mma<<<g1024, 256, GM_SMEM>>>(xh, xl, Qh, Ql2, nullptr, nullptr,
                                          nullptr, qh, nullptr, NTOK, HIDn, En, 0, 3);
        gemm_mma<<<g1024, 256, GM_SMEM>>>(xh, xl, Kh, Kl2, nullptr, nullptr,
                                          nullptr, kh, nullptr, NTOK, HIDn, En, 0, 3);
        gemm_mma<<<g1024, 256, GM_SMEM>>>(xh, xl, Vh, Vl2, nullptr, nullptr,
                                          nullptr, vt, nullptr, NTOK, HIDn, En, 0, 4);

        scoresT_mma<<<dim3(Sn / 128, Sn / 128, Bn * NHn), 256, SC_SMEM>>>(kh, qh, attb);
        col_softmax<<<dim3(Sn / 64, Bn * NHn), 256>>>(attb, ptb);
        av_mma<<<dim3(Sn / 128, Bn * NHn), 256, AV_SMEM>>>(ptb, vt, mh, ml);

        gemm_mma<<<g1024, 256, GM_SMEM>>>(mh, ml, Oh, Ol2, nullptr, nullptr,
                                          projb, nullptr, nullptr, NTOK, En, HIDn, 0, 0);
        add_rmsnorm_kernel<<<NTOK, 256>>>(xb, projb, r2l, rh, rl);

        gemm_mma<<<dim3(FFn / 128, NTOK / 128), 256, GM_SMEM>>>(rh, rl, W1h, W1l, b1l, nullptr,
                                                                nullptr, hh, hl, NTOK, FFn, En, 1 | 2, 2);
        gemm_mma<<<g1024, 256, GM_SMEM>>>(hh, hl, W2h, W2l, b2l, projb,
                                          xb, xh, xl, NTOK, En, FFn, 1 | 4, 1);
    }

    add_rmsnorm_kernel<<<NTOK, 256>>>(xb, nullptr, final_scale, xh, xl);

    gemm_mma<<<dim3(Vn / 128, NTOK / 128), 256, GM_SMEM>>>(xh, xl, whi + 48 * (size_t)M1,
                                                           wlo + 48 * (size_t)M1, b_out, nullptr,
                                                           out, nullptr, nullptr, NTOK, Vn, En, 1, 0);
    log_softmax_kernel<<<NTOK, 256>>>(out);
}

// round 14
// speedup vs baseline: 1.0385x; 1.0100x over previous
#include <cuda_runtime.h>
#include <cuda_bf16.h>
#include <cuda_fp16.h>
#include <math.h>
#include <stdint.h>

// ---------------- problem constants ----------------
#define Lnum 4
#define Bn   2
#define Sn   1024
#define En   1024
#define NHn  16
#define HDn  64
#define HIDn 1024
#define FFn  4096
#define Vn   32000
#define NTOK (Bn*Sn)   // 2048
#define M1   (1u<<20)  // 1024*1024

typedef __nv_bfloat16 bf16;

// ---------------- scratch (static device memory; no allocation) ----------------
__device__ float  g_x   [NTOK*En];                 // residual stream fp32
__device__ float  g_proj[NTOK*En];                 // attn projection fp32
__device__ __half g_att [(size_t)Bn*NHn*Sn*Sn];    // scoresT fp16, 64 MB
__device__ bf16   g_pt  [(size_t)Bn*NHn*Sn*Sn];    // probsT bf16, 64 MB

__device__ bf16 g_xh[NTOK*En],  g_xl[NTOK*En];     // x hi/lo
__device__ bf16 g_qh[NTOK*HIDn];                   // q head-major [b,h,s,d] (bf16 single)
__device__ bf16 g_kh[NTOK*HIDn];                   // k head-major (bf16 single)
__device__ bf16 g_vt[NTOK*HIDn];                   // v transposed [b,h,d,s]
__device__ bf16 g_mh[NTOK*En],  g_ml[NTOK*En];     // mha hi/lo (token-major)
__device__ bf16 g_rh[NTOK*En],  g_rl[NTOK*En];     // rmsnorm out hi/lo
__device__ bf16 g_hh[(size_t)NTOK*FFn], g_hl[(size_t)NTOK*FFn]; // FF hidden hi/lo

// bf16 hi/lo transposed weights: [N,K] layout.
// QKV interleaved: [l][3][N][K] at offset (l*3+j)*M1.  O at 12M1+l*M1.
// W1 16M1+l*4M1 | W2 32M1+l*4M1 | Wout 48M1.
#define WTOT (48u*M1 + (size_t)Vn*En)
__device__ bf16 g_whi[WTOT];
__device__ bf16 g_wlo[WTOT];

// ---------------- helpers ----------------
__device__ __forceinline__ uint32_t smem_u32(const void* p) {
    uint32_t a;
    asm("{ .reg .u64 t; cvta.to.shared.u64 t, %1; cvt.u32.u64 %0, t; }" : "=r"(a) : "l"(p));
    return a;
}
__device__ __forceinline__ uint32_t pack_bf(bf16 a, bf16 b) {
    return (uint32_t)__bfloat16_as_ushort(a) | ((uint32_t)__bfloat16_as_ushort(b) << 16);
}
__device__ __forceinline__ void split2(float x, bf16& h, bf16& l) {
    h = __float2bfloat16_rn(x);
    l = __float2bfloat16_rn(x - __bfloat162float(h));
}

#define LDSM4(r, a) \
    asm volatile("ldmatrix.sync.aligned.m8n8.x4.shared.b16 {%0,%1,%2,%3}, [%4];" \
        : "=r"((r)[0]), "=r"((r)[1]), "=r"((r)[2]), "=r"((r)[3]) : "r"(a))

#define MMA16816(d, a, b0, b1) \
    asm volatile("mma.sync.aligned.m16n8k16.row.col.f32.bf16.bf16.f32 " \
        "{%0,%1,%2,%3}, {%4,%5,%6,%7}, {%8,%9}, {%0,%1,%2,%3};" \
        : "+f"((d)[0]), "+f"((d)[1]), "+f"((d)[2]), "+f"((d)[3]) \
        : "r"((a)[0]), "r"((a)[1]), "r"((a)[2]), "r"((a)[3]), "r"(b0), "r"(b1))

__device__ __forceinline__ void cp_async16(uint32_t dst, const void* src) {
    asm volatile("cp.async.cg.shared.global [%0], [%1], 16;" :: "r"(dst), "l"(src));
}

// ---------------- weight transpose + bf16 split: W[K,N] fp32 -> hi/lo [N,K] ----------------
// grid (N/32, K/64, layers), block (32, 8). Per-layer src/dst strides.
__global__ void convert_w(const float* __restrict__ Wb, bf16* __restrict__ hib,
                          bf16* __restrict__ lob, int K, int N,
                          size_t lsrc, size_t ldst) {
    const float* W = Wb + (size_t)blockIdx.z * lsrc;
    bf16* hi = hib + (size_t)blockIdx.z * ldst;
    bf16* lo = lob + (size_t)blockIdx.z * ldst;
    __shared__ float t[32][65];
    int n0 = blockIdx.x << 5, k0 = blockIdx.y << 6;
    int tx = threadIdx.x, ty = threadIdx.y;
    #pragma unroll
    for (int j = 0; j < 64; j += 8)
        t[tx][ty + j] = W[(size_t)(k0 + ty + j) * N + n0 + tx];
    __syncthreads();
    int tid = ty * 32 + tx;
    int n = tid >> 3, kc = (tid & 7) << 3;
    uint32_t h4[4], l4[4];
    #pragma unroll
    for (int i = 0; i < 4; i++) {
        float v0 = t[n][kc + 2 * i], v1 = t[n][kc + 2 * i + 1];
        bf16 h0, l0, h1, l1;
        split2(v0, h0, l0); split2(v1, h1, l1);
        h4[i] = pack_bf(h0, h1);
        l4[i] = pack_bf(l0, l1);
    }
    size_t o = (size_t)(n0 + n) * K + k0 + kc;
    *(uint4*)&hi[o] = make_uint4(h4[0], h4[1], h4[2], h4[3]);
    *(uint4*)&lo[o] = make_uint4(l4[0], l4[1], l4[2], l4[3]);
}

// ---------------- mma.sync bf16-split GEMM ----------------
// C[M,N] = A(hi/lo [M,K]) * B(hi/lo [N,K]),  fp32 accum, 3-term split.
// grid (M/128, N/128)  <-- x = m for B-tile L2 reuse across the wave.
// flags: 1 = +bias[N], 2 = relu, 4 = +add (residual, MxN)
// omode: 0 = C fp32 only; 1 = C fp32 + Chi/Clo token-major; 2 = Chi/Clo only;
//        3 = head-major bf16 [b,h,s,d]; 4 = transposed bf16 v [b,h,d,s];
//        5 = fused QKV (N=3072): col<1024 -> Chi (q head-major), <2048 -> Clo (k), else C as vt
#define STAGE_BYTES 65536
#define GM_SMEM (2*STAGE_BYTES)
__global__ void __launch_bounds__(256, 1) gemm_mma(
    const bf16* __restrict__ Ahi, const bf16* __restrict__ Alo,
    const bf16* __restrict__ Bhi, const bf16* __restrict__ Blo,
    const float* __restrict__ bias, const float* __restrict__ add,
    float* __restrict__ C, bf16* __restrict__ Chi, bf16* __restrict__ Clo,
    int M, int N, int K, int flags, int omode)
{
    extern __shared__ char smem[];
    const uint32_t sb = smem_u32(smem);
    const int tid = threadIdx.x, wid = tid >> 5, lane = tid & 31;
    const int m0 = blockIdx.x << 7, n0 = blockIdx.y << 7;
    const int wm = (wid & 1) << 6;
    const int wn = (wid >> 1) << 5;

    const bf16* gAh = Ahi + (size_t)m0 * K;
    const bf16* gAl = Alo + (size_t)m0 * K;
    const bf16* gBh = Bhi + (size_t)n0 * K;
    const bf16* gBl = Blo + (size_t)n0 * K;

    const int nchunk = K >> 6;
    const int l_row = tid >> 3;
    const int l_ch  = tid & 7;

    auto load_stage = [&](int s, int c) {
        const uint32_t st = sb + (uint32_t)s * STAGE_BYTES;
        const int kb = c << 6;
        const bf16* srcs[4] = { gAh + kb, gAl + kb, gBh + kb, gBl + kb };
        #pragma unroll
        for (int t = 0; t < 4; t++) {
            const uint32_t dstb = st + (uint32_t)t * 16384u;
            #pragma unroll
            for (int i = 0; i < 4; i++) {
                int row = l_row + (i << 5);
                uint32_t dst = dstb + (uint32_t)(row << 7) + (uint32_t)((l_ch ^ (row & 7)) << 4);
                cp_async16(dst, srcs[t] + (size_t)row * K + (l_ch << 3));
            }
        }
        asm volatile("cp.async.commit_group;" ::: "memory");
    };

    float acc[4][4][4];
    #pragma unroll
    for (int i = 0; i < 4; i++)
        #pragma unroll
        for (int j = 0; j < 4; j++)
            #pragma unroll
            for (int q = 0; q < 4; q++) acc[i][j][q] = 0.f;

    const int a_row = lane & 15;
    const int a_cb  = (lane >> 4) << 4;
    const int b_row = (lane & 7) + ((lane >> 4) << 3);
    const int b_cb  = ((lane >> 3) & 1) << 4;
    const uint32_t swz = (uint32_t)((lane & 7) << 4);

    load_stage(0, 0);

    for (int c = 0; c < nchunk; c++) {
        const int s = c & 1;
        if (c + 1 < nchunk) {
            load_stage(s ^ 1, c + 1);
            asm volatile("cp.async.wait_group 1;" ::: "memory");
        } else {
            asm volatile("cp.async.wait_group 0;" ::: "memory");
        }
        __syncthreads();

        const uint32_t st = sb + (uint32_t)s * STAGE_BYTES;
        #pragma unroll
        for (int kk = 0; kk < 4; kk++) {
            uint32_t ah[4][4], al[4][4], bh[2][4], bl[2][4];
            #pragma unroll
            for (int mi = 0; mi < 4; mi++) {
                int row = wm + (mi << 4) + a_row;
                uint32_t off = (uint32_t)(row << 7) + (((uint32_t)((kk << 5) + a_cb)) ^ swz);
                LDSM4(ah[mi], st + off);
                LDSM4(al[mi], st + 16384u + off);
            }
            #pragma unroll
            for (int j = 0; j < 2; j++) {
                int row = wn + (j << 4) + b_row;
                uint32_t off = (uint32_t)(row << 7) + (((uint32_t)((kk << 5) + b_cb)) ^ swz);
                LDSM4(bh[j], st + 32768u + off);
                LDSM4(bl[j], st + 49152u + off);
            }
            #pragma unroll
            for (int mi = 0; mi < 4; mi++) {
                #pragma unroll
                for (int nj = 0; nj < 4; nj++) {
                    uint32_t bh0 = bh[nj >> 1][(nj & 1) << 1], bh1 = bh[nj >> 1][((nj & 1) << 1) + 1];
                    uint32_t bl0 = bl[nj >> 1][(nj & 1) << 1], bl1 = bl[nj >> 1][((nj & 1) << 1) + 1];
                    MMA16816(acc[mi][nj], ah[mi], bh0, bh1);
                    MMA16816(acc[mi][nj], ah[mi], bl0, bl1);
                    MMA16816(acc[mi][nj], al[mi], bh0, bh1);
                }
            }
        }
        __syncthreads();
    }

    // epilogue
    const int er = m0 + wm + (lane >> 2);
    const int ec = n0 + wn + ((lane & 3) << 1);
    #pragma unroll
    for (int mi = 0; mi < 4; mi++) {
        #pragma unroll
        for (int hf = 0; hf < 2; hf++) {
            int row = er + (mi << 4) + (hf << 3);
            const float* Ar = (flags & 4) ? (add + (size_t)row * N) : nullptr;
            int bidx = row >> 10, srow = row & 1023;
            #pragma unroll
            for (int nj = 0; nj < 4; nj++) {
                int col = ec + (nj << 3);
                float v0 = acc[mi][nj][hf * 2 + 0];
                float v1 = acc[mi][nj][hf * 2 + 1];
                if (flags & 1) { v0 += bias[col]; v1 += bias[col + 1]; }
                if (flags & 4) { v0 += Ar[col];   v1 += Ar[col + 1]; }
                if (flags & 2) { v0 = fmaxf(v0, 0.f); v1 = fmaxf(v1, 0.f); }
                if (omode <= 1)
                    *(float2*)(C + (size_t)row * N + col) = make_float2(v0, v1);
                if (omode == 1 || omode == 2) {
                    bf16 h0, l0, h1, l1;
                    split2(v0, h0, l0); split2(v1, h1, l1);
                    *(uint32_t*)&Chi[(size_t)row * N + col] = pack_bf(h0, h1);
                    *(uint32_t*)&Clo[(size_t)row * N + col] = pack_bf(l0, l1);
                } else if (omode == 3) {
                    int h = col >> 6, d = col & 63;
                    size_t dst = (((size_t)((bidx << 4) + h) << 10) + srow) * 64 + d;
                    *(uint32_t*)&Chi[dst] =
                        pack_bf(__float2bfloat16_rn(v0), __float2bfloat16_rn(v1));
                } else if (omode == 4) {
                    int h = col >> 6, d = col & 63;
                    size_t hb = (size_t)((bidx << 4) + h) << 6;
                    Chi[(hb + d) * 1024 + srow]     = __float2bfloat16_rn(v0);
                    Chi[(hb + d + 1) * 1024 + srow] = __float2bfloat16_rn(v1);
                } else if (omode == 5) {
                    int j = col >> 10, nn = col & 1023;
                    int h = nn >> 6, d = nn & 63;
                    if (j == 2) {
                        bf16* vtp = (bf16*)C;
                        size_t hb = (size_t)((bidx << 4) + h) << 6;
                        vtp[(hb + d) * 1024 + srow]     = __float2bfloat16_rn(v0);
                        vtp[(hb + d + 1) * 1024 + srow] = __float2bfloat16_rn(v1);
                    } else {
                        bf16* dstp = (j == 0) ? Chi : Clo;
                        size_t dst = (((size_t)((bidx << 4) + h) << 10) + srow) * 64 + d;
                        *(uint32_t*)&dstp[dst] =
                            pack_bf(__float2bfloat16_rn(v0), __float2bfloat16_rn(v1));
                    }
                }
            }
        }
    }
}

// ---------------- scoresT: scT[bh][t][s] = 0.125 * k[bh,t,:].q[bh,s,:]  (single bf16, fp16 out) ----------------
#define SC_SMEM 32768
__global__ void __launch_bounds__(256, 1) scoresT_mma(
    const bf16* __restrict__ Kh, const bf16* __restrict__ Qh,
    __half* __restrict__ scT)
{
    extern __shared__ char smem[];
    const uint32_t sb = smem_u32(smem);
    const int tid = threadIdx.x, wid = tid >> 5, lane = tid & 31;
    const int bh = blockIdx.z;
    const int t0 = blockIdx.y << 7, s0 = blockIdx.x << 7;
    const size_t hbase = (size_t)bh << 16;
    const bf16* srcs[2] = { Kh + hbase + (size_t)t0 * 64, Qh + hbase + (size_t)s0 * 64 };

    {
        const int l_row = tid >> 3, l_ch = tid & 7;
        #pragma unroll
        for (int t = 0; t < 2; t++) {
            #pragma unroll
            for (int i = 0; i < 4; i++) {
                int row = l_row + (i << 5);
                uint32_t dst = sb + (uint32_t)t * 16384u + (uint32_t)(row << 7)
                             + (uint32_t)((l_ch ^ (row & 7)) << 4);
                cp_async16(dst, srcs[t] + (size_t)row * 64 + (l_ch << 3));
            }
        }
        asm volatile("cp.async.commit_group;" ::: "memory");
        asm volatile("cp.async.wait_group 0;" ::: "memory");
    }
    __syncthreads();

    const int wm = (wid & 1) << 6, wn = (wid >> 1) << 5;
    float acc[4][4][4];
    #pragma unroll
    for (int i = 0; i < 4; i++)
        #pragma unroll
        for (int j = 0; j < 4; j++)
            #pragma unroll
            for (int q = 0; q < 4; q++) acc[i][j][q] = 0.f;

    const int a_row = lane & 15, a_cb = (lane >> 4) << 4;
    const int b_row = (lane & 7) + ((lane >> 4) << 3), b_cb = ((lane >> 3) & 1) << 4;
    const uint32_t swz = (uint32_t)((lane & 7) << 4);

    #pragma unroll
    for (int kk = 0; kk < 4; kk++) {
        uint32_t ah[4][4], bh2[2][4];
        #pragma unroll
        for (int mi = 0; mi < 4; mi++) {
            int row = wm + (mi << 4) + a_row;
            uint32_t off = (uint32_t)(row << 7) + (((uint32_t)((kk << 5) + a_cb)) ^ swz);
            LDSM4(ah[mi], sb + off);
        }
        #pragma unroll
        for (int j = 0; j < 2; j++) {
            int row = wn + (j << 4) + b_row;
            uint32_t off = (uint32_t)(row << 7) + (((uint32_t)((kk << 5) + b_cb)) ^ swz);
            LDSM4(bh2[j], sb + 16384u + off);
        }
        #pragma unroll
        for (int mi = 0; mi < 4; mi++) {
            #pragma unroll
            for (int nj = 0; nj < 4; nj++) {
                MMA16816(acc[mi][nj], ah[mi],
                         bh2[nj >> 1][(nj & 1) << 1], bh2[nj >> 1][((nj & 1) << 1) + 1]);
            }
        }
    }

    __half* ob = scT + ((size_t)bh << 20);
    const int er = t0 + wm + (lane >> 2);
    const int ec = s0 + wn + ((lane & 3) << 1);
    #pragma unroll
    for (int mi = 0; mi < 4; mi++) {
        #pragma unroll
        for (int hf = 0; hf < 2; hf++) {
            int row = er + (mi << 4) + (hf << 3);
            #pragma unroll
            for (int nj = 0; nj < 4; nj++) {
                int col = ec + (nj << 3);
                *(__half2*)(ob + (size_t)row * Sn + col) =
                    __floats2half2_rn(acc[mi][nj][hf * 2] * 0.125f,
                                      acc[mi][nj][hf * 2 + 1] * 0.125f);
            }
        }
    }
}

// ---------------- parallel column softmax over t (UNMASKED, bug-faithful) ----------------
__global__ void __launch_bounds__(256) col_softmax(const __half* __restrict__ scT,
                                                   bf16* __restrict__ pT) {
    __shared__ float sm0[8][33], sm1[8][33], ss0[8][33], ss1[8][33];
    const int bh = blockIdx.y;
    const int lane = threadIdx.x & 31;
    const int chunk = threadIdx.x >> 5;
    const int s = (blockIdx.x << 6) + (lane << 1);
    const __half* base = scT + ((size_t)bh << 20) + s;
    const int t0 = chunk << 7;
    float cm0 = -3.402823466e38f, cm1 = -3.402823466e38f, cu0 = 0.f, cu1 = 0.f;
    #pragma unroll 4
    for (int t = 0; t < 128; t++) {
        __half2 h = *(const __half2*)(base + ((size_t)(t0 + t) << 10));
        float x0 = __low2float(h), x1 = __high2float(h);
        float n0 = fmaxf(cm0, x0), n1 = fmaxf(cm1, x1);
        cu0 = cu0 * __expf(cm0 - n0) + __expf(x0 - n0);
        cu1 = cu1 * __expf(cm1 - n1) + __expf(x1 - n1);
        cm0 = n0; cm1 = n1;
    }
    sm0[chunk][lane] = cm0; sm1[chunk][lane] = cm1;
    ss0[chunk][lane] = cu0; ss1[chunk][lane] = cu1;
    __syncthreads();
    float gM0 = -3.402823466e38f, gM1 = -3.402823466e38f;
    #pragma unroll
    for (int i = 0; i < 8; i++) {
        gM0 = fmaxf(gM0, sm0[i][lane]);
        gM1 = fmaxf(gM1, sm1[i][lane]);
    }
    float gS0 = 0.f, gS1 = 0.f;
    #pragma unroll
    for (int i = 0; i < 8; i++) {
        gS0 += ss0[i][lane] * __expf(sm0[i][lane] - gM0);
        gS1 += ss1[i][lane] * __expf(sm1[i][lane] - gM1);
    }
    float inv0 = 1.f / gS0, inv1 = 1.f / gS1;
    bf16* ob = pT + ((size_t)bh << 20) + s;
    #pragma unroll 4
    for (int t = 0; t < 128; t++) {
        __half2 h = *(const __half2*)(base + ((size_t)(t0 + t) << 10));
        float p0 = __expf(__low2float(h) - gM0) * inv0;
        float p1 = __expf(__high2float(h) - gM1) * inv1;
        *(uint32_t*)(ob + ((size_t)(t0 + t) << 10)) =
            pack_bf(__float2bfloat16_rn(p0), __float2bfloat16_rn(p1));
    }
}

// ---------------- AV: mha[b,t,h,d] = sum_s pT[bh,t,s] * vT[bh,d,s] ----------------
#define AV_STAGE 49152
#define AV_SMEM (2*AV_STAGE)
__global__ void __launch_bounds__(256, 1) av_mma(
    const bf16* __restrict__ pT, const bf16* __restrict__ vT,
    bf16* __restrict__ Mh, bf16* __restrict__ Ml)
{
    extern __shared__ char smem[];
    const uint32_t sb = smem_u32(smem);
    const int tid = threadIdx.x, wid = tid >> 5, lane = tid & 31;
    const int bh = blockIdx.y, t0 = blockIdx.x << 7;
    const bf16* gA = pT + ((size_t)bh << 20) + (size_t)t0 * 1024;
    const bf16* gB = vT + ((size_t)bh << 16);

    auto load_stage = [&](int s, int c) {
        const uint32_t st = sb + (uint32_t)s * AV_STAGE;
        const int kb = c << 7;
        #pragma unroll
        for (int i = 0; i < 8; i++) {
            int idx = tid + (i << 8);
            int row = idx >> 4, ch = idx & 15;
            uint32_t dst = st + (uint32_t)(row << 8) + (uint32_t)((ch ^ (row & 7)) << 4);
            cp_async16(dst, gA + (size_t)row * 1024 + kb + (ch << 3));
        }
        #pragma unroll
        for (int i = 0; i < 4; i++) {
            int idx = tid + (i << 8);
            int row = idx >> 4, ch = idx & 15;
            uint32_t dst = st + 32768u + (uint32_t)(row << 8) + (uint32_t)((ch ^ (row & 7)) << 4);
            cp_async16(dst, gB + (size_t)row * 1024 + kb + (ch << 3));
        }
        asm volatile("cp.async.commit_group;" ::: "memory");
    };

    const int wm = (wid & 3) << 5, wn = (wid >> 2) << 5;
    float acc[2][4][4];
    #pragma unroll
    for (int i = 0; i < 2; i++)
        #pragma unroll
        for (int j = 0; j < 4; j++)
            #pragma unroll
            for (int q = 0; q < 4; q++) acc[i][j][q] = 0.f;

    const int a_row = lane & 15, a_cb = (lane >> 4) << 4;
    const int b_row = (lane & 7) + ((lane >> 4) << 3), b_cb = ((lane >> 3) & 1) << 4;
    const uint32_t swz = (uint32_t)((lane & 7) << 4);

    load_stage(0, 0);
    for (int c = 0; c < 8; c++) {
        const int s = c & 1;
        if (c + 1 < 8) {
            load_stage(s ^ 1, c + 1);
            asm volatile("cp.async.wait_group 1;" ::: "memory");
        } else {
            asm volatile("cp.async.wait_group 0;" ::: "memory");
        }
        __syncthreads();

        const uint32_t st = sb + (uint32_t)s * AV_STAGE;
        #pragma unroll
        for (int kk = 0; kk < 8; kk++) {
            uint32_t af[2][4], bf2[2][4];
            #pragma unroll
            for (int mi = 0; mi < 2; mi++) {
                int row = wm + (mi << 4) + a_row;
                uint32_t off = (uint32_t)(row << 8) + (((uint32_t)((kk << 5) + a_cb)) ^ swz);
                LDSM4(af[mi], st + off);
            }
            #pragma unroll
            for (int j = 0; j < 2; j++) {
                int row = wn + (j << 4) + b_row;
                uint32_t off = (uint32_t)(row << 8) + (((uint32_t)((kk << 5) + b_cb)) ^ swz);
                LDSM4(bf2[j], st + 32768u + off);
            }
            #pragma unroll
            for (int mi = 0; mi < 2; mi++) {
                #pragma unroll
                for (int nj = 0; nj < 4; nj++) {
                    MMA16816(acc[mi][nj], af[mi],
                             bf2[nj >> 1][(nj & 1) << 1], bf2[nj >> 1][((nj & 1) << 1) + 1]);
                }
            }
        }
        __syncthreads();
    }

    const int b = bh >> 4, h = bh & 15;
    const int er = t0 + wm + (lane >> 2);
    const int ec = wn + ((lane & 3) << 1);
    #pragma unroll
    for (int mi = 0; mi < 2; mi++) {
        #pragma unroll
        for (int hf = 0; hf < 2; hf++) {
            int t = er + (mi << 4) + (hf << 3);
            size_t rowbase = ((size_t)(b << 10) + t) * 1024 + (h << 6);
            #pragma unroll
            for (int nj = 0; nj < 4; nj++) {
                int col = ec + (nj << 3);
                bf16 h0, l0, h1, l1;
                split2(acc[mi][nj][hf * 2], h0, l0);
                split2(acc[mi][nj][hf * 2 + 1], h1, l1);
                *(uint32_t*)&Mh[rowbase + col] = pack_bf(h0, h1);
                *(uint32_t*)&Ml[rowbase + col] = pack_bf(l0, l1);
            }
        }
    }
}

// ---------------- block reductions ----------------
__device__ __forceinline__ float blockReduceSum(float v) {
    __shared__ float sh[33];
    int lane = threadIdx.x & 31, w = threadIdx.x >> 5;
    #pragma unroll
    for (int o = 16; o > 0; o >>= 1) v += __shfl_xor_sync(0xffffffffu, v, o);
    __syncthreads();
    if (lane == 0) sh[w] = v;
    __syncthreads();
    if (w == 0) {
        v = (lane < (int)(blockDim.x >> 5)) ? sh[lane] : 0.f;
        #pragma unroll
        for (int o = 16; o > 0; o >>= 1) v += __shfl_xor_sync(0xffffffffu, v, o);
        if (lane == 0) sh[32] = v;
    }
    __syncthreads();
    return sh[32];
}
__device__ __forceinline__ float blockReduceMax(float v) {
    __shared__ float sh[33];
    int lane = threadIdx.x & 31, w = threadIdx.x >> 5;
    #pragma unroll
    for (int o = 16; o > 0; o >>= 1) v = fmaxf(v, __shfl_xor_sync(0xffffffffu, v, o));
    __syncthreads();
    if (lane == 0) sh[w] = v;
    __syncthreads();
    if (w == 0) {
        v = (lane < (int)(blockDim.x >> 5)) ? sh[lane] : -3.402823466e38f;
        #pragma unroll
        for (int o = 16; o > 0; o >>= 1) v = fmaxf(v, __shfl_xor_sync(0xffffffffu, v, o));
        if (lane == 0) sh[32] = v;
    }
    __syncthreads();
    return sh[32];
}

// ---------------- embedding: x fp32 + hi/lo bf16 ----------------
__global__ void embed_kernel(const int* __restrict__ tokens,
                             const float* __restrict__ tok,
                             const float* __restrict__ pos,
                             float* __restrict__ x,
                             bf16* __restrict__ xh, bf16* __restrict__ xl) {
    int idx = blockIdx.x * blockDim.x + threadIdx.x;
    const int EV = En / 4;
    if (idx >= NTOK * EV) return;
    int bs = idx / EV, e4 = idx % EV;
    int s = bs & (Sn - 1);
    int t = tokens[bs];
    float4 a = ((const float4*)tok)[(size_t)t * EV + e4];
    float4 p = ((const float4*)pos)[(size_t)s * EV + e4];
    float4 r;
    r.x = a.x + p.x; r.y = a.y + p.y; r.z = a.z + p.z; r.w = a.w + p.w;
    ((float4*)x)[idx] = r;
    bf16 h0, l0, h1, l1, h2, l2, h3, l3;
    split2(r.x, h0, l0); split2(r.y, h1, l1);
    split2(r.z, h2, l2); split2(r.w, h3, l3);
    ((uint2*)xh)[idx] = make_uint2(pack_bf(h0, h1), pack_bf(h2, h3));
    ((uint2*)xl)[idx] = make_uint2(pack_bf(l0, l1), pack_bf(l2, l3));
}

// ---------------- rmsnorm -> hi/lo bf16 ----------------
__global__ void add_rmsnorm_kernel(const float* __restrict__ x, const float* __restrict__ add,
                                   const float* __restrict__ scale,
                                   bf16* __restrict__ oh, bf16* __restrict__ ol)
{
    int row = blockIdx.x, tid = threadIdx.x;
    const float* xr = x + (size_t)row * En;
    const float* ar = add ? add + (size_t)row * En : nullptr;
    float v[4]; float ss = 0.f;
    #pragma unroll
    for (int j = 0; j < 4; j++) {
        int e = tid + j * 256;
        float t = xr[e];
        if (ar) t += ar[e];
        v[j] = t;
        ss += t * t;
    }
    ss = blockReduceSum(ss);
    float r = rsqrtf(ss * (1.f / En) + 1e-6f);
    #pragma unroll
    for (int j = 0; j < 4; j++) {
        int e = tid + j * 256;
        float t = v[j] * r * scale[e];
        bf16 h, l;
        split2(t, h, l);
        oh[(size_t)row * En + e] = h;
        ol[(size_t)row * En + e] = l;
    }
}

// ---------------- log_softmax ----------------
__global__ void log_softmax_kernel(float* __restrict__ a) {
    float* row = a + (size_t)blockIdx.x * Vn;
    int tid = threadIdx.x;
    float m = -3.402823466e38f;
    for (int i = tid; i < Vn; i += 256) m = fmaxf(m, row[i]);
    m = blockReduceMax(m);
    float s = 0.f;
    for (int i = tid; i < Vn; i += 256) s += __expf(row[i] - m);
    s = blockReduceSum(s);
    float lse = m + logf(s);
    for (int i = tid; i < Vn; i += 256) row[i] -= lse;
}

// ---------------- launch ----------------
extern "C" void kernel_launch(void* const* d_in, const int* in_sizes, int n_in,
                              void* d_out, int out_size) {
    const int*   tokens      = (const int*)  d_in[0];
    const float* tok_embed   = (const float*)d_in[1];
    const float* pos_embed   = (const float*)d_in[2];
    const float* Qw          = (const float*)d_in[3];
    const float* Kw          = (const float*)d_in[4];
    const float* Vw          = (const float*)d_in[5];
    const float* Ow          = (const float*)d_in[6];
    const float* rs2         = (const float*)d_in[7];
    const float* w1          = (const float*)d_in[8];
    const float* b1          = (const float*)d_in[9];
    const float* w2          = (const float*)d_in[10];
    const float* b2          = (const float*)d_in[11];
    const float* final_scale = (const float*)d_in[12];
    const float* w_out       = (const float*)d_in[13];
    const float* b_out       = (const float*)d_in[14];
    float* out = (float*)d_out;

    float *xb, *projb;
    __half* attb;
    bf16 *whi, *wlo, *ptb, *xh, *xl, *qh, *kh, *vt, *mh, *ml, *rh, *rl, *hh, *hl;
    cudaGetSymbolAddress((void**)&xb,    g_x);
    cudaGetSymbolAddress((void**)&projb, g_proj);
    cudaGetSymbolAddress((void**)&attb,  g_att);
    cudaGetSymbolAddress((void**)&ptb,   g_pt);
    cudaGetSymbolAddress((void**)&whi,   g_whi);
    cudaGetSymbolAddress((void**)&wlo,   g_wlo);
    cudaGetSymbolAddress((void**)&xh,    g_xh);
    cudaGetSymbolAddress((void**)&xl,    g_xl);
    cudaGetSymbolAddress((void**)&qh,    g_qh);
    cudaGetSymbolAddress((void**)&kh,    g_kh);
    cudaGetSymbolAddress((void**)&vt,    g_vt);
    cudaGetSymbolAddress((void**)&mh,    g_mh);
    cudaGetSymbolAddress((void**)&ml,    g_ml);
    cudaGetSymbolAddress((void**)&rh,    g_rh);
    cudaGetSymbolAddress((void**)&rl,    g_rl);
    cudaGetSymbolAddress((void**)&hh,    g_hh);
    cudaGetSymbolAddress((void**)&hl,    g_hl);

    cudaFuncSetAttribute(gemm_mma,    cudaFuncAttributeMaxDynamicSharedMemorySize, GM_SMEM);
    cudaFuncSetAttribute(scoresT_mma, cudaFuncAttributeMaxDynamicSharedMemorySize, SC_SMEM);
    cudaFuncSetAttribute(av_mma,      cudaFuncAttributeMaxDynamicSharedMemorySize, AV_SMEM);

    // ---- weight conversion: transpose + bf16 split, layer-fused (7 launches) ----
    dim3 cb(32, 8);
    // QKV interleaved [l][3][N][K]
    convert_w<<<dim3(32, 16, Lnum), cb>>>(Qw, whi,          wlo,          En, HIDn, M1, 3 * (size_t)M1);
    convert_w<<<dim3(32, 16, Lnum), cb>>>(Kw, whi + M1,     wlo + M1,     En, HIDn, M1, 3 * (size_t)M1);
    convert_w<<<dim3(32, 16, Lnum), cb>>>(Vw, whi + 2 * M1, wlo + 2 * M1, En, HIDn, M1, 3 * (size_t)M1);
    convert_w<<<dim3(32, 16, Lnum), cb>>>(Ow, whi + 12 * (size_t)M1, wlo + 12 * (size_t)M1,
                                          HIDn, En, M1, M1);
    convert_w<<<dim3(128, 16, Lnum), cb>>>(w1, whi + 16 * (size_t)M1, wlo + 16 * (size_t)M1,
                                           En, FFn, 4 * (size_t)M1, 4 * (size_t)M1);
    convert_w<<<dim3(32, 64, Lnum), cb>>>(w2, whi + 32 * (size_t)M1, wlo + 32 * (size_t)M1,
                                          FFn, En, 4 * (size_t)M1, 4 * (size_t)M1);
    convert_w<<<dim3(Vn / 32, 16, 1), cb>>>(w_out, whi + 48 * (size_t)M1, wlo + 48 * (size_t)M1,
                                            En, Vn, 0, 0);

    embed_kernel<<<(NTOK * (En / 4) + 255) / 256, 256>>>(tokens, tok_embed, pos_embed, xb, xh, xl);

    for (int l = 0; l < Lnum; l++) {
        const bf16 *QKVh = whi + (size_t)l * 3 * M1, *QKVl = wlo + (size_t)l * 3 * M1;
        const bf16 *Oh = whi + 12 * (size_t)M1 + (size_t)l * M1, *Ol2 = wlo + 12 * (size_t)M1 + (size_t)l * M1;
        const bf16 *W1h = whi + 16 * (size_t)M1 + (size_t)l * 4 * M1,
                   *W1l = wlo + 16 * (size_t)M1 + (size_t)l * 4 * M1;
        const bf16 *W2h = whi + 32 * (size_t)M1 + (size_t)l * 4 * M1,
                   *W2l = wlo + 32 * (size_t)M1 + (size_t)l * 4 * M1;
        const float* r2l = rs2 + (size_t)l * En;
        const float* b1l = b1 + (size_t)l * FFn;
        const float* b2l = b2 + (size_t)l * En;

        // fused QKV: M=2048, N=3072 (q | k | v)
        gemm_mma<<<dim3(NTOK / 128, 3 * HIDn / 128), 256, GM_SMEM>>>(
            xh, xl, QKVh, QKVl, nullptr, nullptr,
            (float*)vt, qh, kh, NTOK, 3 * HIDn, En, 0, 5);

        scoresT_mma<<<dim3(Sn / 128, Sn / 128, Bn * NHn), 256, SC_SMEM>>>(kh, qh, attb);
        col_softmax<<<dim3(Sn / 64, Bn * NHn), 256>>>(attb, ptb);
        av_mma<<<dim3(Sn / 128, Bn * NHn), 256, AV_SMEM>>>(ptb, vt, mh, ml);

        gemm_mma<<<dim3(NTOK / 128, En / 128), 256, GM_SMEM>>>(
            mh, ml, Oh, Ol2, nullptr, nullptr, projb, nullptr, nullptr, NTOK, En, HIDn, 0, 0);
        add_rmsnorm_kernel<<<NTOK, 256>>>(xb, projb, r2l, rh, rl);

        gemm_mma<<<dim3(NTOK / 128, FFn / 128), 256, GM_SMEM>>>(
            rh, rl, W1h, W1l, b1l, nullptr, nullptr, hh, hl, NTOK, FFn, En, 1 | 2, 2);
        gemm_mma<<<dim3(NTOK / 128, En / 128), 256, GM_SMEM>>>(
            hh, hl, W2h, W2l, b2l, projb, xb, xh, xl, NTOK, En, FFn, 1 | 4, 1);
    }

    add_rmsnorm_kernel<<<NTOK, 256>>>(xb, nullptr, final_scale, xh, xl);

    gemm_mma<<<dim3(NTOK / 128, Vn / 128), 256, GM_SMEM>>>(
        xh, xl, whi + 48 * (size_t)M1, wlo + 48 * (size_t)M1, b_out, nullptr,
        out, nullptr, nullptr, NTOK, Vn, En, 1, 0);
    log_softmax_kernel<<<NTOK, 256>>>(out);
}

// round 15
// speedup vs baseline: 1.1080x; 1.0669x over previous
#include <cuda_runtime.h>
#include <cuda_bf16.h>
#include <cuda_fp16.h>
#include <math.h>
#include <stdint.h>

// ---------------- problem constants ----------------
#define Lnum 4
#define Bn   2
#define Sn   1024
#define En   1024
#define NHn  16
#define HDn  64
#define HIDn 1024
#define FFn  4096
#define Vn   32000
#define NTOK (Bn*Sn)   // 2048
#define M1   (1u<<20)  // 1024*1024

typedef __nv_bfloat16 bf16;

// ---------------- scratch (static device memory; no allocation) ----------------
__device__ float  g_x   [NTOK*En];                 // residual stream fp32
__device__ float  g_proj[NTOK*En];                 // attn projection fp32
__device__ __half g_att [(size_t)Bn*NHn*Sn*Sn];    // scoresT fp16, 64 MB
__device__ bf16   g_pt  [(size_t)Bn*NHn*Sn*Sn];    // probsT bf16, 64 MB

__device__ bf16 g_xh[NTOK*En],  g_xl[NTOK*En];     // x hi/lo
__device__ bf16 g_qh[NTOK*HIDn];                   // q head-major [b,h,s,d] (bf16 single)
__device__ bf16 g_kh[NTOK*HIDn];                   // k head-major (bf16 single)
__device__ bf16 g_vt[NTOK*HIDn];                   // v transposed [b,h,d,s]
__device__ bf16 g_mh[NTOK*En],  g_ml[NTOK*En];     // mha hi/lo (token-major)
__device__ bf16 g_rh[NTOK*En],  g_rl[NTOK*En];     // rmsnorm out hi/lo
__device__ bf16 g_hh[(size_t)NTOK*FFn], g_hl[(size_t)NTOK*FFn]; // FF hidden hi/lo

// bf16 hi/lo transposed weights: [N,K] layout.
// QKV interleaved: [l][3][N][K] at offset (l*3+j)*M1.  O at 12M1+l*M1.
// W1 16M1+l*4M1 | W2 32M1+l*4M1 | Wout 48M1.
#define WTOT (48u*M1 + (size_t)Vn*En)
__device__ bf16 g_whi[WTOT];
__device__ bf16 g_wlo[WTOT];

// ---------------- helpers ----------------
__device__ __forceinline__ uint32_t smem_u32(const void* p) {
    uint32_t a;
    asm("{ .reg .u64 t; cvta.to.shared.u64 t, %1; cvt.u32.u64 %0, t; }" : "=r"(a) : "l"(p));
    return a;
}
__device__ __forceinline__ uint32_t pack_bf(bf16 a, bf16 b) {
    return (uint32_t)__bfloat16_as_ushort(a) | ((uint32_t)__bfloat16_as_ushort(b) << 16);
}
__device__ __forceinline__ void split2(float x, bf16& h, bf16& l) {
    h = __float2bfloat16_rn(x);
    l = __float2bfloat16_rn(x - __bfloat162float(h));
}

#define LDSM4(r, a) \
    asm volatile("ldmatrix.sync.aligned.m8n8.x4.shared.b16 {%0,%1,%2,%3}, [%4];" \
        : "=r"((r)[0]), "=r"((r)[1]), "=r"((r)[2]), "=r"((r)[3]) : "r"(a))

#define MMA16816(d, a, b0, b1) \
    asm volatile("mma.sync.aligned.m16n8k16.row.col.f32.bf16.bf16.f32 " \
        "{%0,%1,%2,%3}, {%4,%5,%6,%7}, {%8,%9}, {%0,%1,%2,%3};" \
        : "+f"((d)[0]), "+f"((d)[1]), "+f"((d)[2]), "+f"((d)[3]) \
        : "r"((a)[0]), "r"((a)[1]), "r"((a)[2]), "r"((a)[3]), "r"(b0), "r"(b1))

__device__ __forceinline__ void cp_async16(uint32_t dst, const void* src) {
    asm volatile("cp.async.cg.shared.global [%0], [%1], 16;" :: "r"(dst), "l"(src));
}

// ---------------- weight transpose + bf16 split: W[K,N] fp32 -> hi/lo [N,K] ----------------
// grid (N/32, K/64, layers), block (32, 8). Per-layer src/dst strides.
__global__ void convert_w(const float* __restrict__ Wb, bf16* __restrict__ hib,
                          bf16* __restrict__ lob, int K, int N,
                          size_t lsrc, size_t ldst) {
    const float* W = Wb + (size_t)blockIdx.z * lsrc;
    bf16* hi = hib + (size_t)blockIdx.z * ldst;
    bf16* lo = lob + (size_t)blockIdx.z * ldst;
    __shared__ float t[32][65];
    int n0 = blockIdx.x << 5, k0 = blockIdx.y << 6;
    int tx = threadIdx.x, ty = threadIdx.y;
    #pragma unroll
    for (int j = 0; j < 64; j += 8)
        t[tx][ty + j] = W[(size_t)(k0 + ty + j) * N + n0 + tx];
    __syncthreads();
    int tid = ty * 32 + tx;
    int n = tid >> 3, kc = (tid & 7) << 3;
    uint32_t h4[4], l4[4];
    #pragma unroll
    for (int i = 0; i < 4; i++) {
        float v0 = t[n][kc + 2 * i], v1 = t[n][kc + 2 * i + 1];
        bf16 h0, l0, h1, l1;
        split2(v0, h0, l0); split2(v1, h1, l1);
        h4[i] = pack_bf(h0, h1);
        l4[i] = pack_bf(l0, l1);
    }
    size_t o = (size_t)(n0 + n) * K + k0 + kc;
    *(uint4*)&hi[o] = make_uint4(h4[0], h4[1], h4[2], h4[3]);
    *(uint4*)&lo[o] = make_uint4(l4[0], l4[1], l4[2], l4[3]);
}

// ---------------- mma.sync bf16-split GEMM ----------------
// C[M,N] = A(hi/lo [M,K]) * B(hi/lo [N,K]),  fp32 accum.
// TERMS=3: Ah*Bh + Ah*Bl + Al*Bh.  TERMS=2: Ah*Bh + Ah*Bl (Alo not loaded).
// grid (M/128, N/128).
// flags: 1 = +bias[N], 2 = relu, 4 = +add (residual, MxN)
// omode: 0 = C fp32 only; 1 = C fp32 + Chi/Clo token-major; 2 = Chi/Clo only;
//        3 = head-major bf16 [b,h,s,d]; 4 = transposed bf16 v [b,h,d,s];
//        5 = fused QKV (N=3072): col<1024 -> Chi (q), <2048 -> Clo (k), else C as vt
#define STAGE_BYTES 65536
#define GM_SMEM (2*STAGE_BYTES)
template<int TERMS>
__global__ void __launch_bounds__(256, 1) gemm_mma(
    const bf16* __restrict__ Ahi, const bf16* __restrict__ Alo,
    const bf16* __restrict__ Bhi, const bf16* __restrict__ Blo,
    const float* __restrict__ bias, const float* __restrict__ add,
    float* __restrict__ C, bf16* __restrict__ Chi, bf16* __restrict__ Clo,
    int M, int N, int K, int flags, int omode)
{
    extern __shared__ char smem[];
    const uint32_t sb = smem_u32(smem);
    const int tid = threadIdx.x, wid = tid >> 5, lane = tid & 31;
    const int m0 = blockIdx.x << 7, n0 = blockIdx.y << 7;
    const int wm = (wid & 1) << 6;
    const int wn = (wid >> 1) << 5;

    const bf16* gAh = Ahi + (size_t)m0 * K;
    const bf16* gAl = Alo + (size_t)m0 * K;
    const bf16* gBh = Bhi + (size_t)n0 * K;
    const bf16* gBl = Blo + (size_t)n0 * K;

    const int nchunk = K >> 6;
    const int l_row = tid >> 3;
    const int l_ch  = tid & 7;

    auto load_stage = [&](int s, int c) {
        const uint32_t st = sb + (uint32_t)s * STAGE_BYTES;
        const int kb = c << 6;
        const bf16* srcs[4] = { gAh + kb, gAl + kb, gBh + kb, gBl + kb };
        #pragma unroll
        for (int t = 0; t < 4; t++) {
            if (TERMS == 2 && t == 1) continue;  // Alo not needed
            const uint32_t dstb = st + (uint32_t)t * 16384u;
            #pragma unroll
            for (int i = 0; i < 4; i++) {
                int row = l_row + (i << 5);
                uint32_t dst = dstb + (uint32_t)(row << 7) + (uint32_t)((l_ch ^ (row & 7)) << 4);
                cp_async16(dst, srcs[t] + (size_t)row * K + (l_ch << 3));
            }
        }
        asm volatile("cp.async.commit_group;" ::: "memory");
    };

    float acc[4][4][4];
    #pragma unroll
    for (int i = 0; i < 4; i++)
        #pragma unroll
        for (int j = 0; j < 4; j++)
            #pragma unroll
            for (int q = 0; q < 4; q++) acc[i][j][q] = 0.f;

    const int a_row = lane & 15;
    const int a_cb  = (lane >> 4) << 4;
    const int b_row = (lane & 7) + ((lane >> 4) << 3);
    const int b_cb  = ((lane >> 3) & 1) << 4;
    const uint32_t swz = (uint32_t)((lane & 7) << 4);

    load_stage(0, 0);

    for (int c = 0; c < nchunk; c++) {
        const int s = c & 1;
        if (c + 1 < nchunk) {
            load_stage(s ^ 1, c + 1);
            asm volatile("cp.async.wait_group 1;" ::: "memory");
        } else {
            asm volatile("cp.async.wait_group 0;" ::: "memory");
        }
        __syncthreads();

        const uint32_t st = sb + (uint32_t)s * STAGE_BYTES;
        #pragma unroll
        for (int kk = 0; kk < 4; kk++) {
            uint32_t ah[4][4], al[4][4], bh[2][4], bl[2][4];
            #pragma unroll
            for (int mi = 0; mi < 4; mi++) {
                int row = wm + (mi << 4) + a_row;
                uint32_t off = (uint32_t)(row << 7) + (((uint32_t)((kk << 5) + a_cb)) ^ swz);
                LDSM4(ah[mi], st + off);
                if (TERMS == 3) LDSM4(al[mi], st + 16384u + off);
            }
            #pragma unroll
            for (int j = 0; j < 2; j++) {
                int row = wn + (j << 4) + b_row;
                uint32_t off = (uint32_t)(row << 7) + (((uint32_t)((kk << 5) + b_cb)) ^ swz);
                LDSM4(bh[j], st + 32768u + off);
                LDSM4(bl[j], st + 49152u + off);
            }
            #pragma unroll
            for (int mi = 0; mi < 4; mi++) {
                #pragma unroll
                for (int nj = 0; nj < 4; nj++) {
                    uint32_t bh0 = bh[nj >> 1][(nj & 1) << 1], bh1 = bh[nj >> 1][((nj & 1) << 1) + 1];
                    uint32_t bl0 = bl[nj >> 1][(nj & 1) << 1], bl1 = bl[nj >> 1][((nj & 1) << 1) + 1];
                    MMA16816(acc[mi][nj], ah[mi], bh0, bh1);
                    MMA16816(acc[mi][nj], ah[mi], bl0, bl1);
                    if (TERMS == 3) MMA16816(acc[mi][nj], al[mi], bh0, bh1);
                }
            }
        }
        __syncthreads();
    }

    // epilogue
    const int er = m0 + wm + (lane >> 2);
    const int ec = n0 + wn + ((lane & 3) << 1);
    #pragma unroll
    for (int mi = 0; mi < 4; mi++) {
        #pragma unroll
        for (int hf = 0; hf < 2; hf++) {
            int row = er + (mi << 4) + (hf << 3);
            const float* Ar = (flags & 4) ? (add + (size_t)row * N) : nullptr;
            int bidx = row >> 10, srow = row & 1023;
            #pragma unroll
            for (int nj = 0; nj < 4; nj++) {
                int col = ec + (nj << 3);
                float v0 = acc[mi][nj][hf * 2 + 0];
                float v1 = acc[mi][nj][hf * 2 + 1];
                if (flags & 1) { v0 += bias[col]; v1 += bias[col + 1]; }
                if (flags & 4) { v0 += Ar[col];   v1 += Ar[col + 1]; }
                if (flags & 2) { v0 = fmaxf(v0, 0.f); v1 = fmaxf(v1, 0.f); }
                if (omode <= 1)
                    *(float2*)(C + (size_t)row * N + col) = make_float2(v0, v1);
                if (omode == 1 || omode == 2) {
                    bf16 h0, l0, h1, l1;
                    split2(v0, h0, l0); split2(v1, h1, l1);
                    *(uint32_t*)&Chi[(size_t)row * N + col] = pack_bf(h0, h1);
                    *(uint32_t*)&Clo[(size_t)row * N + col] = pack_bf(l0, l1);
                } else if (omode == 3) {
                    int h = col >> 6, d = col & 63;
                    size_t dst = (((size_t)((bidx << 4) + h) << 10) + srow) * 64 + d;
                    *(uint32_t*)&Chi[dst] =
                        pack_bf(__float2bfloat16_rn(v0), __float2bfloat16_rn(v1));
                } else if (omode == 4) {
                    int h = col >> 6, d = col & 63;
                    size_t hb = (size_t)((bidx << 4) + h) << 6;
                    Chi[(hb + d) * 1024 + srow]     = __float2bfloat16_rn(v0);
                    Chi[(hb + d + 1) * 1024 + srow] = __float2bfloat16_rn(v1);
                } else if (omode == 5) {
                    int j = col >> 10, nn = col & 1023;
                    int h = nn >> 6, d = nn & 63;
                    if (j == 2) {
                        bf16* vtp = (bf16*)C;
                        size_t hb = (size_t)((bidx << 4) + h) << 6;
                        vtp[(hb + d) * 1024 + srow]     = __float2bfloat16_rn(v0);
                        vtp[(hb + d + 1) * 1024 + srow] = __float2bfloat16_rn(v1);
                    } else {
                        bf16* dstp = (j == 0) ? Chi : Clo;
                        size_t dst = (((size_t)((bidx << 4) + h) << 10) + srow) * 64 + d;
                        *(uint32_t*)&dstp[dst] =
                            pack_bf(__float2bfloat16_rn(v0), __float2bfloat16_rn(v1));
                    }
                }
            }
        }
    }
}

// ---------------- scoresT: scT[bh][t][s] = 0.125 * k[bh,t,:].q[bh,s,:]  (single bf16, fp16 out) ----------------
#define SC_SMEM 32768
__global__ void __launch_bounds__(256, 1) scoresT_mma(
    const bf16* __restrict__ Kh, const bf16* __restrict__ Qh,
    __half* __restrict__ scT)
{
    extern __shared__ char smem[];
    const uint32_t sb = smem_u32(smem);
    const int tid = threadIdx.x, wid = tid >> 5, lane = tid & 31;
    const int bh = blockIdx.z;
    const int t0 = blockIdx.y << 7, s0 = blockIdx.x << 7;
    const size_t hbase = (size_t)bh << 16;
    const bf16* srcs[2] = { Kh + hbase + (size_t)t0 * 64, Qh + hbase + (size_t)s0 * 64 };

    {
        const int l_row = tid >> 3, l_ch = tid & 7;
        #pragma unroll
        for (int t = 0; t < 2; t++) {
            #pragma unroll
            for (int i = 0; i < 4; i++) {
                int row = l_row + (i << 5);
                uint32_t dst = sb + (uint32_t)t * 16384u + (uint32_t)(row << 7)
                             + (uint32_t)((l_ch ^ (row & 7)) << 4);
                cp_async16(dst, srcs[t] + (size_t)row * 64 + (l_ch << 3));
            }
        }
        asm volatile("cp.async.commit_group;" ::: "memory");
        asm volatile("cp.async.wait_group 0;" ::: "memory");
    }
    __syncthreads();

    const int wm = (wid & 1) << 6, wn = (wid >> 1) << 5;
    float acc[4][4][4];
    #pragma unroll
    for (int i = 0; i < 4; i++)
        #pragma unroll
        for (int j = 0; j < 4; j++)
            #pragma unroll
            for (int q = 0; q < 4; q++) acc[i][j][q] = 0.f;

    const int a_row = lane & 15, a_cb = (lane >> 4) << 4;
    const int b_row = (lane & 7) + ((lane >> 4) << 3), b_cb = ((lane >> 3) & 1) << 4;
    const uint32_t swz = (uint32_t)((lane & 7) << 4);

    #pragma unroll
    for (int kk = 0; kk < 4; kk++) {
        uint32_t ah[4][4], bh2[2][4];
        #pragma unroll
        for (int mi = 0; mi < 4; mi++) {
            int row = wm + (mi << 4) + a_row;
            uint32_t off = (uint32_t)(row << 7) + (((uint32_t)((kk << 5) + a_cb)) ^ swz);
            LDSM4(ah[mi], sb + off);
        }
        #pragma unroll
        for (int j = 0; j < 2; j++) {
            int row = wn + (j << 4) + b_row;
            uint32_t off = (uint32_t)(row << 7) + (((uint32_t)((kk << 5) + b_cb)) ^ swz);
            LDSM4(bh2[j], sb + 16384u + off);
        }
        #pragma unroll
        for (int mi = 0; mi < 4; mi++) {
            #pragma unroll
            for (int nj = 0; nj < 4; nj++) {
                MMA16816(acc[mi][nj], ah[mi],
                         bh2[nj >> 1][(nj & 1) << 1], bh2[nj >> 1][((nj & 1) << 1) + 1]);
            }
        }
    }

    __half* ob = scT + ((size_t)bh << 20);
    const int er = t0 + wm + (lane >> 2);
    const int ec = s0 + wn + ((lane & 3) << 1);
    #pragma unroll
    for (int mi = 0; mi < 4; mi++) {
        #pragma unroll
        for (int hf = 0; hf < 2; hf++) {
            int row = er + (mi << 4) + (hf << 3);
            #pragma unroll
            for (int nj = 0; nj < 4; nj++) {
                int col = ec + (nj << 3);
                *(__half2*)(ob + (size_t)row * Sn + col) =
                    __floats2half2_rn(acc[mi][nj][hf * 2] * 0.125f,
                                      acc[mi][nj][hf * 2 + 1] * 0.125f);
            }
        }
    }
}

// ---------------- parallel column softmax over t (UNMASKED, bug-faithful) ----------------
__global__ void __launch_bounds__(256) col_softmax(const __half* __restrict__ scT,
                                                   bf16* __restrict__ pT) {
    __shared__ float sm0[8][33], sm1[8][33], ss0[8][33], ss1[8][33];
    const int bh = blockIdx.y;
    const int lane = threadIdx.x & 31;
    const int chunk = threadIdx.x >> 5;
    const int s = (blockIdx.x << 6) + (lane << 1);
    const __half* base = scT + ((size_t)bh << 20) + s;
    const int t0 = chunk << 7;
    float cm0 = -3.402823466e38f, cm1 = -3.402823466e38f, cu0 = 0.f, cu1 = 0.f;
    #pragma unroll 4
    for (int t = 0; t < 128; t++) {
        __half2 h = *(const __half2*)(base + ((size_t)(t0 + t) << 10));
        float x0 = __low2float(h), x1 = __high2float(h);
        float n0 = fmaxf(cm0, x0), n1 = fmaxf(cm1, x1);
        cu0 = cu0 * __expf(cm0 - n0) + __expf(x0 - n0);
        cu1 = cu1 * __expf(cm1 - n1) + __expf(x1 - n1);
        cm0 = n0; cm1 = n1;
    }
    sm0[chunk][lane] = cm0; sm1[chunk][lane] = cm1;
    ss0[chunk][lane] = cu0; ss1[chunk][lane] = cu1;
    __syncthreads();
    float gM0 = -3.402823466e38f, gM1 = -3.402823466e38f;
    #pragma unroll
    for (int i = 0; i < 8; i++) {
        gM0 = fmaxf(gM0, sm0[i][lane]);
        gM1 = fmaxf(gM1, sm1[i][lane]);
    }
    float gS0 = 0.f, gS1 = 0.f;
    #pragma unroll
    for (int i = 0; i < 8; i++) {
        gS0 += ss0[i][lane] * __expf(sm0[i][lane] - gM0);
        gS1 += ss1[i][lane] * __expf(sm1[i][lane] - gM1);
    }
    float inv0 = 1.f / gS0, inv1 = 1.f / gS1;
    bf16* ob = pT + ((size_t)bh << 20) + s;
    #pragma unroll 4
    for (int t = 0; t < 128; t++) {
        __half2 h = *(const __half2*)(base + ((size_t)(t0 + t) << 10));
        float p0 = __expf(__low2float(h) - gM0) * inv0;
        float p1 = __expf(__high2float(h) - gM1) * inv1;
        *(uint32_t*)(ob + ((size_t)(t0 + t) << 10)) =
            pack_bf(__float2bfloat16_rn(p0), __float2bfloat16_rn(p1));
    }
}

// ---------------- AV: mha[b,t,h,d] = sum_s pT[bh,t,s] * vT[bh,d,s] ----------------
#define AV_STAGE 49152
#define AV_SMEM (2*AV_STAGE)
__global__ void __launch_bounds__(256, 1) av_mma(
    const bf16* __restrict__ pT, const bf16* __restrict__ vT,
    bf16* __restrict__ Mh, bf16* __restrict__ Ml)
{
    extern __shared__ char smem[];
    const uint32_t sb = smem_u32(smem);
    const int tid = threadIdx.x, wid = tid >> 5, lane = tid & 31;
    const int bh = blockIdx.y, t0 = blockIdx.x << 7;
    const bf16* gA = pT + ((size_t)bh << 20) + (size_t)t0 * 1024;
    const bf16* gB = vT + ((size_t)bh << 16);

    auto load_stage = [&](int s, int c) {
        const uint32_t st = sb + (uint32_t)s * AV_STAGE;
        const int kb = c << 7;
        #pragma unroll
        for (int i = 0; i < 8; i++) {
            int idx = tid + (i << 8);
            int row = idx >> 4, ch = idx & 15;
            uint32_t dst = st + (uint32_t)(row << 8) + (uint32_t)((ch ^ (row & 7)) << 4);
            cp_async16(dst, gA + (size_t)row * 1024 + kb + (ch << 3));
        }
        #pragma unroll
        for (int i = 0; i < 4; i++) {
            int idx = tid + (i << 8);
            int row = idx >> 4, ch = idx & 15;
            uint32_t dst = st + 32768u + (uint32_t)(row << 8) + (uint32_t)((ch ^ (row & 7)) << 4);
            cp_async16(dst, gB + (size_t)row * 1024 + kb + (ch << 3));
        }
        asm volatile("cp.async.commit_group;" ::: "memory");
    };

    const int wm = (wid & 3) << 5, wn = (wid >> 2) << 5;
    float acc[2][4][4];
    #pragma unroll
    for (int i = 0; i < 2; i++)
        #pragma unroll
        for (int j = 0; j < 4; j++)
            #pragma unroll
            for (int q = 0; q < 4; q++) acc[i][j][q] = 0.f;

    const int a_row = lane & 15, a_cb = (lane >> 4) << 4;
    const int b_row = (lane & 7) + ((lane >> 4) << 3), b_cb = ((lane >> 3) & 1) << 4;
    const uint32_t swz = (uint32_t)((lane & 7) << 4);

    load_stage(0, 0);
    for (int c = 0; c < 8; c++) {
        const int s = c & 1;
        if (c + 1 < 8) {
            load_stage(s ^ 1, c + 1);
            asm volatile("cp.async.wait_group 1;" ::: "memory");
        } else {
            asm volatile("cp.async.wait_group 0;" ::: "memory");
        }
        __syncthreads();

        const uint32_t st = sb + (uint32_t)s * AV_STAGE;
        #pragma unroll
        for (int kk = 0; kk < 8; kk++) {
            uint32_t af[2][4], bf2[2][4];
            #pragma unroll
            for (int mi = 0; mi < 2; mi++) {
                int row = wm + (mi << 4) + a_row;
                uint32_t off = (uint32_t)(row << 8) + (((uint32_t)((kk << 5) + a_cb)) ^ swz);
                LDSM4(af[mi], st + off);
            }
            #pragma unroll
            for (int j = 0; j < 2; j++) {
                int row = wn + (j << 4) + b_row;
                uint32_t off = (uint32_t)(row << 8) + (((uint32_t)((kk << 5) + b_cb)) ^ swz);
                LDSM4(bf2[j], st + 32768u + off);
            }
            #pragma unroll
            for (int mi = 0; mi < 2; mi++) {
                #pragma unroll
                for (int nj = 0; nj < 4; nj++) {
                    MMA16816(acc[mi][nj], af[mi],
                             bf2[nj >> 1][(nj & 1) << 1], bf2[nj >> 1][((nj & 1) << 1) + 1]);
                }
            }
        }
        __syncthreads();
    }

    const int b = bh >> 4, h = bh & 15;
    const int er = t0 + wm + (lane >> 2);
    const int ec = wn + ((lane & 3) << 1);
    #pragma unroll
    for (int mi = 0; mi < 2; mi++) {
        #pragma unroll
        for (int hf = 0; hf < 2; hf++) {
            int t = er + (mi << 4) + (hf << 3);
            size_t rowbase = ((size_t)(b << 10) + t) * 1024 + (h << 6);
            #pragma unroll
            for (int nj = 0; nj < 4; nj++) {
                int col = ec + (nj << 3);
                bf16 h0, l0, h1, l1;
                split2(acc[mi][nj][hf * 2], h0, l0);
                split2(acc[mi][nj][hf * 2 + 1], h1, l1);
                *(uint32_t*)&Mh[rowbase + col] = pack_bf(h0, h1);
                *(uint32_t*)&Ml[rowbase + col] = pack_bf(l0, l1);
            }
        }
    }
}

// ---------------- block reductions ----------------
__device__ __forceinline__ float blockReduceSum(float v) {
    __shared__ float sh[33];
    int lane = threadIdx.x & 31, w = threadIdx.x >> 5;
    #pragma unroll
    for (int o = 16; o > 0; o >>= 1) v += __shfl_xor_sync(0xffffffffu, v, o);
    __syncthreads();
    if (lane == 0) sh[w] = v;
    __syncthreads();
    if (w == 0) {
        v = (lane < (int)(blockDim.x >> 5)) ? sh[lane] : 0.f;
        #pragma unroll
        for (int o = 16; o > 0; o >>= 1) v += __shfl_xor_sync(0xffffffffu, v, o);
        if (lane == 0) sh[32] = v;
    }
    __syncthreads();
    return sh[32];
}
__device__ __forceinline__ float blockReduceMax(float v) {
    __shared__ float sh[33];
    int lane = threadIdx.x & 31, w = threadIdx.x >> 5;
    #pragma unroll
    for (int o = 16; o > 0; o >>= 1) v = fmaxf(v, __shfl_xor_sync(0xffffffffu, v, o));
    __syncthreads();
    if (lane == 0) sh[w] = v;
    __syncthreads();
    if (w == 0) {
        v = (lane < (int)(blockDim.x >> 5)) ? sh[lane] : -3.402823466e38f;
        #pragma unroll
        for (int o = 16; o > 0; o >>= 1) v = fmaxf(v, __shfl_xor_sync(0xffffffffu, v, o));
        if (lane == 0) sh[32] = v;
    }
    __syncthreads();
    return sh[32];
}

// ---------------- embedding: x fp32 + hi/lo bf16 ----------------
__global__ void embed_kernel(const int* __restrict__ tokens,
                             const float* __restrict__ tok,
                             const float* __restrict__ pos,
                             float* __restrict__ x,
                             bf16* __restrict__ xh, bf16* __restrict__ xl) {
    int idx = blockIdx.x * blockDim.x + threadIdx.x;
    const int EV = En / 4;
    if (idx >= NTOK * EV) return;
    int bs = idx / EV, e4 = idx % EV;
    int s = bs & (Sn - 1);
    int t = tokens[bs];
    float4 a = ((const float4*)tok)[(size_t)t * EV + e4];
    float4 p = ((const float4*)pos)[(size_t)s * EV + e4];
    float4 r;
    r.x = a.x + p.x; r.y = a.y + p.y; r.z = a.z + p.z; r.w = a.w + p.w;
    ((float4*)x)[idx] = r;
    bf16 h0, l0, h1, l1, h2, l2, h3, l3;
    split2(r.x, h0, l0); split2(r.y, h1, l1);
    split2(r.z, h2, l2); split2(r.w, h3, l3);
    ((uint2*)xh)[idx] = make_uint2(pack_bf(h0, h1), pack_bf(h2, h3));
    ((uint2*)xl)[idx] = make_uint2(pack_bf(l0, l1), pack_bf(l2, l3));
}

// ---------------- rmsnorm -> hi/lo bf16 ----------------
__global__ void add_rmsnorm_kernel(const float* __restrict__ x, const float* __restrict__ add,
                                   const float* __restrict__ scale,
                                   bf16* __restrict__ oh, bf16* __restrict__ ol)
{
    int row = blockIdx.x, tid = threadIdx.x;
    const float* xr = x + (size_t)row * En;
    const float* ar = add ? add + (size_t)row * En : nullptr;
    float v[4]; float ss = 0.f;
    #pragma unroll
    for (int j = 0; j < 4; j++) {
        int e = tid + j * 256;
        float t = xr[e];
        if (ar) t += ar[e];
        v[j] = t;
        ss += t * t;
    }
    ss = blockReduceSum(ss);
    float r = rsqrtf(ss * (1.f / En) + 1e-6f);
    #pragma unroll
    for (int j = 0; j < 4; j++) {
        int e = tid + j * 256;
        float t = v[j] * r * scale[e];
        bf16 h, l;
        split2(t, h, l);
        oh[(size_t)row * En + e] = h;
        ol[(size_t)row * En + e] = l;
    }
}

// ---------------- log_softmax ----------------
__global__ void log_softmax_kernel(float* __restrict__ a) {
    float* row = a + (size_t)blockIdx.x * Vn;
    int tid = threadIdx.x;
    float m = -3.402823466e38f;
    for (int i = tid; i < Vn; i += 256) m = fmaxf(m, row[i]);
    m = blockReduceMax(m);
    float s = 0.f;
    for (int i = tid; i < Vn; i += 256) s += __expf(row[i] - m);
    s = blockReduceSum(s);
    float lse = m + logf(s);
    for (int i = tid; i < Vn; i += 256) row[i] -= lse;
}

// ---------------- launch ----------------
extern "C" void kernel_launch(void* const* d_in, const int* in_sizes, int n_in,
                              void* d_out, int out_size) {
    const int*   tokens      = (const int*)  d_in[0];
    const float* tok_embed   = (const float*)d_in[1];
    const float* pos_embed   = (const float*)d_in[2];
    const float* Qw          = (const float*)d_in[3];
    const float* Kw          = (const float*)d_in[4];
    const float* Vw          = (const float*)d_in[5];
    const float* Ow          = (const float*)d_in[6];
    const float* rs2         = (const float*)d_in[7];
    const float* w1          = (const float*)d_in[8];
    const float* b1          = (const float*)d_in[9];
    const float* w2          = (const float*)d_in[10];
    const float* b2          = (const float*)d_in[11];
    const float* final_scale = (const float*)d_in[12];
    const float* w_out       = (const float*)d_in[13];
    const float* b_out       = (const float*)d_in[14];
    float* out = (float*)d_out;

    float *xb, *projb;
    __half* attb;
    bf16 *whi, *wlo, *ptb, *xh, *xl, *qh, *kh, *vt, *mh, *ml, *rh, *rl, *hh, *hl;
    cudaGetSymbolAddress((void**)&xb,    g_x);
    cudaGetSymbolAddress((void**)&projb, g_proj);
    cudaGetSymbolAddress((void**)&attb,  g_att);
    cudaGetSymbolAddress((void**)&ptb,   g_pt);
    cudaGetSymbolAddress((void**)&whi,   g_whi);
    cudaGetSymbolAddress((void**)&wlo,   g_wlo);
    cudaGetSymbolAddress((void**)&xh,    g_xh);
    cudaGetSymbolAddress((void**)&xl,    g_xl);
    cudaGetSymbolAddress((void**)&qh,    g_qh);
    cudaGetSymbolAddress((void**)&kh,    g_kh);
    cudaGetSymbolAddress((void**)&vt,    g_vt);
    cudaGetSymbolAddress((void**)&mh,    g_mh);
    cudaGetSymbolAddress((void**)&ml,    g_ml);
    cudaGetSymbolAddress((void**)&rh,    g_rh);
    cudaGetSymbolAddress((void**)&rl,    g_rl);
    cudaGetSymbolAddress((void**)&hh,    g_hh);
    cudaGetSymbolAddress((void**)&hl,    g_hl);

    cudaFuncSetAttribute(gemm_mma<3>, cudaFuncAttributeMaxDynamicSharedMemorySize, GM_SMEM);
    cudaFuncSetAttribute(gemm_mma<2>, cudaFuncAttributeMaxDynamicSharedMemorySize, GM_SMEM);
    cudaFuncSetAttribute(scoresT_mma, cudaFuncAttributeMaxDynamicSharedMemorySize, SC_SMEM);
    cudaFuncSetAttribute(av_mma,      cudaFuncAttributeMaxDynamicSharedMemorySize, AV_SMEM);

    // ---- weight conversion: transpose + bf16 split, layer-fused (7 launches) ----
    dim3 cb(32, 8);
    convert_w<<<dim3(32, 16, Lnum), cb>>>(Qw, whi,          wlo,          En, HIDn, M1, 3 * (size_t)M1);
    convert_w<<<dim3(32, 16, Lnum), cb>>>(Kw, whi + M1,     wlo + M1,     En, HIDn, M1, 3 * (size_t)M1);
    convert_w<<<dim3(32, 16, Lnum), cb>>>(Vw, whi + 2 * M1, wlo + 2 * M1, En, HIDn, M1, 3 * (size_t)M1);
    convert_w<<<dim3(32, 16, Lnum), cb>>>(Ow, whi + 12 * (size_t)M1, wlo + 12 * (size_t)M1,
                                          HIDn, En, M1, M1);
    convert_w<<<dim3(128, 16, Lnum), cb>>>(w1, whi + 16 * (size_t)M1, wlo + 16 * (size_t)M1,
                                           En, FFn, 4 * (size_t)M1, 4 * (size_t)M1);
    convert_w<<<dim3(32, 64, Lnum), cb>>>(w2, whi + 32 * (size_t)M1, wlo + 32 * (size_t)M1,
                                          FFn, En, 4 * (size_t)M1, 4 * (size_t)M1);
    convert_w<<<dim3(Vn / 32, 16, 1), cb>>>(w_out, whi + 48 * (size_t)M1, wlo + 48 * (size_t)M1,
                                            En, Vn, 0, 0);

    embed_kernel<<<(NTOK * (En / 4) + 255) / 256, 256>>>(tokens, tok_embed, pos_embed, xb, xh, xl);

    for (int l = 0; l < Lnum; l++) {
        const bf16 *QKVh = whi + (size_t)l * 3 * M1, *QKVl = wlo + (size_t)l * 3 * M1;
        const bf16 *Oh = whi + 12 * (size_t)M1 + (size_t)l * M1, *Ol2 = wlo + 12 * (size_t)M1 + (size_t)l * M1;
        const bf16 *W1h = whi + 16 * (size_t)M1 + (size_t)l * 4 * M1,
                   *W1l = wlo + 16 * (size_t)M1 + (size_t)l * 4 * M1;
        const bf16 *W2h = whi + 32 * (size_t)M1 + (size_t)l * 4 * M1,
                   *W2l = wlo + 32 * (size_t)M1 + (size_t)l * 4 * M1;
        const float* r2l = rs2 + (size_t)l * En;
        const float* b1l = b1 + (size_t)l * FFn;
        const float* b2l = b2 + (size_t)l * En;

        // fused QKV: M=2048, N=3072 (q | k | v)
        gemm_mma<3><<<dim3(NTOK / 128, 3 * HIDn / 128), 256, GM_SMEM>>>(
            xh, xl, QKVh, QKVl, nullptr, nullptr,
            (float*)vt, qh, kh, NTOK, 3 * HIDn, En, 0, 5);

        scoresT_mma<<<dim3(Sn / 128, Sn / 128, Bn * NHn), 256, SC_SMEM>>>(kh, qh, attb);
        col_softmax<<<dim3(Sn / 64, Bn * NHn), 256>>>(attb, ptb);
        av_mma<<<dim3(Sn / 128, Bn * NHn), 256, AV_SMEM>>>(ptb, vt, mh, ml);

        gemm_mma<3><<<dim3(NTOK / 128, En / 128), 256, GM_SMEM>>>(
            mh, ml, Oh, Ol2, nullptr, nullptr, projb, nullptr, nullptr, NTOK, En, HIDn, 0, 0);
        add_rmsnorm_kernel<<<NTOK, 256>>>(xb, projb, r2l, rh, rl);

        gemm_mma<3><<<dim3(NTOK / 128, FFn / 128), 256, GM_SMEM>>>(
            rh, rl, W1h, W1l, b1l, nullptr, nullptr, hh, hl, NTOK, FFn, En, 1 | 2, 2);
        gemm_mma<3><<<dim3(NTOK / 128, En / 128), 256, GM_SMEM>>>(
            hh, hl, W2h, W2l, b2l, projb, xb, xh, xl, NTOK, En, FFn, 1 | 4, 1);
    }

    add_rmsnorm_kernel<<<NTOK, 256>>>(xb, nullptr, final_scale, xh, xl);

    // logits: 2-term split (activations hi-only; weights hi/lo)
    gemm_mma<2><<<dim3(NTOK / 128, Vn / 128), 256, GM_SMEM>>>(
        xh, xl, whi + 48 * (size_t)M1, wlo + 48 * (size_t)M1, b_out, nullptr,
        out, nullptr, nullptr, NTOK, Vn, En, 1, 0);
    log_softmax_kernel<<<NTOK, 256>>>(out);
}

// round 16
// speedup vs baseline: 1.8870x; 1.7030x over previous
#include <cuda_runtime.h>
#include <cuda_fp16.h>
#include <math.h>
#include <stdint.h>

// ---------------- problem constants ----------------
#define Lnum 4
#define Bn   2
#define Sn   1024
#define En   1024
#define NHn  16
#define HDn  64
#define HIDn 1024
#define FFn  4096
#define Vn   32000
#define NTOK (Bn*Sn)   // 2048
#define M1   (1u<<20)  // 1024*1024

typedef __half fp16;

// ---------------- scratch (static device memory; no allocation) ----------------
__device__ float g_x   [NTOK*En];                 // residual stream fp32
__device__ float g_proj[NTOK*En];                 // attn projection fp32
__device__ fp16  g_att [(size_t)Bn*NHn*Sn*Sn];    // scoresT fp16, 64 MB
__device__ fp16  g_pt  [(size_t)Bn*NHn*Sn*Sn];    // probsT fp16, 64 MB

__device__ fp16 g_xh[NTOK*En];                    // x fp16
__device__ fp16 g_qh[NTOK*HIDn];                  // q head-major [b,h,s,d]
__device__ fp16 g_kh[NTOK*HIDn];                  // k head-major
__device__ fp16 g_vt[NTOK*HIDn];                  // v transposed [b,h,d,s]
__device__ fp16 g_mh[NTOK*En];                    // mha token-major
__device__ fp16 g_rh[NTOK*En];                    // rmsnorm out
__device__ fp16 g_hh[(size_t)NTOK*FFn];           // FF hidden

// fp16 transposed weights: [N,K] layout.
// QKV interleaved: [l][3][N][K] at offset (l*3+j)*M1.  O at 12M1+l*M1.
// W1 16M1+l*4M1 | W2 32M1+l*4M1 | Wout 48M1.
#define WTOT (48u*M1 + (size_t)Vn*En)
__device__ fp16 g_wh[WTOT];

// ---------------- helpers ----------------
__device__ __forceinline__ uint32_t smem_u32(const void* p) {
    uint32_t a;
    asm("{ .reg .u64 t; cvta.to.shared.u64 t, %1; cvt.u32.u64 %0, t; }" : "=r"(a) : "l"(p));
    return a;
}
__device__ __forceinline__ uint32_t pack_hf(float a, float b) {
    __half2 h = __floats2half2_rn(a, b);
    return *(uint32_t*)&h;
}

#define LDSM4(r, a) \
    asm volatile("ldmatrix.sync.aligned.m8n8.x4.shared.b16 {%0,%1,%2,%3}, [%4];" \
        : "=r"((r)[0]), "=r"((r)[1]), "=r"((r)[2]), "=r"((r)[3]) : "r"(a))

#define MMA16816(d, a, b0, b1) \
    asm volatile("mma.sync.aligned.m16n8k16.row.col.f32.f16.f16.f32 " \
        "{%0,%1,%2,%3}, {%4,%5,%6,%7}, {%8,%9}, {%0,%1,%2,%3};" \
        : "+f"((d)[0]), "+f"((d)[1]), "+f"((d)[2]), "+f"((d)[3]) \
        : "r"((a)[0]), "r"((a)[1]), "r"((a)[2]), "r"((a)[3]), "r"(b0), "r"(b1))

__device__ __forceinline__ void cp_async16(uint32_t dst, const void* src) {
    asm volatile("cp.async.cg.shared.global [%0], [%1], 16;" :: "r"(dst), "l"(src));
}

// ---------------- weight transpose + fp16: W[K,N] fp32 -> [N,K] fp16 ----------------
// grid (N/32, K/64, layers), block (32, 8). Per-layer src/dst strides.
__global__ void convert_w(const float* __restrict__ Wb, fp16* __restrict__ hb,
                          int K, int N, size_t lsrc, size_t ldst) {
    const float* W = Wb + (size_t)blockIdx.z * lsrc;
    fp16* hw = hb + (size_t)blockIdx.z * ldst;
    __shared__ float t[32][65];
    int n0 = blockIdx.x << 5, k0 = blockIdx.y << 6;
    int tx = threadIdx.x, ty = threadIdx.y;
    #pragma unroll
    for (int j = 0; j < 64; j += 8)
        t[tx][ty + j] = W[(size_t)(k0 + ty + j) * N + n0 + tx];
    __syncthreads();
    int tid = ty * 32 + tx;
    int n = tid >> 3, kc = (tid & 7) << 3;
    uint32_t h4[4];
    #pragma unroll
    for (int i = 0; i < 4; i++)
        h4[i] = pack_hf(t[n][kc + 2 * i], t[n][kc + 2 * i + 1]);
    size_t o = (size_t)(n0 + n) * K + kc + k0;
    *(uint4*)&hw[o] = make_uint4(h4[0], h4[1], h4[2], h4[3]);
}

// ---------------- mma.sync fp16 GEMM ----------------
// C[M,N] = A(fp16 [M,K]) * B(fp16 [N,K]),  fp32 accum, single term.
// grid (M/128, N/128).
// flags: 1 = +bias[N], 2 = relu, 4 = +add (residual, MxN)
// omode: 0 = C fp32 only; 1 = C fp32 + Ch fp16 token-major; 2 = Ch only;
//        5 = fused QKV (N=3072): col<1024 -> Ch (q head-major), <2048 -> Ck (k), else C as vt
#define STAGE_BYTES 32768
#define GM_SMEM (2*STAGE_BYTES)
__global__ void __launch_bounds__(256, 1) gemm_mma(
    const fp16* __restrict__ A, const fp16* __restrict__ B,
    const float* __restrict__ bias, const float* __restrict__ add,
    float* __restrict__ C, fp16* __restrict__ Ch, fp16* __restrict__ Ck,
    int M, int N, int K, int flags, int omode)
{
    extern __shared__ char smem[];
    const uint32_t sb = smem_u32(smem);
    const int tid = threadIdx.x, wid = tid >> 5, lane = tid & 31;
    const int m0 = blockIdx.x << 7, n0 = blockIdx.y << 7;
    const int wm = (wid & 1) << 6;
    const int wn = (wid >> 1) << 5;

    const fp16* gA = A + (size_t)m0 * K;
    const fp16* gB = B + (size_t)n0 * K;

    const int nchunk = K >> 6;
    const int l_row = tid >> 3;
    const int l_ch  = tid & 7;

    auto load_stage = [&](int s, int c) {
        const uint32_t st = sb + (uint32_t)s * STAGE_BYTES;
        const int kb = c << 6;
        const fp16* srcs[2] = { gA + kb, gB + kb };
        #pragma unroll
        for (int t = 0; t < 2; t++) {
            const uint32_t dstb = st + (uint32_t)t * 16384u;
            #pragma unroll
            for (int i = 0; i < 4; i++) {
                int row = l_row + (i << 5);
                uint32_t dst = dstb + (uint32_t)(row << 7) + (uint32_t)((l_ch ^ (row & 7)) << 4);
                cp_async16(dst, srcs[t] + (size_t)row * K + (l_ch << 3));
            }
        }
        asm volatile("cp.async.commit_group;" ::: "memory");
    };

    float acc[4][4][4];
    #pragma unroll
    for (int i = 0; i < 4; i++)
        #pragma unroll
        for (int j = 0; j < 4; j++)
            #pragma unroll
            for (int q = 0; q < 4; q++) acc[i][j][q] = 0.f;

    const int a_row = lane & 15;
    const int a_cb  = (lane >> 4) << 4;
    const int b_row = (lane & 7) + ((lane >> 4) << 3);
    const int b_cb  = ((lane >> 3) & 1) << 4;
    const uint32_t swz = (uint32_t)((lane & 7) << 4);

    load_stage(0, 0);

    for (int c = 0; c < nchunk; c++) {
        const int s = c & 1;
        if (c + 1 < nchunk) {
            load_stage(s ^ 1, c + 1);
            asm volatile("cp.async.wait_group 1;" ::: "memory");
        } else {
            asm volatile("cp.async.wait_group 0;" ::: "memory");
        }
        __syncthreads();

        const uint32_t st = sb + (uint32_t)s * STAGE_BYTES;
        #pragma unroll
        for (int kk = 0; kk < 4; kk++) {
            uint32_t ah[4][4], bh[2][4];
            #pragma unroll
            for (int mi = 0; mi < 4; mi++) {
                int row = wm + (mi << 4) + a_row;
                uint32_t off = (uint32_t)(row << 7) + (((uint32_t)((kk << 5) + a_cb)) ^ swz);
                LDSM4(ah[mi], st + off);
            }
            #pragma unroll
            for (int j = 0; j < 2; j++) {
                int row = wn + (j << 4) + b_row;
                uint32_t off = (uint32_t)(row << 7) + (((uint32_t)((kk << 5) + b_cb)) ^ swz);
                LDSM4(bh[j], st + 16384u + off);
            }
            #pragma unroll
            for (int mi = 0; mi < 4; mi++) {
                #pragma unroll
                for (int nj = 0; nj < 4; nj++) {
                    MMA16816(acc[mi][nj], ah[mi],
                             bh[nj >> 1][(nj & 1) << 1], bh[nj >> 1][((nj & 1) << 1) + 1]);
                }
            }
        }
        __syncthreads();
    }

    // epilogue
    const int er = m0 + wm + (lane >> 2);
    const int ec = n0 + wn + ((lane & 3) << 1);
    #pragma unroll
    for (int mi = 0; mi < 4; mi++) {
        #pragma unroll
        for (int hf = 0; hf < 2; hf++) {
            int row = er + (mi << 4) + (hf << 3);
            const float* Ar = (flags & 4) ? (add + (size_t)row * N) : nullptr;
            int bidx = row >> 10, srow = row & 1023;
            #pragma unroll
            for (int nj = 0; nj < 4; nj++) {
                int col = ec + (nj << 3);
                float v0 = acc[mi][nj][hf * 2 + 0];
                float v1 = acc[mi][nj][hf * 2 + 1];
                if (flags & 1) { v0 += bias[col]; v1 += bias[col + 1]; }
                if (flags & 4) { v0 += Ar[col];   v1 += Ar[col + 1]; }
                if (flags & 2) { v0 = fmaxf(v0, 0.f); v1 = fmaxf(v1, 0.f); }
                if (omode <= 1)
                    *(float2*)(C + (size_t)row * N + col) = make_float2(v0, v1);
                if (omode == 1 || omode == 2) {
                    *(uint32_t*)&Ch[(size_t)row * N + col] = pack_hf(v0, v1);
                } else if (omode == 5) {
                    int j = col >> 10, nn = col & 1023;
                    int h = nn >> 6, d = nn & 63;
                    if (j == 2) {
                        fp16* vtp = (fp16*)C;
                        size_t hb = (size_t)((bidx << 4) + h) << 6;
                        vtp[(hb + d) * 1024 + srow]     = __float2half_rn(v0);
                        vtp[(hb + d + 1) * 1024 + srow] = __float2half_rn(v1);
                    } else {
                        fp16* dstp = (j == 0) ? Ch : Ck;
                        size_t dst = (((size_t)((bidx << 4) + h) << 10) + srow) * 64 + d;
                        *(uint32_t*)&dstp[dst] = pack_hf(v0, v1);
                    }
                }
            }
        }
    }
}

// ---------------- scoresT: scT[bh][t][s] = 0.125 * k[bh,t,:].q[bh,s,:]  (fp16 in/out) ----------------
#define SC_SMEM 32768
__global__ void __launch_bounds__(256, 1) scoresT_mma(
    const fp16* __restrict__ Kh, const fp16* __restrict__ Qh,
    fp16* __restrict__ scT)
{
    extern __shared__ char smem[];
    const uint32_t sb = smem_u32(smem);
    const int tid = threadIdx.x, wid = tid >> 5, lane = tid & 31;
    const int bh = blockIdx.z;
    const int t0 = blockIdx.y << 7, s0 = blockIdx.x << 7;
    const size_t hbase = (size_t)bh << 16;
    const fp16* srcs[2] = { Kh + hbase + (size_t)t0 * 64, Qh + hbase + (size_t)s0 * 64 };

    {
        const int l_row = tid >> 3, l_ch = tid & 7;
        #pragma unroll
        for (int t = 0; t < 2; t++) {
            #pragma unroll
            for (int i = 0; i < 4; i++) {
                int row = l_row + (i << 5);
                uint32_t dst = sb + (uint32_t)t * 16384u + (uint32_t)(row << 7)
                             + (uint32_t)((l_ch ^ (row & 7)) << 4);
                cp_async16(dst, srcs[t] + (size_t)row * 64 + (l_ch << 3));
            }
        }
        asm volatile("cp.async.commit_group;" ::: "memory");
        asm volatile("cp.async.wait_group 0;" ::: "memory");
    }
    __syncthreads();

    const int wm = (wid & 1) << 6, wn = (wid >> 1) << 5;
    float acc[4][4][4];
    #pragma unroll
    for (int i = 0; i < 4; i++)
        #pragma unroll
        for (int j = 0; j < 4; j++)
            #pragma unroll
            for (int q = 0; q < 4; q++) acc[i][j][q] = 0.f;

    const int a_row = lane & 15, a_cb = (lane >> 4) << 4;
    const int b_row = (lane & 7) + ((lane >> 4) << 3), b_cb = ((lane >> 3) & 1) << 4;
    const uint32_t swz = (uint32_t)((lane & 7) << 4);

    #pragma unroll
    for (int kk = 0; kk < 4; kk++) {
        uint32_t ah[4][4], bh2[2][4];
        #pragma unroll
        for (int mi = 0; mi < 4; mi++) {
            int row = wm + (mi << 4) + a_row;
            uint32_t off = (uint32_t)(row << 7) + (((uint32_t)((kk << 5) + a_cb)) ^ swz);
            LDSM4(ah[mi], sb + off);
        }
        #pragma unroll
        for (int j = 0; j < 2; j++) {
            int row = wn + (j << 4) + b_row;
            uint32_t off = (uint32_t)(row << 7) + (((uint32_t)((kk << 5) + b_cb)) ^ swz);
            LDSM4(bh2[j], sb + 16384u + off);
        }
        #pragma unroll
        for (int mi = 0; mi < 4; mi++) {
            #pragma unroll
            for (int nj = 0; nj < 4; nj++) {
                MMA16816(acc[mi][nj], ah[mi],
                         bh2[nj >> 1][(nj & 1) << 1], bh2[nj >> 1][((nj & 1) << 1) + 1]);
            }
        }
    }

    fp16* ob = scT + ((size_t)bh << 20);
    const int er = t0 + wm + (lane >> 2);
    const int ec = s0 + wn + ((lane & 3) << 1);
    #pragma unroll
    for (int mi = 0; mi < 4; mi++) {
        #pragma unroll
        for (int hf = 0; hf < 2; hf++) {
            int row = er + (mi << 4) + (hf << 3);
            #pragma unroll
            for (int nj = 0; nj < 4; nj++) {
                int col = ec + (nj << 3);
                *(uint32_t*)(ob + (size_t)row * Sn + col) =
                    pack_hf(acc[mi][nj][hf * 2] * 0.125f,
                            acc[mi][nj][hf * 2 + 1] * 0.125f);
            }
        }
    }
}

// ---------------- parallel column softmax over t (UNMASKED, bug-faithful) ----------------
__global__ void __launch_bounds__(256) col_softmax(const fp16* __restrict__ scT,
                                                   fp16* __restrict__ pT) {
    __shared__ float sm0[8][33], sm1[8][33], ss0[8][33], ss1[8][33];
    const int bh = blockIdx.y;
    const int lane = threadIdx.x & 31;
    const int chunk = threadIdx.x >> 5;
    const int s = (blockIdx.x << 6) + (lane << 1);
    const fp16* base = scT + ((size_t)bh << 20) + s;
    const int t0 = chunk << 7;
    float cm0 = -3.402823466e38f, cm1 = -3.402823466e38f, cu0 = 0.f, cu1 = 0.f;
    #pragma unroll 4
    for (int t = 0; t < 128; t++) {
        __half2 h = *(const __half2*)(base + ((size_t)(t0 + t) << 10));
        float x0 = __low2float(h), x1 = __high2float(h);
        float n0 = fmaxf(cm0, x0), n1 = fmaxf(cm1, x1);
        cu0 = cu0 * __expf(cm0 - n0) + __expf(x0 - n0);
        cu1 = cu1 * __expf(cm1 - n1) + __expf(x1 - n1);
        cm0 = n0; cm1 = n1;
    }
    sm0[chunk][lane] = cm0; sm1[chunk][lane] = cm1;
    ss0[chunk][lane] = cu0; ss1[chunk][lane] = cu1;
    __syncthreads();
    float gM0 = -3.402823466e38f, gM1 = -3.402823466e38f;
    #pragma unroll
    for (int i = 0; i < 8; i++) {
        gM0 = fmaxf(gM0, sm0[i][lane]);
        gM1 = fmaxf(gM1, sm1[i][lane]);
    }
    float gS0 = 0.f, gS1 = 0.f;
    #pragma unroll
    for (int i = 0; i < 8; i++) {
        gS0 += ss0[i][lane] * __expf(sm0[i][lane] - gM0);
        gS1 += ss1[i][lane] * __expf(sm1[i][lane] - gM1);
    }
    float inv0 = 1.f / gS0, inv1 = 1.f / gS1;
    fp16* ob = pT + ((size_t)bh << 20) + s;
    #pragma unroll 4
    for (int t = 0; t < 128; t++) {
        __half2 h = *(const __half2*)(base + ((size_t)(t0 + t) << 10));
        float p0 = __expf(__low2float(h) - gM0) * inv0;
        float p1 = __expf(__high2float(h) - gM1) * inv1;
        *(uint32_t*)(ob + ((size_t)(t0 + t) << 10)) = pack_hf(p0, p1);
    }
}

// ---------------- AV: mha[b,t,h,d] = sum_s pT[bh,t,s] * vT[bh,d,s] ----------------
#define AV_STAGE 49152
#define AV_SMEM (2*AV_STAGE)
__global__ void __launch_bounds__(256, 1) av_mma(
    const fp16* __restrict__ pT, const fp16* __restrict__ vT,
    fp16* __restrict__ Mh)
{
    extern __shared__ char smem[];
    const uint32_t sb = smem_u32(smem);
    const int tid = threadIdx.x, wid = tid >> 5, lane = tid & 31;
    const int bh = blockIdx.y, t0 = blockIdx.x << 7;
    const fp16* gA = pT + ((size_t)bh << 20) + (size_t)t0 * 1024;
    const fp16* gB = vT + ((size_t)bh << 16);

    auto load_stage = [&](int s, int c) {
        const uint32_t st = sb + (uint32_t)s * AV_STAGE;
        const int kb = c << 7;
        #pragma unroll
        for (int i = 0; i < 8; i++) {
            int idx = tid + (i << 8);
            int row = idx >> 4, ch = idx & 15;
            uint32_t dst = st + (uint32_t)(row << 8) + (uint32_t)((ch ^ (row & 7)) << 4);
            cp_async16(dst, gA + (size_t)row * 1024 + kb + (ch << 3));
        }
        #pragma unroll
        for (int i = 0; i < 4; i++) {
            int idx = tid + (i << 8);
            int row = idx >> 4, ch = idx & 15;
            uint32_t dst = st + 32768u + (uint32_t)(row << 8) + (uint32_t)((ch ^ (row & 7)) << 4);
            cp_async16(dst, gB + (size_t)row * 1024 + kb + (ch << 3));
        }
        asm volatile("cp.async.commit_group;" ::: "memory");
    };

    const int wm = (wid & 3) << 5, wn = (wid >> 2) << 5;
    float acc[2][4][4];
    #pragma unroll
    for (int i = 0; i < 2; i++)
        #pragma unroll
        for (int j = 0; j < 4; j++)
            #pragma unroll
            for (int q = 0; q < 4; q++) acc[i][j][q] = 0.f;

    const int a_row = lane & 15, a_cb = (lane >> 4) << 4;
    const int b_row = (lane & 7) + ((lane >> 4) << 3), b_cb = ((lane >> 3) & 1) << 4;
    const uint32_t swz = (uint32_t)((lane & 7) << 4);

    load_stage(0, 0);
    for (int c = 0; c < 8; c++) {
        const int s = c & 1;
        if (c + 1 < 8) {
            load_stage(s ^ 1, c + 1);
            asm volatile("cp.async.wait_group 1;" ::: "memory");
        } else {
            asm volatile("cp.async.wait_group 0;" ::: "memory");
        }
        __syncthreads();

        const uint32_t st = sb + (uint32_t)s * AV_STAGE;
        #pragma unroll
        for (int kk = 0; kk < 8; kk++) {
            uint32_t af[2][4], bf2[2][4];
            #pragma unroll
            for (int mi = 0; mi < 2; mi++) {
                int row = wm + (mi << 4) + a_row;
                uint32_t off = (uint32_t)(row << 8) + (((uint32_t)((kk << 5) + a_cb)) ^ swz);
                LDSM4(af[mi], st + off);
            }
            #pragma unroll
            for (int j = 0; j < 2; j++) {
                int row = wn + (j << 4) + b_row;
                uint32_t off = (uint32_t)(row << 8) + (((uint32_t)((kk << 5) + b_cb)) ^ swz);
                LDSM4(bf2[j], st + 32768u + off);
            }
            #pragma unroll
            for (int mi = 0; mi < 2; mi++) {
                #pragma unroll
                for (int nj = 0; nj < 4; nj++) {
                    MMA16816(acc[mi][nj], af[mi],
                             bf2[nj >> 1][(nj & 1) << 1], bf2[nj >> 1][((nj & 1) << 1) + 1]);
                }
            }
        }
        __syncthreads();
    }

    const int b = bh >> 4, h = bh & 15;
    const int er = t0 + wm + (lane >> 2);
    const int ec = wn + ((lane & 3) << 1);
    #pragma unroll
    for (int mi = 0; mi < 2; mi++) {
        #pragma unroll
        for (int hf = 0; hf < 2; hf++) {
            int t = er + (mi << 4) + (hf << 3);
            size_t rowbase = ((size_t)(b << 10) + t) * 1024 + (h << 6);
            #pragma unroll
            for (int nj = 0; nj < 4; nj++) {
                int col = ec + (nj << 3);
                *(uint32_t*)&Mh[rowbase + col] =
                    pack_hf(acc[mi][nj][hf * 2], acc[mi][nj][hf * 2 + 1]);
            }
        }
    }
}

// ---------------- block reductions ----------------
__device__ __forceinline__ float blockReduceSum(float v) {
    __shared__ float sh[33];
    int lane = threadIdx.x & 31, w = threadIdx.x >> 5;
    #pragma unroll
    for (int o = 16; o > 0; o >>= 1) v += __shfl_xor_sync(0xffffffffu, v, o);
    __syncthreads();
    if (lane == 0) sh[w] = v;
    __syncthreads();
    if (w == 0) {
        v = (lane < (int)(blockDim.x >> 5)) ? sh[lane] : 0.f;
        #pragma unroll
        for (int o = 16; o > 0; o >>= 1) v += __shfl_xor_sync(0xffffffffu, v, o);
        if (lane == 0) sh[32] = v;
    }
    __syncthreads();
    return sh[32];
}
__device__ __forceinline__ float blockReduceMax(float v) {
    __shared__ float sh[33];
    int lane = threadIdx.x & 31, w = threadIdx.x >> 5;
    #pragma unroll
    for (int o = 16; o > 0; o >>= 1) v = fmaxf(v, __shfl_xor_sync(0xffffffffu, v, o));
    __syncthreads();
    if (lane == 0) sh[w] = v;
    __syncthreads();
    if (w == 0) {
        v = (lane < (int)(blockDim.x >> 5)) ? sh[lane] : -3.402823466e38f;
        #pragma unroll
        for (int o = 16; o > 0; o >>= 1) v = fmaxf(v, __shfl_xor_sync(0xffffffffu, v, o));
        if (lane == 0) sh[32] = v;
    }
    __syncthreads();
    return sh[32];
}

// ---------------- embedding: x fp32 + fp16 ----------------
__global__ void embed_kernel(const int* __restrict__ tokens,
                             const float* __restrict__ tok,
                             const float* __restrict__ pos,
                             float* __restrict__ x, fp16* __restrict__ xh) {
    int idx = blockIdx.x * blockDim.x + threadIdx.x;
    const int EV = En / 4;
    if (idx >= NTOK * EV) return;
    int bs = idx / EV, e4 = idx % EV;
    int s = bs & (Sn - 1);
    int t = tokens[bs];
    float4 a = ((const float4*)tok)[(size_t)t * EV + e4];
    float4 p = ((const float4*)pos)[(size_t)s * EV + e4];
    float4 r;
    r.x = a.x + p.x; r.y = a.y + p.y; r.z = a.z + p.z; r.w = a.w + p.w;
    ((float4*)x)[idx] = r;
    ((uint2*)xh)[idx] = make_uint2(pack_hf(r.x, r.y), pack_hf(r.z, r.w));
}

// ---------------- rmsnorm -> fp16 ----------------
__global__ void add_rmsnorm_kernel(const float* __restrict__ x, const float* __restrict__ add,
                                   const float* __restrict__ scale, fp16* __restrict__ oh)
{
    int row = blockIdx.x, tid = threadIdx.x;
    const float* xr = x + (size_t)row * En;
    const float* ar = add ? add + (size_t)row * En : nullptr;
    float v[4]; float ss = 0.f;
    #pragma unroll
    for (int j = 0; j < 4; j++) {
        int e = tid + j * 256;
        float t = xr[e];
        if (ar) t += ar[e];
        v[j] = t;
        ss += t * t;
    }
    ss = blockReduceSum(ss);
    float r = rsqrtf(ss * (1.f / En) + 1e-6f);
    #pragma unroll
    for (int j = 0; j < 4; j++) {
        int e = tid + j * 256;
        oh[(size_t)row * En + e] = __float2half_rn(v[j] * r * scale[e]);
    }
}

// ---------------- log_softmax ----------------
__global__ void log_softmax_kernel(float* __restrict__ a) {
    float* row = a + (size_t)blockIdx.x * Vn;
    int tid = threadIdx.x;
    float m = -3.402823466e38f;
    for (int i = tid; i < Vn; i += 256) m = fmaxf(m, row[i]);
    m = blockReduceMax(m);
    float s = 0.f;
    for (int i = tid; i < Vn; i += 256) s += __expf(row[i] - m);
    s = blockReduceSum(s);
    float lse = m + logf(s);
    for (int i = tid; i < Vn; i += 256) row[i] -= lse;
}

// ---------------- launch ----------------
extern "C" void kernel_launch(void* const* d_in, const int* in_sizes, int n_in,
                              void* d_out, int out_size) {
    const int*   tokens      = (const int*)  d_in[0];
    const float* tok_embed   = (const float*)d_in[1];
    const float* pos_embed   = (const float*)d_in[2];
    const float* Qw          = (const float*)d_in[3];
    const float* Kw          = (const float*)d_in[4];
    const float* Vw          = (const float*)d_in[5];
    const float* Ow          = (const float*)d_in[6];
    const float* rs2         = (const float*)d_in[7];
    const float* w1          = (const float*)d_in[8];
    const float* b1          = (const float*)d_in[9];
    const float* w2          = (const float*)d_in[10];
    const float* b2          = (const float*)d_in[11];
    const float* final_scale = (const float*)d_in[12];
    const float* w_out       = (const float*)d_in[13];
    const float* b_out       = (const float*)d_in[14];
    float* out = (float*)d_out;

    float *xb, *projb;
    fp16 *wh, *attb, *ptb, *xh, *qh, *kh, *vt, *mh, *rh, *hh;
    cudaGetSymbolAddress((void**)&xb,    g_x);
    cudaGetSymbolAddress((void**)&projb, g_proj);
    cudaGetSymbolAddress((void**)&attb,  g_att);
    cudaGetSymbolAddress((void**)&ptb,   g_pt);
    cudaGetSymbolAddress((void**)&wh,    g_wh);
    cudaGetSymbolAddress((void**)&xh,    g_xh);
    cudaGetSymbolAddress((void**)&qh,    g_qh);
    cudaGetSymbolAddress((void**)&kh,    g_kh);
    cudaGetSymbolAddress((void**)&vt,    g_vt);
    cudaGetSymbolAddress((void**)&mh,    g_mh);
    cudaGetSymbolAddress((void**)&rh,    g_rh);
    cudaGetSymbolAddress((void**)&hh,    g_hh);

    cudaFuncSetAttribute(gemm_mma,    cudaFuncAttributeMaxDynamicSharedMemorySize, GM_SMEM);
    cudaFuncSetAttribute(scoresT_mma, cudaFuncAttributeMaxDynamicSharedMemorySize, SC_SMEM);
    cudaFuncSetAttribute(av_mma,      cudaFuncAttributeMaxDynamicSharedMemorySize, AV_SMEM);

    // ---- weight conversion: transpose + fp16, layer-fused (7 launches) ----
    dim3 cb(32, 8);
    convert_w<<<dim3(32, 16, Lnum), cb>>>(Qw, wh,          En, HIDn, M1, 3 * (size_t)M1);
    convert_w<<<dim3(32, 16, Lnum), cb>>>(Kw, wh + M1,     En, HIDn, M1, 3 * (size_t)M1);
    convert_w<<<dim3(32, 16, Lnum), cb>>>(Vw, wh + 2 * M1, En, HIDn, M1, 3 * (size_t)M1);
    convert_w<<<dim3(32, 16, Lnum), cb>>>(Ow, wh + 12 * (size_t)M1, HIDn, En, M1, M1);
    convert_w<<<dim3(128, 16, Lnum), cb>>>(w1, wh + 16 * (size_t)M1, En, FFn,
                                           4 * (size_t)M1, 4 * (size_t)M1);
    convert_w<<<dim3(32, 64, Lnum), cb>>>(w2, wh + 32 * (size_t)M1, FFn, En,
                                          4 * (size_t)M1, 4 * (size_t)M1);
    convert_w<<<dim3(Vn / 32, 16, 1), cb>>>(w_out, wh + 48 * (size_t)M1, En, Vn, 0, 0);

    embed_kernel<<<(NTOK * (En / 4) + 255) / 256, 256>>>(tokens, tok_embed, pos_embed, xb, xh);

    for (int l = 0; l < Lnum; l++) {
        const fp16 *QKVw = wh + (size_t)l * 3 * M1;
        const fp16 *Owl  = wh + 12 * (size_t)M1 + (size_t)l * M1;
        const fp16 *W1l  = wh + 16 * (size_t)M1 + (size_t)l * 4 * M1;
        const fp16 *W2l  = wh + 32 * (size_t)M1 + (size_t)l * 4 * M1;
        const float* r2l = rs2 + (size_t)l * En;
        const float* b1l = b1 + (size_t)l * FFn;
        const float* b2l = b2 + (size_t)l * En;

        // fused QKV: M=2048, N=3072 (q | k | v)
        gemm_mma<<<dim3(NTOK / 128, 3 * HIDn / 128), 256, GM_SMEM>>>(
            xh, QKVw, nullptr, nullptr, (float*)vt, qh, kh, NTOK, 3 * HIDn, En, 0, 5);

        scoresT_mma<<<dim3(Sn / 128, Sn / 128, Bn * NHn), 256, SC_SMEM>>>(kh, qh, attb);
        col_softmax<<<dim3(Sn / 64, Bn * NHn), 256>>>(attb, ptb);
        av_mma<<<dim3(Sn / 128, Bn * NHn), 256, AV_SMEM>>>(ptb, vt, mh);

        gemm_mma<<<dim3(NTOK / 128, En / 128), 256, GM_SMEM>>>(
            mh, Owl, nullptr, nullptr, projb, nullptr, nullptr, NTOK, En, HIDn, 0, 0);
        add_rmsnorm_kernel<<<NTOK, 256>>>(xb, projb, r2l, rh);

        gemm_mma<<<dim3(NTOK / 128, FFn / 128), 256, GM_SMEM>>>(
            rh, W1l, b1l, nullptr, nullptr, hh, nullptr, NTOK, FFn, En, 1 | 2, 2);
        gemm_mma<<<dim3(NTOK / 128, En / 128), 256, GM_SMEM>>>(
            hh, W2l, b2l, projb, xb, xh, nullptr, NTOK, En, FFn, 1 | 4, 1);
    }

    add_rmsnorm_kernel<<<NTOK, 256>>>(xb, nullptr, final_scale, xh);

    gemm_mma<<<dim3(NTOK / 128, Vn / 128), 256, GM_SMEM>>>(
        xh, wh + 48 * (size_t)M1, b_out, nullptr, out, nullptr, nullptr, NTOK, Vn, En, 1, 0);
    log_softmax_kernel<<<NTOK, 256>>>(out);
}

// round 17
// speedup vs baseline: 1.9752x; 1.0468x over previous
#include <cuda_runtime.h>
#include <cuda_fp16.h>
#include <math.h>
#include <stdint.h>

// ---------------- problem constants ----------------
#define Lnum 4
#define Bn   2
#define Sn   1024
#define En   1024
#define NHn  16
#define HDn  64
#define HIDn 1024
#define FFn  4096
#define Vn   32000
#define NTOK (Bn*Sn)   // 2048
#define M1   (1u<<20)  // 1024*1024

typedef __half fp16;

// ---------------- scratch (static device memory; no allocation) ----------------
__device__ float g_x   [NTOK*En];                 // residual stream fp32
__device__ float g_proj[NTOK*En];                 // attn projection fp32
__device__ fp16  g_att [(size_t)Bn*NHn*Sn*Sn];    // scoresT fp16, 64 MB
__device__ fp16  g_pt  [(size_t)Bn*NHn*Sn*Sn];    // probsT fp16, 64 MB
__device__ fp16  g_lg  [(size_t)NTOK*Vn];         // logits fp16, 131 MB

__device__ fp16 g_xh[NTOK*En];                    // x fp16
__device__ fp16 g_qh[NTOK*HIDn];                  // q head-major [b,h,s,d]
__device__ fp16 g_kh[NTOK*HIDn];                  // k head-major
__device__ fp16 g_vt[NTOK*HIDn];                  // v transposed [b,h,d,s]
__device__ fp16 g_mh[NTOK*En];                    // mha token-major
__device__ fp16 g_rh[NTOK*En];                    // rmsnorm out
__device__ fp16 g_hh[(size_t)NTOK*FFn];           // FF hidden

// fp16 transposed weights: [N,K] layout.
// QKV interleaved: [l][3][N][K] at offset (l*3+j)*M1.  O at 12M1+l*M1.
// W1 16M1+l*4M1 | W2 32M1+l*4M1 | Wout 48M1.
#define WTOT (48u*M1 + (size_t)Vn*En)
__device__ fp16 g_wh[WTOT];

// ---------------- helpers ----------------
__device__ __forceinline__ uint32_t smem_u32(const void* p) {
    uint32_t a;
    asm("{ .reg .u64 t; cvta.to.shared.u64 t, %1; cvt.u32.u64 %0, t; }" : "=r"(a) : "l"(p));
    return a;
}
__device__ __forceinline__ uint32_t pack_hf(float a, float b) {
    __half2 h = __floats2half2_rn(a, b);
    return *(uint32_t*)&h;
}
__device__ __forceinline__ void ms_combine(float& m, float& s, float m2, float s2) {
    float M = fmaxf(m, m2);
    s = s * __expf(m - M) + s2 * __expf(m2 - M);
    m = M;
}

#define LDSM4(r, a) \
    asm volatile("ldmatrix.sync.aligned.m8n8.x4.shared.b16 {%0,%1,%2,%3}, [%4];" \
        : "=r"((r)[0]), "=r"((r)[1]), "=r"((r)[2]), "=r"((r)[3]) : "r"(a))

#define MMA16816(d, a, b0, b1) \
    asm volatile("mma.sync.aligned.m16n8k16.row.col.f32.f16.f16.f32 " \
        "{%0,%1,%2,%3}, {%4,%5,%6,%7}, {%8,%9}, {%0,%1,%2,%3};" \
        : "+f"((d)[0]), "+f"((d)[1]), "+f"((d)[2]), "+f"((d)[3]) \
        : "r"((a)[0]), "r"((a)[1]), "r"((a)[2]), "r"((a)[3]), "r"(b0), "r"(b1))

__device__ __forceinline__ void cp_async16(uint32_t dst, const void* src) {
    asm volatile("cp.async.cg.shared.global [%0], [%1], 16;" :: "r"(dst), "l"(src));
}

// ---------------- weight transpose + fp16: W[K,N] fp32 -> [N,K] fp16 ----------------
// grid (N/32, K/64, layers), block (32, 8). Per-layer src/dst strides.
__global__ void convert_w(const float* __restrict__ Wb, fp16* __restrict__ hb,
                          int K, int N, size_t lsrc, size_t ldst) {
    const float* W = Wb + (size_t)blockIdx.z * lsrc;
    fp16* hw = hb + (size_t)blockIdx.z * ldst;
    __shared__ float t[32][65];
    int n0 = blockIdx.x << 5, k0 = blockIdx.y << 6;
    int tx = threadIdx.x, ty = threadIdx.y;
    #pragma unroll
    for (int j = 0; j < 64; j += 8)
        t[tx][ty + j] = W[(size_t)(k0 + ty + j) * N + n0 + tx];
    __syncthreads();
    int tid = ty * 32 + tx;
    int n = tid >> 3, kc = (tid & 7) << 3;
    uint32_t h4[4];
    #pragma unroll
    for (int i = 0; i < 4; i++)
        h4[i] = pack_hf(t[n][kc + 2 * i], t[n][kc + 2 * i + 1]);
    size_t o = (size_t)(n0 + n) * K + kc + k0;
    *(uint4*)&hw[o] = make_uint4(h4[0], h4[1], h4[2], h4[3]);
}

// ---------------- mma.sync fp16 GEMM ----------------
// C[M,N] = A(fp16 [M,K]) * B(fp16 [N,K]),  fp32 accum, single term.
// grid (M/128, N/128).
// flags: 1 = +bias[N], 2 = relu, 4 = +add (residual, MxN)
// omode: 0 = C fp32 only; 1 = C fp32 + Ch fp16 token-major; 2 = Ch only;
//        5 = fused QKV (N=3072): col<1024 -> Ch (q head-major), <2048 -> Ck (k), else C as vt
#define STAGE_BYTES 32768
#define GM_SMEM (2*STAGE_BYTES)
__global__ void __launch_bounds__(256, 1) gemm_mma(
    const fp16* __restrict__ A, const fp16* __restrict__ B,
    const float* __restrict__ bias, const float* __restrict__ add,
    float* __restrict__ C, fp16* __restrict__ Ch, fp16* __restrict__ Ck,
    int M, int N, int K, int flags, int omode)
{
    extern __shared__ char smem[];
    const uint32_t sb = smem_u32(smem);
    const int tid = threadIdx.x, wid = tid >> 5, lane = tid & 31;
    const int m0 = blockIdx.x << 7, n0 = blockIdx.y << 7;
    const int wm = (wid & 1) << 6;
    const int wn = (wid >> 1) << 5;

    const fp16* gA = A + (size_t)m0 * K;
    const fp16* gB = B + (size_t)n0 * K;

    const int nchunk = K >> 6;
    const int l_row = tid >> 3;
    const int l_ch  = tid & 7;

    auto load_stage = [&](int s, int c) {
        const uint32_t st = sb + (uint32_t)s * STAGE_BYTES;
        const int kb = c << 6;
        const fp16* srcs[2] = { gA + kb, gB + kb };
        #pragma unroll
        for (int t = 0; t < 2; t++) {
            const uint32_t dstb = st + (uint32_t)t * 16384u;
            #pragma unroll
            for (int i = 0; i < 4; i++) {
                int row = l_row + (i << 5);
                uint32_t dst = dstb + (uint32_t)(row << 7) + (uint32_t)((l_ch ^ (row & 7)) << 4);
                cp_async16(dst, srcs[t] + (size_t)row * K + (l_ch << 3));
            }
        }
        asm volatile("cp.async.commit_group;" ::: "memory");
    };

    float acc[4][4][4];
    #pragma unroll
    for (int i = 0; i < 4; i++)
        #pragma unroll
        for (int j = 0; j < 4; j++)
            #pragma unroll
            for (int q = 0; q < 4; q++) acc[i][j][q] = 0.f;

    const int a_row = lane & 15;
    const int a_cb  = (lane >> 4) << 4;
    const int b_row = (lane & 7) + ((lane >> 4) << 3);
    const int b_cb  = ((lane >> 3) & 1) << 4;
    const uint32_t swz = (uint32_t)((lane & 7) << 4);

    load_stage(0, 0);

    for (int c = 0; c < nchunk; c++) {
        const int s = c & 1;
        if (c + 1 < nchunk) {
            load_stage(s ^ 1, c + 1);
            asm volatile("cp.async.wait_group 1;" ::: "memory");
        } else {
            asm volatile("cp.async.wait_group 0;" ::: "memory");
        }
        __syncthreads();

        const uint32_t st = sb + (uint32_t)s * STAGE_BYTES;
        #pragma unroll
        for (int kk = 0; kk < 4; kk++) {
            uint32_t ah[4][4], bh[2][4];
            #pragma unroll
            for (int mi = 0; mi < 4; mi++) {
                int row = wm + (mi << 4) + a_row;
                uint32_t off = (uint32_t)(row << 7) + (((uint32_t)((kk << 5) + a_cb)) ^ swz);
                LDSM4(ah[mi], st + off);
            }
            #pragma unroll
            for (int j = 0; j < 2; j++) {
                int row = wn + (j << 4) + b_row;
                uint32_t off = (uint32_t)(row << 7) + (((uint32_t)((kk << 5) + b_cb)) ^ swz);
                LDSM4(bh[j], st + 16384u + off);
            }
            #pragma unroll
            for (int mi = 0; mi < 4; mi++) {
                #pragma unroll
                for (int nj = 0; nj < 4; nj++) {
                    MMA16816(acc[mi][nj], ah[mi],
                             bh[nj >> 1][(nj & 1) << 1], bh[nj >> 1][((nj & 1) << 1) + 1]);
                }
            }
        }
        __syncthreads();
    }

    // epilogue
    const int er = m0 + wm + (lane >> 2);
    const int ec = n0 + wn + ((lane & 3) << 1);
    #pragma unroll
    for (int mi = 0; mi < 4; mi++) {
        #pragma unroll
        for (int hf = 0; hf < 2; hf++) {
            int row = er + (mi << 4) + (hf << 3);
            const float* Ar = (flags & 4) ? (add + (size_t)row * N) : nullptr;
            int bidx = row >> 10, srow = row & 1023;
            #pragma unroll
            for (int nj = 0; nj < 4; nj++) {
                int col = ec + (nj << 3);
                float v0 = acc[mi][nj][hf * 2 + 0];
                float v1 = acc[mi][nj][hf * 2 + 1];
                if (flags & 1) { v0 += bias[col]; v1 += bias[col + 1]; }
                if (flags & 4) { v0 += Ar[col];   v1 += Ar[col + 1]; }
                if (flags & 2) { v0 = fmaxf(v0, 0.f); v1 = fmaxf(v1, 0.f); }
                if (omode <= 1)
                    *(float2*)(C + (size_t)row * N + col) = make_float2(v0, v1);
                if (omode == 1 || omode == 2) {
                    *(uint32_t*)&Ch[(size_t)row * N + col] = pack_hf(v0, v1);
                } else if (omode == 5) {
                    int j = col >> 10, nn = col & 1023;
                    int h = nn >> 6, d = nn & 63;
                    if (j == 2) {
                        fp16* vtp = (fp16*)C;
                        size_t hb = (size_t)((bidx << 4) + h) << 6;
                        vtp[(hb + d) * 1024 + srow]     = __float2half_rn(v0);
                        vtp[(hb + d + 1) * 1024 + srow] = __float2half_rn(v1);
                    } else {
                        fp16* dstp = (j == 0) ? Ch : Ck;
                        size_t dst = (((size_t)((bidx << 4) + h) << 10) + srow) * 64 + d;
                        *(uint32_t*)&dstp[dst] = pack_hf(v0, v1);
                    }
                }
            }
        }
    }
}

// ---------------- scoresT: scT[bh][t][s] = 0.125 * k[bh,t,:].q[bh,s,:]  (fp16 in/out) ----------------
#define SC_SMEM 32768
__global__ void __launch_bounds__(256, 1) scoresT_mma(
    const fp16* __restrict__ Kh, const fp16* __restrict__ Qh,
    fp16* __restrict__ scT)
{
    extern __shared__ char smem[];
    const uint32_t sb = smem_u32(smem);
    const int tid = threadIdx.x, wid = tid >> 5, lane = tid & 31;
    const int bh = blockIdx.z;
    const int t0 = blockIdx.y << 7, s0 = blockIdx.x << 7;
    const size_t hbase = (size_t)bh << 16;
    const fp16* srcs[2] = { Kh + hbase + (size_t)t0 * 64, Qh + hbase + (size_t)s0 * 64 };

    {
        const int l_row = tid >> 3, l_ch = tid & 7;
        #pragma unroll
        for (int t = 0; t < 2; t++) {
            #pragma unroll
            for (int i = 0; i < 4; i++) {
                int row = l_row + (i << 5);
                uint32_t dst = sb + (uint32_t)t * 16384u + (uint32_t)(row << 7)
                             + (uint32_t)((l_ch ^ (row & 7)) << 4);
                cp_async16(dst, srcs[t] + (size_t)row * 64 + (l_ch << 3));
            }
        }
        asm volatile("cp.async.commit_group;" ::: "memory");
        asm volatile("cp.async.wait_group 0;" ::: "memory");
    }
    __syncthreads();

    const int wm = (wid & 1) << 6, wn = (wid >> 1) << 5;
    float acc[4][4][4];
    #pragma unroll
    for (int i = 0; i < 4; i++)
        #pragma unroll
        for (int j = 0; j < 4; j++)
            #pragma unroll
            for (int q = 0; q < 4; q++) acc[i][j][q] = 0.f;

    const int a_row = lane & 15, a_cb = (lane >> 4) << 4;
    const int b_row = (lane & 7) + ((lane >> 4) << 3), b_cb = ((lane >> 3) & 1) << 4;
    const uint32_t swz = (uint32_t)((lane & 7) << 4);

    #pragma unroll
    for (int kk = 0; kk < 4; kk++) {
        uint32_t ah[4][4], bh2[2][4];
        #pragma unroll
        for (int mi = 0; mi < 4; mi++) {
            int row = wm + (mi << 4) + a_row;
            uint32_t off = (uint32_t)(row << 7) + (((uint32_t)((kk << 5) + a_cb)) ^ swz);
            LDSM4(ah[mi], sb + off);
        }
        #pragma unroll
        for (int j = 0; j < 2; j++) {
            int row = wn + (j << 4) + b_row;
            uint32_t off = (uint32_t)(row << 7) + (((uint32_t)((kk << 5) + b_cb)) ^ swz);
            LDSM4(bh2[j], sb + 16384u + off);
        }
        #pragma unroll
        for (int mi = 0; mi < 4; mi++) {
            #pragma unroll
            for (int nj = 0; nj < 4; nj++) {
                MMA16816(acc[mi][nj], ah[mi],
                         bh2[nj >> 1][(nj & 1) << 1], bh2[nj >> 1][((nj & 1) << 1) + 1]);
            }
        }
    }

    fp16* ob = scT + ((size_t)bh << 20);
    const int er = t0 + wm + (lane >> 2);
    const int ec = s0 + wn + ((lane & 3) << 1);
    #pragma unroll
    for (int mi = 0; mi < 4; mi++) {
        #pragma unroll
        for (int hf = 0; hf < 2; hf++) {
            int row = er + (mi << 4) + (hf << 3);
            #pragma unroll
            for (int nj = 0; nj < 4; nj++) {
                int col = ec + (nj << 3);
                *(uint32_t*)(ob + (size_t)row * Sn + col) =
                    pack_hf(acc[mi][nj][hf * 2] * 0.125f,
                            acc[mi][nj][hf * 2 + 1] * 0.125f);
            }
        }
    }
}

// ---------------- parallel column softmax over t (UNMASKED, bug-faithful) ----------------
__global__ void __launch_bounds__(256) col_softmax(const fp16* __restrict__ scT,
                                                   fp16* __restrict__ pT) {
    __shared__ float sm0[8][33], sm1[8][33], ss0[8][33], ss1[8][33];
    const int bh = blockIdx.y;
    const int lane = threadIdx.x & 31;
    const int chunk = threadIdx.x >> 5;
    const int s = (blockIdx.x << 6) + (lane << 1);
    const fp16* base = scT + ((size_t)bh << 20) + s;
    const int t0 = chunk << 7;
    float cm0 = -3.402823466e38f, cm1 = -3.402823466e38f, cu0 = 0.f, cu1 = 0.f;
    #pragma unroll 4
    for (int t = 0; t < 128; t++) {
        __half2 h = *(const __half2*)(base + ((size_t)(t0 + t) << 10));
        float x0 = __low2float(h), x1 = __high2float(h);
        float n0 = fmaxf(cm0, x0), n1 = fmaxf(cm1, x1);
        cu0 = cu0 * __expf(cm0 - n0) + __expf(x0 - n0);
        cu1 = cu1 * __expf(cm1 - n1) + __expf(x1 - n1);
        cm0 = n0; cm1 = n1;
    }
    sm0[chunk][lane] = cm0; sm1[chunk][lane] = cm1;
    ss0[chunk][lane] = cu0; ss1[chunk][lane] = cu1;
    __syncthreads();
    float gM0 = -3.402823466e38f, gM1 = -3.402823466e38f;
    #pragma unroll
    for (int i = 0; i < 8; i++) {
        gM0 = fmaxf(gM0, sm0[i][lane]);
        gM1 = fmaxf(gM1, sm1[i][lane]);
    }
    float gS0 = 0.f, gS1 = 0.f;
    #pragma unroll
    for (int i = 0; i < 8; i++) {
        gS0 += ss0[i][lane] * __expf(sm0[i][lane] - gM0);
        gS1 += ss1[i][lane] * __expf(sm1[i][lane] - gM1);
    }
    float inv0 = 1.f / gS0, inv1 = 1.f / gS1;
    fp16* ob = pT + ((size_t)bh << 20) + s;
    #pragma unroll 4
    for (int t = 0; t < 128; t++) {
        __half2 h = *(const __half2*)(base + ((size_t)(t0 + t) << 10));
        float p0 = __expf(__low2float(h) - gM0) * inv0;
        float p1 = __expf(__high2float(h) - gM1) * inv1;
        *(uint32_t*)(ob + ((size_t)(t0 + t) << 10)) = pack_hf(p0, p1);
    }
}

// ---------------- AV: mha[b,t,h,d] = sum_s pT[bh,t,s] * vT[bh,d,s] ----------------
#define AV_STAGE 49152
#define AV_SMEM (2*AV_STAGE)
__global__ void __launch_bounds__(256, 1) av_mma(
    const fp16* __restrict__ pT, const fp16* __restrict__ vT,
    fp16* __restrict__ Mh)
{
    extern __shared__ char smem[];
    const uint32_t sb = smem_u32(smem);
    const int tid = threadIdx.x, wid = tid >> 5, lane = tid & 31;
    const int bh = blockIdx.y, t0 = blockIdx.x << 7;
    const fp16* gA = pT + ((size_t)bh << 20) + (size_t)t0 * 1024;
    const fp16* gB = vT + ((size_t)bh << 16);

    auto load_stage = [&](int s, int c) {
        const uint32_t st = sb + (uint32_t)s * AV_STAGE;
        const int kb = c << 7;
        #pragma unroll
        for (int i = 0; i < 8; i++) {
            int idx = tid + (i << 8);
            int row = idx >> 4, ch = idx & 15;
            uint32_t dst = st + (uint32_t)(row << 8) + (uint32_t)((ch ^ (row & 7)) << 4);
            cp_async16(dst, gA + (size_t)row * 1024 + kb + (ch << 3));
        }
        #pragma unroll
        for (int i = 0; i < 4; i++) {
            int idx = tid + (i << 8);
            int row = idx >> 4, ch = idx & 15;
            uint32_t dst = st + 32768u + (uint32_t)(row << 8) + (uint32_t)((ch ^ (row & 7)) << 4);
            cp_async16(dst, gB + (size_t)row * 1024 + kb + (ch << 3));
        }
        asm volatile("cp.async.commit_group;" ::: "memory");
    };

    const int wm = (wid & 3) << 5, wn = (wid >> 2) << 5;
    float acc[2][4][4];
    #pragma unroll
    for (int i = 0; i < 2; i++)
        #pragma unroll
        for (int j = 0; j < 4; j++)
            #pragma unroll
            for (int q = 0; q < 4; q++) acc[i][j][q] = 0.f;

    const int a_row = lane & 15, a_cb = (lane >> 4) << 4;
    const int b_row = (lane & 7) + ((lane >> 4) << 3), b_cb = ((lane >> 3) & 1) << 4;
    const uint32_t swz = (uint32_t)((lane & 7) << 4);

    load_stage(0, 0);
    for (int c = 0; c < 8; c++) {
        const int s = c & 1;
        if (c + 1 < 8) {
            load_stage(s ^ 1, c + 1);
            asm volatile("cp.async.wait_group 1;" ::: "memory");
        } else {
            asm volatile("cp.async.wait_group 0;" ::: "memory");
        }
        __syncthreads();

        const uint32_t st = sb + (uint32_t)s * AV_STAGE;
        #pragma unroll
        for (int kk = 0; kk < 8; kk++) {
            uint32_t af[2][4], bf2[2][4];
            #pragma unroll
            for (int mi = 0; mi < 2; mi++) {
                int row = wm + (mi << 4) + a_row;
                uint32_t off = (uint32_t)(row << 8) + (((uint32_t)((kk << 5) + a_cb)) ^ swz);
                LDSM4(af[mi], st + off);
            }
            #pragma unroll
            for (int j = 0; j < 2; j++) {
                int row = wn + (j << 4) + b_row;
                uint32_t off = (uint32_t)(row << 8) + (((uint32_t)((kk << 5) + b_cb)) ^ swz);
                LDSM4(bf2[j], st + 32768u + off);
            }
            #pragma unroll
            for (int mi = 0; mi < 2; mi++) {
                #pragma unroll
                for (int nj = 0; nj < 4; nj++) {
                    MMA16816(acc[mi][nj], af[mi],
                             bf2[nj >> 1][(nj & 1) << 1], bf2[nj >> 1][((nj & 1) << 1) + 1]);
                }
            }
        }
        __syncthreads();
    }

    const int b = bh >> 4, h = bh & 15;
    const int er = t0 + wm + (lane >> 2);
    const int ec = wn + ((lane & 3) << 1);
    #pragma unroll
    for (int mi = 0; mi < 2; mi++) {
        #pragma unroll
        for (int hf = 0; hf < 2; hf++) {
            int t = er + (mi << 4) + (hf << 3);
            size_t rowbase = ((size_t)(b << 10) + t) * 1024 + (h << 6);
            #pragma unroll
            for (int nj = 0; nj < 4; nj++) {
                int col = ec + (nj << 3);
                *(uint32_t*)&Mh[rowbase + col] =
                    pack_hf(acc[mi][nj][hf * 2], acc[mi][nj][hf * 2 + 1]);
            }
        }
    }
}

// ---------------- block reductions ----------------
__device__ __forceinline__ float blockReduceSum(float v) {
    __shared__ float sh[33];
    int lane = threadIdx.x & 31, w = threadIdx.x >> 5;
    #pragma unroll
    for (int o = 16; o > 0; o >>= 1) v += __shfl_xor_sync(0xffffffffu, v, o);
    __syncthreads();
    if (lane == 0) sh[w] = v;
    __syncthreads();
    if (w == 0) {
        v = (lane < (int)(blockDim.x >> 5)) ? sh[lane] : 0.f;
        #pragma unroll
        for (int o = 16; o > 0; o >>= 1) v += __shfl_xor_sync(0xffffffffu, v, o);
        if (lane == 0) sh[32] = v;
    }
    __syncthreads();
    return sh[32];
}

// ---------------- embedding: x fp32 + fp16 ----------------
__global__ void embed_kernel(const int* __restrict__ tokens,
                             const float* __restrict__ tok,
                             const float* __restrict__ pos,
                             float* __restrict__ x, fp16* __restrict__ xh) {
    int idx = blockIdx.x * blockDim.x + threadIdx.x;
    const int EV = En / 4;
    if (idx >= NTOK * EV) return;
    int bs = idx / EV, e4 = idx % EV;
    int s = bs & (Sn - 1);
    int t = tokens[bs];
    float4 a = ((const float4*)tok)[(size_t)t * EV + e4];
    float4 p = ((const float4*)pos)[(size_t)s * EV + e4];
    float4 r;
    r.x = a.x + p.x; r.y = a.y + p.y; r.z = a.z + p.z; r.w = a.w + p.w;
    ((float4*)x)[idx] = r;
    ((uint2*)xh)[idx] = make_uint2(pack_hf(r.x, r.y), pack_hf(r.z, r.w));
}

// ---------------- rmsnorm -> fp16 ----------------
__global__ void add_rmsnorm_kernel(const float* __restrict__ x, const float* __restrict__ add,
                                   const float* __restrict__ scale, fp16* __restrict__ oh)
{
    int row = blockIdx.x, tid = threadIdx.x;
    const float* xr = x + (size_t)row * En;
    const float* ar = add ? add + (size_t)row * En : nullptr;
    float v[4]; float ss = 0.f;
    #pragma unroll
    for (int j = 0; j < 4; j++) {
        int e = tid + j * 256;
        float t = xr[e];
        if (ar) t += ar[e];
        v[j] = t;
        ss += t * t;
    }
    ss = blockReduceSum(ss);
    float r = rsqrtf(ss * (1.f / En) + 1e-6f);
    #pragma unroll
    for (int j = 0; j < 4; j++) {
        int e = tid + j * 256;
        oh[(size_t)row * En + e] = __float2half_rn(v[j] * r * scale[e]);
    }
}

// ---------------- log_softmax over fp16 logits -> fp32 out ----------------
// One block (256 thr) per row. Single online-stats pass + one write pass.
__global__ void __launch_bounds__(256) log_softmax_h(const fp16* __restrict__ lg,
                                                     float* __restrict__ out) {
    __shared__ float shm[9], shs[9];
    const fp16* row = lg + (size_t)blockIdx.x * Vn;
    float* orow = out + (size_t)blockIdx.x * Vn;
    const int tid = threadIdx.x, lane = tid & 31, w = tid >> 5;
    float m = -3.402823466e38f, s = 0.f;
    for (int i = tid; i < Vn / 2; i += 256) {
        __half2 h = *(const __half2*)(row + i * 2);
        float x0 = __low2float(h), x1 = __high2float(h);
        float n0 = fmaxf(m, fmaxf(x0, x1));
        s = s * __expf(m - n0) + __expf(x0 - n0) + __expf(x1 - n0);
        m = n0;
    }
    #pragma unroll
    for (int o = 16; o > 0; o >>= 1) {
        float mo = __shfl_xor_sync(0xffffffffu, m, o);
        float so = __shfl_xor_sync(0xffffffffu, s, o);
        ms_combine(m, s, mo, so);
    }
    if (lane == 0) { shm[w] = m; shs[w] = s; }
    __syncthreads();
    if (w == 0) {
        m = (lane < 8) ? shm[lane] : -3.402823466e38f;
        s = (lane < 8) ? shs[lane] : 0.f;
        #pragma unroll
        for (int o = 4; o > 0; o >>= 1) {
            float mo = __shfl_xor_sync(0xffffffffu, m, o);
            float so = __shfl_xor_sync(0xffffffffu, s, o);
            ms_combine(m, s, mo, so);
        }
        if (lane == 0) { shm[8] = m; shs[8] = s; }
    }
    __syncthreads();
    float lse = shm[8] + logf(shs[8]);
    for (int i = tid; i < Vn / 2; i += 256) {
        __half2 h = *(const __half2*)(row + i * 2);
        *(float2*)(orow + i * 2) =
            make_float2(__low2float(h) - lse, __high2float(h) - lse);
    }
}

// ---------------- launch ----------------
extern "C" void kernel_launch(void* const* d_in, const int* in_sizes, int n_in,
                              void* d_out, int out_size) {
    const int*   tokens      = (const int*)  d_in[0];
    const float* tok_embed   = (const float*)d_in[1];
    const float* pos_embed   = (const float*)d_in[2];
    const float* Qw          = (const float*)d_in[3];
    const float* Kw          = (const float*)d_in[4];
    const float* Vw          = (const float*)d_in[5];
    const float* Ow          = (const float*)d_in[6];
    const float* rs2         = (const float*)d_in[7];
    const float* w1          = (const float*)d_in[8];
    const float* b1          = (const float*)d_in[9];
    const float* w2          = (const float*)d_in[10];
    const float* b2          = (const float*)d_in[11];
    const float* final_scale = (const float*)d_in[12];
    const float* w_out       = (const float*)d_in[13];
    const float* b_out       = (const float*)d_in[14];
    float* out = (float*)d_out;

    float *xb, *projb;
    fp16 *wh, *attb, *ptb, *lgb, *xh, *qh, *kh, *vt, *mh, *rh, *hh;
    cudaGetSymbolAddress((void**)&xb,    g_x);
    cudaGetSymbolAddress((void**)&projb, g_proj);
    cudaGetSymbolAddress((void**)&attb,  g_att);
    cudaGetSymbolAddress((void**)&ptb,   g_pt);
    cudaGetSymbolAddress((void**)&lgb,   g_lg);
    cudaGetSymbolAddress((void**)&wh,    g_wh);
    cudaGetSymbolAddress((void**)&xh,    g_xh);
    cudaGetSymbolAddress((void**)&qh,    g_qh);
    cudaGetSymbolAddress((void**)&kh,    g_kh);
    cudaGetSymbolAddress((void**)&vt,    g_vt);
    cudaGetSymbolAddress((void**)&mh,    g_mh);
    cudaGetSymbolAddress((void**)&rh,    g_rh);
    cudaGetSymbolAddress((void**)&hh,    g_hh);

    cudaFuncSetAttribute(gemm_mma,    cudaFuncAttributeMaxDynamicSharedMemorySize, GM_SMEM);
    cudaFuncSetAttribute(scoresT_mma, cudaFuncAttributeMaxDynamicSharedMemorySize, SC_SMEM);
    cudaFuncSetAttribute(av_mma,      cudaFuncAttributeMaxDynamicSharedMemorySize, AV_SMEM);

    // ---- weight conversion: transpose + fp16, layer-fused (7 launches) ----
    dim3 cb(32, 8);
    convert_w<<<dim3(32, 16, Lnum), cb>>>(Qw, wh,          En, HIDn, M1, 3 * (size_t)M1);
    convert_w<<<dim3(32, 16, Lnum), cb>>>(Kw, wh + M1,     En, HIDn, M1, 3 * (size_t)M1);
    convert_w<<<dim3(32, 16, Lnum), cb>>>(Vw, wh + 2 * M1, En, HIDn, M1, 3 * (size_t)M1);
    convert_w<<<dim3(32, 16, Lnum), cb>>>(Ow, wh + 12 * (size_t)M1, HIDn, En, M1, M1);
    convert_w<<<dim3(128, 16, Lnum), cb>>>(w1, wh + 16 * (size_t)M1, En, FFn,
                                           4 * (size_t)M1, 4 * (size_t)M1);
    convert_w<<<dim3(32, 64, Lnum), cb>>>(w2, wh + 32 * (size_t)M1, FFn, En,
                                          4 * (size_t)M1, 4 * (size_t)M1);
    convert_w<<<dim3(Vn / 32, 16, 1), cb>>>(w_out, wh + 48 * (size_t)M1, En, Vn, 0, 0);

    embed_kernel<<<(NTOK * (En / 4) + 255) / 256, 256>>>(tokens, tok_embed, pos_embed, xb, xh);

    for (int l = 0; l < Lnum; l++) {
        const fp16 *QKVw = wh + (size_t)l * 3 * M1;
        const fp16 *Owl  = wh + 12 * (size_t)M1 + (size_t)l * M1;
        const fp16 *W1l  = wh + 16 * (size_t)M1 + (size_t)l * 4 * M1;
        const fp16 *W2l  = wh + 32 * (size_t)M1 + (size_t)l * 4 * M1;
        const float* r2l = rs2 + (size_t)l * En;
        const float* b1l = b1 + (size_t)l * FFn;
        const float* b2l = b2 + (size_t)l * En;

        // fused QKV: M=2048, N=3072 (q | k | v)
        gemm_mma<<<dim3(NTOK / 128, 3 * HIDn / 128), 256, GM_SMEM>>>(
            xh, QKVw, nullptr, nullptr, (float*)vt, qh, kh, NTOK, 3 * HIDn, En, 0, 5);

        scoresT_mma<<<dim3(Sn / 128, Sn / 128, Bn * NHn), 256, SC_SMEM>>>(kh, qh, attb);
        col_softmax<<<dim3(Sn / 64, Bn * NHn), 256>>>(attb, ptb);
        av_mma<<<dim3(Sn / 128, Bn * NHn), 256, AV_SMEM>>>(ptb, vt, mh);

        gemm_mma<<<dim3(NTOK / 128, En / 128), 256, GM_SMEM>>>(
            mh, Owl, nullptr, nullptr, projb, nullptr, nullptr, NTOK, En, HIDn, 0, 0);
        add_rmsnorm_kernel<<<NTOK, 256>>>(xb, projb, r2l, rh);

        gemm_mma<<<dim3(NTOK / 128, FFn / 128), 256, GM_SMEM>>>(
            rh, W1l, b1l, nullptr, nullptr, hh, nullptr, NTOK, FFn, En, 1 | 2, 2);
        gemm_mma<<<dim3(NTOK / 128, En / 128), 256, GM_SMEM>>>(
            hh, W2l, b2l, projb, xb, xh, nullptr, NTOK, En, FFn, 1 | 4, 1);
    }

    add_rmsnorm_kernel<<<NTOK, 256>>>(xb, nullptr, final_scale, xh);

    // logits: fp16 intermediate (bias fused), then fused single-pass log_softmax
    gemm_mma<<<dim3(NTOK / 128, Vn / 128), 256, GM_SMEM>>>(
        xh, wh + 48 * (size_t)M1, b_out, nullptr, nullptr, lgb, nullptr, NTOK, Vn, En, 1, 2);
    log_softmax_h<<<NTOK, 256>>>(lgb, out);
}